// round 6
// baseline (speedup 1.0000x reference)
#include <cuda_runtime.h>
#include <math.h>

#define NBATCH 4
#define NTOK   4096
#define NC     256
#define NH     8
#define ND     32
#define NPL    64
#define EPSF   1.1920929e-07f

// ---------------- scratch (device globals; no runtime alloc allowed) -------------
__device__ float g_qtmp[NBATCH*NTOK*NC];        // raw q gemm out (16 MB)
__device__ float g_q[NBATCH*NTOK*NC];           // q_scaled, layout (B,H,N,D) (16 MB)
__device__ float g_ltd[NBATCH*NH*NTOK*9];       // learnable-token dots + bias (4.7 MB)
__device__ float g_kv[NBATCH*NTOK*2*NC];        // kv, k-half l2-normalized in place (32 MB)
__device__ float g_gate[NBATCH*NTOK*NH];        // per-head gates (0.5 MB)
__device__ float g_xs[NBATCH*NTOK*NC];          // sr+gelu out (16 MB)
__device__ float g_pool[NBATCH*NPL*NC];         // pooled + LN (0.25 MB)
__device__ float g_kvp2[NBATCH*NPL*2*NC];       // pooled kv, k-half normalized (0.5 MB)
__device__ float g_cpbh[4096*512];              // cpb hidden (8 MB)
__device__ float g_cpb[4096*NH];                // cpb table (128 KB)
__device__ float g_attnout[NBATCH*NTOK*NC];     // pre-proj attention out (16 MB)

// ---------------- helpers --------------------------------------------------------
__device__ __forceinline__ float warpSum(float v){
  #pragma unroll
  for (int o=16;o>0;o>>=1) v += __shfl_xor_sync(0xffffffffu, v, o);
  return v;
}
__device__ __forceinline__ float warpMax(float v){
  #pragma unroll
  for (int o=16;o>0;o>>=1) v = fmaxf(v, __shfl_xor_sync(0xffffffffu, v, o));
  return v;
}

// ---------------- fp32 SGEMM: C = A(MxK) * W(NxK)^T + bias -----------------------
// 128x128 block tile, 8x8 per thread, double-buffered SMEM, float4 LDS.
template<bool GELU>
__global__ void __launch_bounds__(256, 2)
sgemm_kernel(const float* __restrict__ A, const float* __restrict__ W,
             const float* __restrict__ bias, float* __restrict__ C,
             int M, int N, int K)
{
  __shared__ float As[2][16][128];
  __shared__ float Ws[2][16][128];
  const int tid = threadIdx.x;
  const int m0 = blockIdx.y * 128;
  const int n0 = blockIdx.x * 128;
  const int lrow = tid >> 1;         // loader row within tile (0..127)
  const int lk   = (tid & 1) * 8;    // loader k offset (0 or 8)
  const int tx = tid & 15;           // -> 8 output cols
  const int ty = tid >> 4;           // -> 8 output rows

  const float* Ap = A + (long)(m0 + lrow) * K + lk;
  const float* Wp = W + (long)(n0 + lrow) * K + lk;

  float acc[8][8];
  #pragma unroll
  for (int i=0;i<8;i++)
    #pragma unroll
    for (int j=0;j<8;j++) acc[i][j]=0.f;

  // initial tile -> buffer 0
  {
    float4 a0 = *(const float4*)(Ap);
    float4 a1 = *(const float4*)(Ap+4);
    float4 w0 = *(const float4*)(Wp);
    float4 w1 = *(const float4*)(Wp+4);
    As[0][lk+0][lrow]=a0.x; As[0][lk+1][lrow]=a0.y; As[0][lk+2][lrow]=a0.z; As[0][lk+3][lrow]=a0.w;
    As[0][lk+4][lrow]=a1.x; As[0][lk+5][lrow]=a1.y; As[0][lk+6][lrow]=a1.z; As[0][lk+7][lrow]=a1.w;
    Ws[0][lk+0][lrow]=w0.x; Ws[0][lk+1][lrow]=w0.y; Ws[0][lk+2][lrow]=w0.z; Ws[0][lk+3][lrow]=w0.w;
    Ws[0][lk+4][lrow]=w1.x; Ws[0][lk+5][lrow]=w1.y; Ws[0][lk+6][lrow]=w1.z; Ws[0][lk+7][lrow]=w1.w;
  }
  __syncthreads();

  int buf = 0;
  for (int k0 = 0; k0 < K; k0 += 16){
    const bool more = (k0 + 16 < K);
    float4 pa0, pa1, pw0, pw1;
    if (more){
      pa0 = *(const float4*)(Ap + k0 + 16);
      pa1 = *(const float4*)(Ap + k0 + 20);
      pw0 = *(const float4*)(Wp + k0 + 16);
      pw1 = *(const float4*)(Wp + k0 + 20);
    }
    #pragma unroll
    for (int kk=0; kk<16; kk++){
      float4 af0 = *(const float4*)(&As[buf][kk][ty*8]);
      float4 af1 = *(const float4*)(&As[buf][kk][ty*8+4]);
      float4 wf0 = *(const float4*)(&Ws[buf][kk][tx*8]);
      float4 wf1 = *(const float4*)(&Ws[buf][kk][tx*8+4]);
      float a[8] = {af0.x,af0.y,af0.z,af0.w,af1.x,af1.y,af1.z,af1.w};
      float w[8] = {wf0.x,wf0.y,wf0.z,wf0.w,wf1.x,wf1.y,wf1.z,wf1.w};
      #pragma unroll
      for (int i=0;i<8;i++)
        #pragma unroll
        for (int j=0;j<8;j++)
          acc[i][j] = fmaf(a[i], w[j], acc[i][j]);
    }
    if (more){
      int nb = buf ^ 1;
      As[nb][lk+0][lrow]=pa0.x; As[nb][lk+1][lrow]=pa0.y; As[nb][lk+2][lrow]=pa0.z; As[nb][lk+3][lrow]=pa0.w;
      As[nb][lk+4][lrow]=pa1.x; As[nb][lk+5][lrow]=pa1.y; As[nb][lk+6][lrow]=pa1.z; As[nb][lk+7][lrow]=pa1.w;
      Ws[nb][lk+0][lrow]=pw0.x; Ws[nb][lk+1][lrow]=pw0.y; Ws[nb][lk+2][lrow]=pw0.z; Ws[nb][lk+3][lrow]=pw0.w;
      Ws[nb][lk+4][lrow]=pw1.x; Ws[nb][lk+5][lrow]=pw1.y; Ws[nb][lk+6][lrow]=pw1.z; Ws[nb][lk+7][lrow]=pw1.w;
    }
    __syncthreads();
    buf ^= 1;
  }

  #pragma unroll
  for (int i=0;i<8;i++){
    int m = m0 + ty*8 + i;
    #pragma unroll
    for (int jq=0;jq<2;jq++){
      int n = n0 + tx*8 + jq*4;
      float4 v;
      v.x = acc[i][jq*4+0] + bias[n+0];
      v.y = acc[i][jq*4+1] + bias[n+1];
      v.z = acc[i][jq*4+2] + bias[n+2];
      v.w = acc[i][jq*4+3] + bias[n+3];
      if (GELU){
        v.x = 0.5f*v.x*(1.f + erff(v.x*0.70710678118654752f));
        v.y = 0.5f*v.y*(1.f + erff(v.y*0.70710678118654752f));
        v.z = 0.5f*v.z*(1.f + erff(v.z*0.70710678118654752f));
        v.w = 0.5f*v.w*(1.f + erff(v.w*0.70710678118654752f));
      }
      *(float4*)(C + (long)m*N + n) = v;
    }
  }
}

// ---------------- q post: l2norm, scale, learnable-token dots ---------------------
__global__ void __launch_bounds__(256)
qpost_kernel(const float* __restrict__ temp, const float* __restrict__ qe,
             const float* __restrict__ lt, const float* __restrict__ lb)
{
  int w = (blockIdx.x * 256 + threadIdx.x) >> 5;   // (b*8+h)*4096+n
  int lane = threadIdx.x & 31;
  int n = w & 4095;
  int bh = w >> 12;
  int h = bh & 7, b = bh >> 3;
  float qv = g_qtmp[(b*4096+n)*256 + h*32 + lane];
  float ss = warpSum(qv*qv);
  float qn = qv / fmaxf(sqrtf(ss), EPSF);
  int yi = n >> 6, xj = n & 63;
  int ch = min(yi+1,63) - max(yi-1,0) + 1;
  int cw = min(xj+1,63) - max(xj-1,0) + 1;
  float sls = logf((float)(ch*cw) + 64.f);
  float sp = log1pf(expf(temp[h]));
  g_q[w*32 + lane] = (qn + qe[h*32+lane]) * sp * sls;
  #pragma unroll
  for (int l=0;l<9;l++){
    float p = warpSum(qn * lt[h*288 + lane*9 + l]);
    if (lane == l) g_ltd[w*9 + l] = p + lb[h*9+l];
  }
}

// ---------------- kv post: l2-normalize k half per head (in place) ---------------
__global__ void __launch_bounds__(256)
kvpost_kernel()
{
  int w = (blockIdx.x*256 + threadIdx.x) >> 5;  // row*8+h
  int lane = threadIdx.x & 31;
  int h = w & 7, row = w >> 3;
  float* p = g_kv + row*512 + h*32 + lane;
  float v = *p;
  float ss = warpSum(v*v);
  *p = v / fmaxf(sqrtf(ss), EPSF);
}

__global__ void __launch_bounds__(256)
kvp2post_kernel()
{
  int w = (blockIdx.x*256 + threadIdx.x) >> 5;  // row*8+h, row < 256
  int lane = threadIdx.x & 31;
  int h = w & 7, row = w >> 3;
  float* p = g_kvp2 + row*512 + h*32 + lane;
  float v = *p;
  float ss = warpSum(v*v);
  *p = v / fmaxf(sqrtf(ss), EPSF);
}

// ---------------- gating (routed top-2, shared, w0) ------------------------------
__global__ void __launch_bounds__(256)
gates_kernel(const float* __restrict__ x, const float* __restrict__ wg,
             const float* __restrict__ wg0, const float* __restrict__ wg1)
{
  int w = (blockIdx.x*256 + threadIdx.x) >> 5;   // row = b*4096+n
  int lane = threadIdx.x & 31;
  const float* xr = x + w*256;
  float xv[8];
  {
    float4 a = *(const float4*)(xr + lane*8);
    float4 c = *(const float4*)(xr + lane*8 + 4);
    xv[0]=a.x; xv[1]=a.y; xv[2]=a.z; xv[3]=a.w;
    xv[4]=c.x; xv[5]=c.y; xv[6]=c.z; xv[7]=c.w;
  }
  float d[10];
  #pragma unroll
  for (int r=0;r<10;r++){
    const float* wr = (r<4) ? (wg + r*256) : ((r<6) ? (wg0 + (r-4)*256) : (wg1 + (r-6)*256));
    float pp = 0.f;
    #pragma unroll
    for (int k=0;k<8;k++) pp = fmaf(xv[k], wr[lane*8+k], pp);
    d[r] = warpSum(pp);
  }
  if (lane == 0){
    float m = fmaxf(fmaxf(d[0],d[1]),fmaxf(d[2],d[3]));
    float e[4], se=0.f;
    #pragma unroll
    for (int k=0;k<4;k++){ e[k]=expf(d[k]-m); se+=e[k]; }
    float gg[4];
    #pragma unroll
    for (int k=0;k<4;k++) gg[k]=e[k]/se;
    int i0=0;
    #pragma unroll
    for (int k=1;k<4;k++) if (gg[k]>gg[i0]) i0=k;
    int i1=-1;
    #pragma unroll
    for (int k=0;k<4;k++) if (k!=i0 && (i1<0 || gg[k]>gg[i1])) i1=k;
    float s2 = fmaxf(gg[i0]+gg[i1], EPSF);
    float routed[4]={0.f,0.f,0.f,0.f};
    routed[i0]=gg[i0]/s2*2.f; routed[i1]=gg[i1]/s2*2.f;
    float m0 = fmaxf(d[4],d[5]);
    float e4=expf(d[4]-m0), e5=expf(d[5]-m0);
    float w00 = e4/(e4+e5)*2.f, w01 = e5/(e4+e5)*2.f;
    float m1 = fmaxf(fmaxf(d[6],d[7]),fmaxf(d[8],d[9]));
    float es[4], ss2=0.f;
    #pragma unroll
    for (int k=0;k<4;k++){ es[k]=expf(d[6+k]-m1); ss2+=es[k]; }
    float* gp = g_gate + w*8;
    #pragma unroll
    for (int k=0;k<4;k++) gp[k]   = w00 * (es[k]/ss2*4.f);
    #pragma unroll
    for (int k=0;k<4;k++) gp[4+k] = w01 * routed[k];
  }
}

// ---------------- 8x8 avg pool + LayerNorm ---------------------------------------
__global__ void __launch_bounds__(256)
pool_ln_kernel(const float* __restrict__ ng, const float* __restrict__ nb)
{
  int b = blockIdx.x >> 6, p = blockIdx.x & 63;
  int c = threadIdx.x;
  int pi = p >> 3, pj = p & 7;
  float s = 0.f;
  #pragma unroll
  for (int si=0; si<8; si++){
    int rowbase = b*4096 + (pi*8+si)*64 + pj*8;
    #pragma unroll
    for (int sj=0; sj<8; sj++)
      s += g_xs[(rowbase + sj)*256 + c];
  }
  float v = s * (1.f/64.f);
  __shared__ float shs[8], shq[8];
  int lane = c & 31, wid = c >> 5;
  float s1 = warpSum(v), sq = warpSum(v*v);
  if (lane==0){ shs[wid]=s1; shq[wid]=sq; }
  __syncthreads();
  float tot=0.f, totq=0.f;
  #pragma unroll
  for (int i=0;i<8;i++){ tot+=shs[i]; totq+=shq[i]; }
  float mu = tot*(1.f/256.f);
  float var = totq*(1.f/256.f) - mu*mu;
  g_pool[(b*64+p)*256 + c] = (v-mu)*rsqrtf(var+1e-5f)*ng[c] + nb[c];
}

// ---------------- cpb MLP --------------------------------------------------------
__global__ void __launch_bounds__(256)
cpb_hidden_kernel(const float* __restrict__ ct, const float* __restrict__ w1,
                  const float* __restrict__ b1)
{
  int tid = blockIdx.x*256 + threadIdx.x;
  if (tid >= 4096*512) return;
  int t = tid >> 9, j = tid & 511;
  float v = fmaf(ct[t*2], w1[j*2], fmaf(ct[t*2+1], w1[j*2+1], b1[j]));
  g_cpbh[tid] = fmaxf(v, 0.f);
}

__global__ void __launch_bounds__(256)
cpb_out_kernel(const float* __restrict__ w2, const float* __restrict__ b2)
{
  int t = (blockIdx.x*256 + threadIdx.x) >> 5;   // table row
  int lane = threadIdx.x & 31;
  float s[8] = {0,0,0,0,0,0,0,0};
  #pragma unroll
  for (int it=0; it<16; it++){
    float hv = g_cpbh[t*512 + it*32 + lane];
    #pragma unroll
    for (int h=0;h<8;h++) s[h] = fmaf(hv, w2[h*512 + it*32 + lane], s[h]);
  }
  #pragma unroll
  for (int h=0;h<8;h++){
    float tot = warpSum(s[h]);
    if (lane == 0) g_cpb[t*8 + h] = tot + b2[h];
  }
}

// ---------------- fused local+pool attention -------------------------------------
__global__ void __launch_bounds__(256)
attn_kernel(const float* __restrict__ rpb, const int* __restrict__ rpi)
{
  __shared__ float ks[32*64];   // k_pool transposed [d][p]
  __shared__ float vs[64*32];   // v_pool [p][d]
  const int bh = blockIdx.y;
  const int h = bh & 7, b = bh >> 3;
  const int tid = threadIdx.x;
  for (int idx = tid; idx < 2048; idx += 256){
    int p = idx >> 5, d = idx & 31;
    const float* base = g_kvp2 + (b*64+p)*512 + h*32 + d;
    ks[d*64+p] = base[0];
    vs[idx]    = base[256];
  }
  __syncthreads();
  const int warp = tid >> 5, lane = tid & 31;
  float rpbl[9];
  #pragma unroll
  for (int l=0;l<9;l++) rpbl[l] = rpb[h*9+l];

  for (int it=0; it<8; it++){
    int n = blockIdx.x*64 + warp*8 + it;
    int yi = n >> 6, xj = n & 63;
    float qs = g_q[((b*8+h)*4096 + n)*32 + lane];
    // local window scores (zero-padded -> score = rpb, v = 0)
    float sloc[9]; int nloc[9];
    #pragma unroll
    for (int l=0;l<9;l++){
      int y  = yi + l/3 - 1;
      int x2 = xj + l%3 - 1;
      bool val = ((unsigned)y < 64u) && ((unsigned)x2 < 64u);
      int nl = y*64 + x2;
      nloc[l] = val ? nl : -1;
      float kd = val ? g_kv[(b*4096+nl)*512 + h*32 + lane] : 0.f;
      sloc[l] = warpSum(qs*kd) + rpbl[l];
    }
    // pool scores: lane handles p=lane and p=lane+32
    const int* rr = rpi + n*64;
    int ia = rr[lane], ib = rr[lane+32];
    float s0 = g_cpb[ia*8+h];
    float s1 = g_cpb[ib*8+h];
    #pragma unroll
    for (int d=0; d<32; d++){
      float qd = __shfl_sync(0xffffffffu, qs, d);
      s0 = fmaf(qd, ks[d*64+lane],    s0);
      s1 = fmaf(qd, ks[d*64+lane+32], s1);
    }
    // softmax over 73
    float m = fmaxf(s0, s1);
    #pragma unroll
    for (int l=0;l<9;l++) m = fmaxf(m, sloc[l]);
    m = warpMax(m);
    float el[9], suml = 0.f;
    #pragma unroll
    for (int l=0;l<9;l++){ el[l] = expf(sloc[l]-m); suml += el[l]; }
    float e0 = expf(s0-m), e1 = expf(s1-m);
    float inv = 1.f / (suml + warpSum(e0+e1));
    // local AV (+ learnable-token modulation)
    const float* ltdp = g_ltd + ((b*8+h)*4096 + n)*9;
    float outv = 0.f;
    #pragma unroll
    for (int l=0;l<9;l++){
      float al = el[l]*inv + ltdp[l];
      if (nloc[l] >= 0)
        outv = fmaf(al, g_kv[(b*4096+nloc[l])*512 + 256 + h*32 + lane], outv);
    }
    // pool AV
    #pragma unroll
    for (int p=0;p<32;p++){
      float ap = __shfl_sync(0xffffffffu, e0, p) * inv;
      outv = fmaf(ap, vs[p*32+lane], outv);
    }
    #pragma unroll
    for (int p=0;p<32;p++){
      float ap = __shfl_sync(0xffffffffu, e1, p) * inv;
      outv = fmaf(ap, vs[(p+32)*32+lane], outv);
    }
    float gate = g_gate[(b*4096+n)*8 + h];
    g_attnout[(b*4096+n)*256 + h*32 + lane] = outv * gate;
  }
}

// ---------------- launch ---------------------------------------------------------
extern "C" void kernel_launch(void* const* d_in, const int* in_sizes, int n_in,
                              void* d_out, int out_size)
{
  const float* x      = (const float*)d_in[0];
  const float* ctab   = (const float*)d_in[1];
  const float* q_w    = (const float*)d_in[2];
  const float* q_b    = (const float*)d_in[3];
  const float* kv_w   = (const float*)d_in[4];
  const float* kv_b   = (const float*)d_in[5];
  const float* temp   = (const float*)d_in[6];
  const float* qe     = (const float*)d_in[7];
  const float* rpb    = (const float*)d_in[8];
  const float* lt     = (const float*)d_in[9];
  const float* lb     = (const float*)d_in[10];
  const float* cpb1_w = (const float*)d_in[11];
  const float* cpb1_b = (const float*)d_in[12];
  const float* cpb2_w = (const float*)d_in[13];
  const float* cpb2_b = (const float*)d_in[14];
  const float* sr_w   = (const float*)d_in[15];
  const float* sr_b   = (const float*)d_in[16];
  const float* norm_g = (const float*)d_in[17];
  const float* norm_b = (const float*)d_in[18];
  const float* wg_w   = (const float*)d_in[19];
  const float* wg0_w  = (const float*)d_in[20];
  const float* wg1_w  = (const float*)d_in[21];
  const float* proj_w = (const float*)d_in[22];
  const float* proj_b = (const float*)d_in[23];
  const int*   rpi    = (const int*)d_in[24];
  float* out = (float*)d_out;

  float *p_qtmp, *p_kv, *p_xs, *p_pool, *p_kvp2, *p_attnout;
  cudaGetSymbolAddress((void**)&p_qtmp,    g_qtmp);
  cudaGetSymbolAddress((void**)&p_kv,      g_kv);
  cudaGetSymbolAddress((void**)&p_xs,      g_xs);
  cudaGetSymbolAddress((void**)&p_pool,    g_pool);
  cudaGetSymbolAddress((void**)&p_kvp2,    g_kvp2);
  cudaGetSymbolAddress((void**)&p_attnout, g_attnout);

  const int M = NBATCH*NTOK;   // 16384

  // gating (only needs x)
  gates_kernel<<<2048, 256>>>(x, wg_w, wg0_w, wg1_w);
  // q path
  sgemm_kernel<false><<<dim3(2,128), 256>>>(x, q_w, q_b, p_qtmp, M, 256, 256);
  qpost_kernel<<<16384, 256>>>(temp, qe, lt, lb);
  // kv path
  sgemm_kernel<false><<<dim3(4,128), 256>>>(x, kv_w, kv_b, p_kv, M, 512, 256);
  kvpost_kernel<<<16384, 256>>>();
  // pooled path
  sgemm_kernel<true><<<dim3(2,128), 256>>>(x, sr_w, sr_b, p_xs, M, 256, 256);
  pool_ln_kernel<<<256, 256>>>(norm_g, norm_b);
  sgemm_kernel<false><<<dim3(4,2), 256>>>(p_pool, kv_w, kv_b, p_kvp2, 256, 512, 256);
  kvp2post_kernel<<<256, 256>>>();
  // cpb MLP
  cpb_hidden_kernel<<<8192, 256>>>(ctab, cpb1_w, cpb1_b);
  cpb_out_kernel<<<512, 256>>>(cpb2_w, cpb2_b);
  // fused attention
  attn_kernel<<<dim3(64, 32), 256>>>(rpb, rpi);
  // projection
  sgemm_kernel<false><<<dim3(2,128), 256>>>(p_attnout, proj_w, proj_b, out, M, 256, 256);
}

// round 7
// speedup vs baseline: 1.0591x; 1.0591x over previous
#include <cuda_runtime.h>
#include <math.h>

#define NBATCH 4
#define NTOK   4096
#define NC     256
#define NH     8
#define ND     32
#define NPL    64
#define EPSF   1.1920929e-07f

// ---------------- scratch (device globals; no runtime alloc allowed) -------------
__device__ float g_qtmp[NBATCH*NTOK*NC];        // raw q gemm out (16 MB)
__device__ float g_q[NBATCH*NTOK*NC];           // q_scaled, layout (B,H,N,D) (16 MB)
__device__ float g_ltd[NBATCH*NH*NTOK*9];       // learnable-token dots + bias (4.7 MB)
__device__ float g_kv[NBATCH*NTOK*2*NC];        // kv, k-half l2-normalized in place (32 MB)
__device__ float g_gate[NBATCH*NTOK*NH];        // per-head gates (0.5 MB)
__device__ float g_xs[NBATCH*NTOK*NC];          // sr+gelu out (16 MB)
__device__ float g_pool[NBATCH*NPL*NC];         // pooled + LN (0.25 MB)
__device__ float g_kvp2[NBATCH*NPL*2*NC];       // pooled kv, k-half normalized (0.5 MB)
__device__ float g_cpbh[4096*512];              // cpb hidden (8 MB)
__device__ float g_cpb[4096*NH];                // cpb table (128 KB)
__device__ float g_attnout[NBATCH*NTOK*NC];     // pre-proj attention out (16 MB)

// ---------------- helpers --------------------------------------------------------
__device__ __forceinline__ float warpSum(float v){
  #pragma unroll
  for (int o=16;o>0;o>>=1) v += __shfl_xor_sync(0xffffffffu, v, o);
  return v;
}
__device__ __forceinline__ float warpMax(float v){
  #pragma unroll
  for (int o=16;o>0;o>>=1) v = fmaxf(v, __shfl_xor_sync(0xffffffffu, v, o));
  return v;
}

// ---------------- fp32 SGEMM: C = A(MxK) * W(NxK)^T + bias -----------------------
// 128x128 block tile, 8x8 per thread, double-buffered SMEM.
// Conflict-free fragment layout: 8 warps = 4(M) x 2(N); warp tile 32x64;
// lane ly=lane>>3 (rows ly*4 + {0..3, 16..19}), lx=lane&7 (cols lx*4 + {0..3, 32..35}).
template<bool GELU>
__global__ void __launch_bounds__(256, 2)
sgemm_kernel(const float* __restrict__ A, const float* __restrict__ W,
             const float* __restrict__ bias, float* __restrict__ C,
             int M, int N, int K)
{
  __shared__ float As[2][16][128];
  __shared__ float Ws[2][16][128];
  const int tid = threadIdx.x;
  const int m0 = blockIdx.y * 128;
  const int n0 = blockIdx.x * 128;
  const int lrow = tid >> 1;         // loader row within tile (0..127)
  const int lk   = (tid & 1) * 8;    // loader k offset (0 or 8)

  const int wid  = tid >> 5, lane = tid & 31;
  const int wy   = wid & 3;          // warp row group (4 along M)
  const int wx   = wid >> 2;         // warp col group (2 along N)
  const int ly   = lane >> 3;        // 0..3
  const int lx   = lane & 7;         // 0..7
  const int ra   = wy*32 + ly*4;     // A fragment base row in tile
  const int cb   = wx*64 + lx*4;     // W fragment base col in tile

  const float* Ap = A + (long)(m0 + lrow) * K + lk;
  const float* Wp = W + (long)(n0 + lrow) * K + lk;

  float acc[8][8];
  #pragma unroll
  for (int i=0;i<8;i++)
    #pragma unroll
    for (int j=0;j<8;j++) acc[i][j]=0.f;

  // initial tile -> buffer 0
  {
    float4 a0 = *(const float4*)(Ap);
    float4 a1 = *(const float4*)(Ap+4);
    float4 w0 = *(const float4*)(Wp);
    float4 w1 = *(const float4*)(Wp+4);
    As[0][lk+0][lrow]=a0.x; As[0][lk+1][lrow]=a0.y; As[0][lk+2][lrow]=a0.z; As[0][lk+3][lrow]=a0.w;
    As[0][lk+4][lrow]=a1.x; As[0][lk+5][lrow]=a1.y; As[0][lk+6][lrow]=a1.z; As[0][lk+7][lrow]=a1.w;
    Ws[0][lk+0][lrow]=w0.x; Ws[0][lk+1][lrow]=w0.y; Ws[0][lk+2][lrow]=w0.z; Ws[0][lk+3][lrow]=w0.w;
    Ws[0][lk+4][lrow]=w1.x; Ws[0][lk+5][lrow]=w1.y; Ws[0][lk+6][lrow]=w1.z; Ws[0][lk+7][lrow]=w1.w;
  }
  __syncthreads();

  int buf = 0;
  for (int k0 = 0; k0 < K; k0 += 16){
    const bool more = (k0 + 16 < K);
    float4 pa0, pa1, pw0, pw1;
    if (more){
      pa0 = *(const float4*)(Ap + k0 + 16);
      pa1 = *(const float4*)(Ap + k0 + 20);
      pw0 = *(const float4*)(Wp + k0 + 16);
      pw1 = *(const float4*)(Wp + k0 + 20);
    }
    #pragma unroll
    for (int kk=0; kk<16; kk++){
      float4 af0 = *(const float4*)(&As[buf][kk][ra]);
      float4 af1 = *(const float4*)(&As[buf][kk][ra+16]);
      float4 wf0 = *(const float4*)(&Ws[buf][kk][cb]);
      float4 wf1 = *(const float4*)(&Ws[buf][kk][cb+32]);
      float a[8] = {af0.x,af0.y,af0.z,af0.w,af1.x,af1.y,af1.z,af1.w};
      float w[8] = {wf0.x,wf0.y,wf0.z,wf0.w,wf1.x,wf1.y,wf1.z,wf1.w};
      #pragma unroll
      for (int i=0;i<8;i++)
        #pragma unroll
        for (int j=0;j<8;j++)
          acc[i][j] = fmaf(a[i], w[j], acc[i][j]);
    }
    if (more){
      int nb = buf ^ 1;
      As[nb][lk+0][lrow]=pa0.x; As[nb][lk+1][lrow]=pa0.y; As[nb][lk+2][lrow]=pa0.z; As[nb][lk+3][lrow]=pa0.w;
      As[nb][lk+4][lrow]=pa1.x; As[nb][lk+5][lrow]=pa1.y; As[nb][lk+6][lrow]=pa1.z; As[nb][lk+7][lrow]=pa1.w;
      Ws[nb][lk+0][lrow]=pw0.x; Ws[nb][lk+1][lrow]=pw0.y; Ws[nb][lk+2][lrow]=pw0.z; Ws[nb][lk+3][lrow]=pw0.w;
      Ws[nb][lk+4][lrow]=pw1.x; Ws[nb][lk+5][lrow]=pw1.y; Ws[nb][lk+6][lrow]=pw1.z; Ws[nb][lk+7][lrow]=pw1.w;
    }
    __syncthreads();
    buf ^= 1;
  }

  #pragma unroll
  for (int i=0;i<8;i++){
    int m = m0 + ra + ((i < 4) ? i : (12 + i));   // rows ra+{0..3}, ra+16+{0..3}
    #pragma unroll
    for (int jg=0;jg<2;jg++){
      int n = n0 + cb + jg*32;
      float4 v;
      v.x = acc[i][jg*4+0] + bias[n+0];
      v.y = acc[i][jg*4+1] + bias[n+1];
      v.z = acc[i][jg*4+2] + bias[n+2];
      v.w = acc[i][jg*4+3] + bias[n+3];
      if (GELU){
        v.x = 0.5f*v.x*(1.f + erff(v.x*0.70710678118654752f));
        v.y = 0.5f*v.y*(1.f + erff(v.y*0.70710678118654752f));
        v.z = 0.5f*v.z*(1.f + erff(v.z*0.70710678118654752f));
        v.w = 0.5f*v.w*(1.f + erff(v.w*0.70710678118654752f));
      }
      *(float4*)(C + (long)m*N + n) = v;
    }
  }
}

// ---------------- q post: l2norm, scale, learnable-token dots ---------------------
__global__ void __launch_bounds__(256)
qpost_kernel(const float* __restrict__ temp, const float* __restrict__ qe,
             const float* __restrict__ lt, const float* __restrict__ lb)
{
  int w = (blockIdx.x * 256 + threadIdx.x) >> 5;   // (b*8+h)*4096+n
  int lane = threadIdx.x & 31;
  int n = w & 4095;
  int bh = w >> 12;
  int h = bh & 7, b = bh >> 3;
  float qv = g_qtmp[(b*4096+n)*256 + h*32 + lane];
  float ss = warpSum(qv*qv);
  float qn = qv / fmaxf(sqrtf(ss), EPSF);
  int yi = n >> 6, xj = n & 63;
  int ch = min(yi+1,63) - max(yi-1,0) + 1;
  int cw = min(xj+1,63) - max(xj-1,0) + 1;
  float sls = logf((float)(ch*cw) + 64.f);
  float sp = log1pf(expf(temp[h]));
  g_q[w*32 + lane] = (qn + qe[h*32+lane]) * sp * sls;
  #pragma unroll
  for (int l=0;l<9;l++){
    float p = warpSum(qn * lt[h*288 + lane*9 + l]);
    if (lane == l) g_ltd[w*9 + l] = p + lb[h*9+l];
  }
}

// ---------------- kv post: l2-normalize k half per head (in place) ---------------
__global__ void __launch_bounds__(256)
kvpost_kernel()
{
  int w = (blockIdx.x*256 + threadIdx.x) >> 5;  // row*8+h
  int lane = threadIdx.x & 31;
  int h = w & 7, row = w >> 3;
  float* p = g_kv + row*512 + h*32 + lane;
  float v = *p;
  float ss = warpSum(v*v);
  *p = v / fmaxf(sqrtf(ss), EPSF);
}

__global__ void __launch_bounds__(256)
kvp2post_kernel()
{
  int w = (blockIdx.x*256 + threadIdx.x) >> 5;  // row*8+h, row < 256
  int lane = threadIdx.x & 31;
  int h = w & 7, row = w >> 3;
  float* p = g_kvp2 + row*512 + h*32 + lane;
  float v = *p;
  float ss = warpSum(v*v);
  *p = v / fmaxf(sqrtf(ss), EPSF);
}

// ---------------- gating (routed top-2, shared, w0) ------------------------------
__global__ void __launch_bounds__(256)
gates_kernel(const float* __restrict__ x, const float* __restrict__ wg,
             const float* __restrict__ wg0, const float* __restrict__ wg1)
{
  int w = (blockIdx.x*256 + threadIdx.x) >> 5;   // row = b*4096+n
  int lane = threadIdx.x & 31;
  const float* xr = x + w*256;
  float xv[8];
  {
    float4 a = *(const float4*)(xr + lane*8);
    float4 c = *(const float4*)(xr + lane*8 + 4);
    xv[0]=a.x; xv[1]=a.y; xv[2]=a.z; xv[3]=a.w;
    xv[4]=c.x; xv[5]=c.y; xv[6]=c.z; xv[7]=c.w;
  }
  float d[10];
  #pragma unroll
  for (int r=0;r<10;r++){
    const float* wr = (r<4) ? (wg + r*256) : ((r<6) ? (wg0 + (r-4)*256) : (wg1 + (r-6)*256));
    float pp = 0.f;
    #pragma unroll
    for (int k=0;k<8;k++) pp = fmaf(xv[k], wr[lane*8+k], pp);
    d[r] = warpSum(pp);
  }
  if (lane == 0){
    float m = fmaxf(fmaxf(d[0],d[1]),fmaxf(d[2],d[3]));
    float e[4], se=0.f;
    #pragma unroll
    for (int k=0;k<4;k++){ e[k]=expf(d[k]-m); se+=e[k]; }
    float gg[4];
    #pragma unroll
    for (int k=0;k<4;k++) gg[k]=e[k]/se;
    int i0=0;
    #pragma unroll
    for (int k=1;k<4;k++) if (gg[k]>gg[i0]) i0=k;
    int i1=-1;
    #pragma unroll
    for (int k=0;k<4;k++) if (k!=i0 && (i1<0 || gg[k]>gg[i1])) i1=k;
    float s2 = fmaxf(gg[i0]+gg[i1], EPSF);
    float routed[4]={0.f,0.f,0.f,0.f};
    routed[i0]=gg[i0]/s2*2.f; routed[i1]=gg[i1]/s2*2.f;
    float m0 = fmaxf(d[4],d[5]);
    float e4=expf(d[4]-m0), e5=expf(d[5]-m0);
    float w00 = e4/(e4+e5)*2.f, w01 = e5/(e4+e5)*2.f;
    float m1 = fmaxf(fmaxf(d[6],d[7]),fmaxf(d[8],d[9]));
    float es[4], ss2=0.f;
    #pragma unroll
    for (int k=0;k<4;k++){ es[k]=expf(d[6+k]-m1); ss2+=es[k]; }
    float* gp = g_gate + w*8;
    #pragma unroll
    for (int k=0;k<4;k++) gp[k]   = w00 * (es[k]/ss2*4.f);
    #pragma unroll
    for (int k=0;k<4;k++) gp[4+k] = w01 * routed[k];
  }
}

// ---------------- 8x8 avg pool + LayerNorm ---------------------------------------
__global__ void __launch_bounds__(256)
pool_ln_kernel(const float* __restrict__ ng, const float* __restrict__ nb)
{
  int b = blockIdx.x >> 6, p = blockIdx.x & 63;
  int c = threadIdx.x;
  int pi = p >> 3, pj = p & 7;
  float s = 0.f;
  #pragma unroll
  for (int si=0; si<8; si++){
    int rowbase = b*4096 + (pi*8+si)*64 + pj*8;
    #pragma unroll
    for (int sj=0; sj<8; sj++)
      s += g_xs[(rowbase + sj)*256 + c];
  }
  float v = s * (1.f/64.f);
  __shared__ float shs[8], shq[8];
  int lane = c & 31, wid = c >> 5;
  float s1 = warpSum(v), sq = warpSum(v*v);
  if (lane==0){ shs[wid]=s1; shq[wid]=sq; }
  __syncthreads();
  float tot=0.f, totq=0.f;
  #pragma unroll
  for (int i=0;i<8;i++){ tot+=shs[i]; totq+=shq[i]; }
  float mu = tot*(1.f/256.f);
  float var = totq*(1.f/256.f) - mu*mu;
  g_pool[(b*64+p)*256 + c] = (v-mu)*rsqrtf(var+1e-5f)*ng[c] + nb[c];
}

// ---------------- cpb MLP --------------------------------------------------------
__global__ void __launch_bounds__(256)
cpb_hidden_kernel(const float* __restrict__ ct, const float* __restrict__ w1,
                  const float* __restrict__ b1)
{
  int tid = blockIdx.x*256 + threadIdx.x;
  if (tid >= 4096*512) return;
  int t = tid >> 9, j = tid & 511;
  float v = fmaf(ct[t*2], w1[j*2], fmaf(ct[t*2+1], w1[j*2+1], b1[j]));
  g_cpbh[tid] = fmaxf(v, 0.f);
}

__global__ void __launch_bounds__(256)
cpb_out_kernel(const float* __restrict__ w2, const float* __restrict__ b2)
{
  int t = (blockIdx.x*256 + threadIdx.x) >> 5;   // table row
  int lane = threadIdx.x & 31;
  float s[8] = {0,0,0,0,0,0,0,0};
  #pragma unroll
  for (int it=0; it<16; it++){
    float hv = g_cpbh[t*512 + it*32 + lane];
    #pragma unroll
    for (int h=0;h<8;h++) s[h] = fmaf(hv, w2[h*512 + it*32 + lane], s[h]);
  }
  #pragma unroll
  for (int h=0;h<8;h++){
    float tot = warpSum(s[h]);
    if (lane == 0) g_cpb[t*8 + h] = tot + b2[h];
  }
}

// ---------------- fused local+pool attention -------------------------------------
__global__ void __launch_bounds__(256)
attn_kernel(const float* __restrict__ rpb, const int* __restrict__ rpi)
{
  __shared__ float ks[32*64];   // k_pool transposed [d][p]
  __shared__ float vs[64*32];   // v_pool [p][d]
  const int bh = blockIdx.y;
  const int h = bh & 7, b = bh >> 3;
  const int tid = threadIdx.x;
  for (int idx = tid; idx < 2048; idx += 256){
    int p = idx >> 5, d = idx & 31;
    const float* base = g_kvp2 + (b*64+p)*512 + h*32 + d;
    ks[d*64+p] = base[0];
    vs[idx]    = base[256];
  }
  __syncthreads();
  const int warp = tid >> 5, lane = tid & 31;
  float rpbl[9];
  #pragma unroll
  for (int l=0;l<9;l++) rpbl[l] = rpb[h*9+l];

  for (int it=0; it<8; it++){
    int n = blockIdx.x*64 + warp*8 + it;
    int yi = n >> 6, xj = n & 63;
    float qs = g_q[((b*8+h)*4096 + n)*32 + lane];
    // local window scores (zero-padded -> score = rpb, v = 0)
    float sloc[9]; int nloc[9];
    #pragma unroll
    for (int l=0;l<9;l++){
      int y  = yi + l/3 - 1;
      int x2 = xj + l%3 - 1;
      bool val = ((unsigned)y < 64u) && ((unsigned)x2 < 64u);
      int nl = y*64 + x2;
      nloc[l] = val ? nl : -1;
      float kd = val ? g_kv[(b*4096+nl)*512 + h*32 + lane] : 0.f;
      sloc[l] = warpSum(qs*kd) + rpbl[l];
    }
    // pool scores: lane handles p=lane and p=lane+32
    const int* rr = rpi + n*64;
    int ia = rr[lane], ib = rr[lane+32];
    float s0 = g_cpb[ia*8+h];
    float s1 = g_cpb[ib*8+h];
    #pragma unroll
    for (int d=0; d<32; d++){
      float qd = __shfl_sync(0xffffffffu, qs, d);
      s0 = fmaf(qd, ks[d*64+lane],    s0);
      s1 = fmaf(qd, ks[d*64+lane+32], s1);
    }
    // softmax over 73
    float m = fmaxf(s0, s1);
    #pragma unroll
    for (int l=0;l<9;l++) m = fmaxf(m, sloc[l]);
    m = warpMax(m);
    float el[9], suml = 0.f;
    #pragma unroll
    for (int l=0;l<9;l++){ el[l] = expf(sloc[l]-m); suml += el[l]; }
    float e0 = expf(s0-m), e1 = expf(s1-m);
    float inv = 1.f / (suml + warpSum(e0+e1));
    // local AV (+ learnable-token modulation)
    const float* ltdp = g_ltd + ((b*8+h)*4096 + n)*9;
    float outv = 0.f;
    #pragma unroll
    for (int l=0;l<9;l++){
      float al = el[l]*inv + ltdp[l];
      if (nloc[l] >= 0)
        outv = fmaf(al, g_kv[(b*4096+nloc[l])*512 + 256 + h*32 + lane], outv);
    }
    // pool AV
    #pragma unroll
    for (int p=0;p<32;p++){
      float ap = __shfl_sync(0xffffffffu, e0, p) * inv;
      outv = fmaf(ap, vs[p*32+lane], outv);
    }
    #pragma unroll
    for (int p=0;p<32;p++){
      float ap = __shfl_sync(0xffffffffu, e1, p) * inv;
      outv = fmaf(ap, vs[(p+32)*32+lane], outv);
    }
    float gate = g_gate[(b*4096+n)*8 + h];
    g_attnout[(b*4096+n)*256 + h*32 + lane] = outv * gate;
  }
}

// ---------------- launch ---------------------------------------------------------
extern "C" void kernel_launch(void* const* d_in, const int* in_sizes, int n_in,
                              void* d_out, int out_size)
{
  const float* x      = (const float*)d_in[0];
  const float* ctab   = (const float*)d_in[1];
  const float* q_w    = (const float*)d_in[2];
  const float* q_b    = (const float*)d_in[3];
  const float* kv_w   = (const float*)d_in[4];
  const float* kv_b   = (const float*)d_in[5];
  const float* temp   = (const float*)d_in[6];
  const float* qe     = (const float*)d_in[7];
  const float* rpb    = (const float*)d_in[8];
  const float* lt     = (const float*)d_in[9];
  const float* lb     = (const float*)d_in[10];
  const float* cpb1_w = (const float*)d_in[11];
  const float* cpb1_b = (const float*)d_in[12];
  const float* cpb2_w = (const float*)d_in[13];
  const float* cpb2_b = (const float*)d_in[14];
  const float* sr_w   = (const float*)d_in[15];
  const float* sr_b   = (const float*)d_in[16];
  const float* norm_g = (const float*)d_in[17];
  const float* norm_b = (const float*)d_in[18];
  const float* wg_w   = (const float*)d_in[19];
  const float* wg0_w  = (const float*)d_in[20];
  const float* wg1_w  = (const float*)d_in[21];
  const float* proj_w = (const float*)d_in[22];
  const float* proj_b = (const float*)d_in[23];
  const int*   rpi    = (const int*)d_in[24];
  float* out = (float*)d_out;

  float *p_qtmp, *p_kv, *p_xs, *p_pool, *p_kvp2, *p_attnout;
  cudaGetSymbolAddress((void**)&p_qtmp,    g_qtmp);
  cudaGetSymbolAddress((void**)&p_kv,      g_kv);
  cudaGetSymbolAddress((void**)&p_xs,      g_xs);
  cudaGetSymbolAddress((void**)&p_pool,    g_pool);
  cudaGetSymbolAddress((void**)&p_kvp2,    g_kvp2);
  cudaGetSymbolAddress((void**)&p_attnout, g_attnout);

  const int M = NBATCH*NTOK;   // 16384

  // gating (only needs x)
  gates_kernel<<<2048, 256>>>(x, wg_w, wg0_w, wg1_w);
  // q path
  sgemm_kernel<false><<<dim3(2,128), 256>>>(x, q_w, q_b, p_qtmp, M, 256, 256);
  qpost_kernel<<<16384, 256>>>(temp, qe, lt, lb);
  // kv path
  sgemm_kernel<false><<<dim3(4,128), 256>>>(x, kv_w, kv_b, p_kv, M, 512, 256);
  kvpost_kernel<<<16384, 256>>>();
  // pooled path
  sgemm_kernel<true><<<dim3(2,128), 256>>>(x, sr_w, sr_b, p_xs, M, 256, 256);
  pool_ln_kernel<<<256, 256>>>(norm_g, norm_b);
  sgemm_kernel<false><<<dim3(4,2), 256>>>(p_pool, kv_w, kv_b, p_kvp2, 256, 512, 256);
  kvp2post_kernel<<<256, 256>>>();
  // cpb MLP
  cpb_hidden_kernel<<<8192, 256>>>(ctab, cpb1_w, cpb1_b);
  cpb_out_kernel<<<512, 256>>>(cpb2_w, cpb2_b);
  // fused attention
  attn_kernel<<<dim3(64, 32), 256>>>(rpb, rpi);
  // projection
  sgemm_kernel<false><<<dim3(2,128), 256>>>(p_attnout, proj_w, proj_b, out, M, 256, 256);
}

// round 8
// speedup vs baseline: 1.1118x; 1.0498x over previous
#include <cuda_runtime.h>
#include <math.h>

#define NBATCH 4
#define NTOK   4096
#define NC     256
#define NH     8
#define ND     32
#define NPL    64
#define EPSF   1.1920929e-07f

// ---------------- scratch (device globals; no runtime alloc allowed) -------------
__device__ float g_qtmp[NBATCH*NTOK*NC];        // raw q gemm out (16 MB)
__device__ float g_q[NBATCH*NTOK*NC];           // q_scaled, layout (B,H,N,D) (16 MB)
__device__ float g_ltd[NBATCH*NH*NTOK*9];       // learnable-token dots + bias (4.7 MB)
__device__ float g_kv[NBATCH*NTOK*2*NC];        // kv, k-half l2-normalized in place (32 MB)
__device__ float g_gate[NBATCH*NTOK*NH];        // per-head gates (0.5 MB)
__device__ float g_xs[NBATCH*NTOK*NC];          // sr+gelu out (16 MB)
__device__ float g_pool[NBATCH*NPL*NC];         // pooled + LN (0.25 MB)
__device__ float g_kvp2[NBATCH*NPL*2*NC];       // pooled kv, k-half normalized (0.5 MB)
__device__ float g_cpbh[4096*512];              // cpb hidden (8 MB)
__device__ float g_cpb[4096*NH];                // cpb table (128 KB)
__device__ float g_attnout[NBATCH*NTOK*NC];     // pre-proj attention out (16 MB)

// ---------------- helpers --------------------------------------------------------
__device__ __forceinline__ float warpSum(float v){
  #pragma unroll
  for (int o=16;o>0;o>>=1) v += __shfl_xor_sync(0xffffffffu, v, o);
  return v;
}
__device__ __forceinline__ float warpMax(float v){
  #pragma unroll
  for (int o=16;o>0;o>>=1) v = fmaxf(v, __shfl_xor_sync(0xffffffffu, v, o));
  return v;
}

// packed f32x2 helpers (Blackwell FFMA2 path — 2 exact fp32 FMAs per issue)
__device__ __forceinline__ unsigned long long pack2(float lo, float hi){
  unsigned long long r;
  asm("mov.b64 %0, {%1, %2};" : "=l"(r) : "f"(lo), "f"(hi));
  return r;
}
__device__ __forceinline__ void unpack2(unsigned long long v, float& lo, float& hi){
  asm("mov.b64 {%0, %1}, %2;" : "=f"(lo), "=f"(hi) : "l"(v));
}
__device__ __forceinline__ void ffma2(unsigned long long& d,
                                      unsigned long long a, unsigned long long b){
  asm("fma.rn.f32x2 %0, %1, %2, %0;" : "+l"(d) : "l"(a), "l"(b));
}

// ---------------- fp32 SGEMM: C = A(MxK) * W(NxK)^T + bias -----------------------
// 128x128 block tile, 8x8 per thread, double-buffered SMEM, conflict-free
// fragment layout; inner product via packed fma.rn.f32x2 (FFMA2).
template<bool GELU>
__global__ void __launch_bounds__(256, 2)
sgemm_kernel(const float* __restrict__ A, const float* __restrict__ W,
             const float* __restrict__ bias, float* __restrict__ C,
             int M, int N, int K)
{
  __shared__ float As[2][16][128];
  __shared__ float Ws[2][16][128];
  const int tid = threadIdx.x;
  const int m0 = blockIdx.y * 128;
  const int n0 = blockIdx.x * 128;
  const int lrow = tid >> 1;         // loader row within tile (0..127)
  const int lk   = (tid & 1) * 8;    // loader k offset (0 or 8)

  const int wid  = tid >> 5, lane = tid & 31;
  const int wy   = wid & 3;          // warp row group (4 along M)
  const int wx   = wid >> 2;         // warp col group (2 along N)
  const int ly   = lane >> 3;        // 0..3
  const int lx   = lane & 7;         // 0..7
  const int ra   = wy*32 + ly*4;     // A fragment base row in tile
  const int cb   = wx*64 + lx*4;     // W fragment base col in tile

  const float* Ap = A + (long)(m0 + lrow) * K + lk;
  const float* Wp = W + (long)(n0 + lrow) * K + lk;

  // acc2[i][j]: packed pair = cols {2j, 2j+1} of the 8-col fragment for row i
  unsigned long long acc2[8][4];
  #pragma unroll
  for (int i=0;i<8;i++)
    #pragma unroll
    for (int j=0;j<4;j++) acc2[i][j]=0ULL;

  // initial tile -> buffer 0
  {
    float4 a0 = *(const float4*)(Ap);
    float4 a1 = *(const float4*)(Ap+4);
    float4 w0 = *(const float4*)(Wp);
    float4 w1 = *(const float4*)(Wp+4);
    As[0][lk+0][lrow]=a0.x; As[0][lk+1][lrow]=a0.y; As[0][lk+2][lrow]=a0.z; As[0][lk+3][lrow]=a0.w;
    As[0][lk+4][lrow]=a1.x; As[0][lk+5][lrow]=a1.y; As[0][lk+6][lrow]=a1.z; As[0][lk+7][lrow]=a1.w;
    Ws[0][lk+0][lrow]=w0.x; Ws[0][lk+1][lrow]=w0.y; Ws[0][lk+2][lrow]=w0.z; Ws[0][lk+3][lrow]=w0.w;
    Ws[0][lk+4][lrow]=w1.x; Ws[0][lk+5][lrow]=w1.y; Ws[0][lk+6][lrow]=w1.z; Ws[0][lk+7][lrow]=w1.w;
  }
  __syncthreads();

  int buf = 0;
  for (int k0 = 0; k0 < K; k0 += 16){
    const bool more = (k0 + 16 < K);
    float4 pa0, pa1, pw0, pw1;
    if (more){
      pa0 = *(const float4*)(Ap + k0 + 16);
      pa1 = *(const float4*)(Ap + k0 + 20);
      pw0 = *(const float4*)(Wp + k0 + 16);
      pw1 = *(const float4*)(Wp + k0 + 20);
    }
    #pragma unroll
    for (int kk=0; kk<16; kk++){
      float4 af0 = *(const float4*)(&As[buf][kk][ra]);
      float4 af1 = *(const float4*)(&As[buf][kk][ra+16]);
      float4 wf0 = *(const float4*)(&Ws[buf][kk][cb]);
      float4 wf1 = *(const float4*)(&Ws[buf][kk][cb+32]);
      // broadcast-pack A rows, pair-pack W cols
      unsigned long long ab[8], wp2[4];
      ab[0]=pack2(af0.x,af0.x); ab[1]=pack2(af0.y,af0.y);
      ab[2]=pack2(af0.z,af0.z); ab[3]=pack2(af0.w,af0.w);
      ab[4]=pack2(af1.x,af1.x); ab[5]=pack2(af1.y,af1.y);
      ab[6]=pack2(af1.z,af1.z); ab[7]=pack2(af1.w,af1.w);
      wp2[0]=pack2(wf0.x,wf0.y); wp2[1]=pack2(wf0.z,wf0.w);
      wp2[2]=pack2(wf1.x,wf1.y); wp2[3]=pack2(wf1.z,wf1.w);
      #pragma unroll
      for (int i=0;i<8;i++)
        #pragma unroll
        for (int j=0;j<4;j++)
          ffma2(acc2[i][j], ab[i], wp2[j]);
    }
    if (more){
      int nb = buf ^ 1;
      As[nb][lk+0][lrow]=pa0.x; As[nb][lk+1][lrow]=pa0.y; As[nb][lk+2][lrow]=pa0.z; As[nb][lk+3][lrow]=pa0.w;
      As[nb][lk+4][lrow]=pa1.x; As[nb][lk+5][lrow]=pa1.y; As[nb][lk+6][lrow]=pa1.z; As[nb][lk+7][lrow]=pa1.w;
      Ws[nb][lk+0][lrow]=pw0.x; Ws[nb][lk+1][lrow]=pw0.y; Ws[nb][lk+2][lrow]=pw0.z; Ws[nb][lk+3][lrow]=pw0.w;
      Ws[nb][lk+4][lrow]=pw1.x; Ws[nb][lk+5][lrow]=pw1.y; Ws[nb][lk+6][lrow]=pw1.z; Ws[nb][lk+7][lrow]=pw1.w;
    }
    __syncthreads();
    buf ^= 1;
  }

  #pragma unroll
  for (int i=0;i<8;i++){
    int m = m0 + ra + ((i < 4) ? i : (12 + i));   // rows ra+{0..3}, ra+16+{0..3}
    #pragma unroll
    for (int jg=0;jg<2;jg++){
      int n = n0 + cb + jg*32;
      float4 v;
      unpack2(acc2[i][jg*2+0], v.x, v.y);
      unpack2(acc2[i][jg*2+1], v.z, v.w);
      v.x += bias[n+0];
      v.y += bias[n+1];
      v.z += bias[n+2];
      v.w += bias[n+3];
      if (GELU){
        v.x = 0.5f*v.x*(1.f + erff(v.x*0.70710678118654752f));
        v.y = 0.5f*v.y*(1.f + erff(v.y*0.70710678118654752f));
        v.z = 0.5f*v.z*(1.f + erff(v.z*0.70710678118654752f));
        v.w = 0.5f*v.w*(1.f + erff(v.w*0.70710678118654752f));
      }
      *(float4*)(C + (long)m*N + n) = v;
    }
  }
}

// ---------------- q post: l2norm, scale, learnable-token dots ---------------------
__global__ void __launch_bounds__(256)
qpost_kernel(const float* __restrict__ temp, const float* __restrict__ qe,
             const float* __restrict__ lt, const float* __restrict__ lb)
{
  int w = (blockIdx.x * 256 + threadIdx.x) >> 5;   // (b*8+h)*4096+n
  int lane = threadIdx.x & 31;
  int n = w & 4095;
  int bh = w >> 12;
  int h = bh & 7, b = bh >> 3;
  float qv = g_qtmp[(b*4096+n)*256 + h*32 + lane];
  float ss = warpSum(qv*qv);
  float qn = qv / fmaxf(sqrtf(ss), EPSF);
  int yi = n >> 6, xj = n & 63;
  int ch = min(yi+1,63) - max(yi-1,0) + 1;
  int cw = min(xj+1,63) - max(xj-1,0) + 1;
  float sls = logf((float)(ch*cw) + 64.f);
  float sp = log1pf(expf(temp[h]));
  g_q[w*32 + lane] = (qn + qe[h*32+lane]) * sp * sls;
  #pragma unroll
  for (int l=0;l<9;l++){
    float p = warpSum(qn * lt[h*288 + lane*9 + l]);
    if (lane == l) g_ltd[w*9 + l] = p + lb[h*9+l];
  }
}

// ---------------- kv post: l2-normalize k half per head (in place) ---------------
__global__ void __launch_bounds__(256)
kvpost_kernel()
{
  int w = (blockIdx.x*256 + threadIdx.x) >> 5;  // row*8+h
  int lane = threadIdx.x & 31;
  int h = w & 7, row = w >> 3;
  float* p = g_kv + row*512 + h*32 + lane;
  float v = *p;
  float ss = warpSum(v*v);
  *p = v / fmaxf(sqrtf(ss), EPSF);
}

__global__ void __launch_bounds__(256)
kvp2post_kernel()
{
  int w = (blockIdx.x*256 + threadIdx.x) >> 5;  // row*8+h, row < 256
  int lane = threadIdx.x & 31;
  int h = w & 7, row = w >> 3;
  float* p = g_kvp2 + row*512 + h*32 + lane;
  float v = *p;
  float ss = warpSum(v*v);
  *p = v / fmaxf(sqrtf(ss), EPSF);
}

// ---------------- gating (routed top-2, shared, w0) ------------------------------
__global__ void __launch_bounds__(256)
gates_kernel(const float* __restrict__ x, const float* __restrict__ wg,
             const float* __restrict__ wg0, const float* __restrict__ wg1)
{
  int w = (blockIdx.x*256 + threadIdx.x) >> 5;   // row = b*4096+n
  int lane = threadIdx.x & 31;
  const float* xr = x + w*256;
  float xv[8];
  {
    float4 a = *(const float4*)(xr + lane*8);
    float4 c = *(const float4*)(xr + lane*8 + 4);
    xv[0]=a.x; xv[1]=a.y; xv[2]=a.z; xv[3]=a.w;
    xv[4]=c.x; xv[5]=c.y; xv[6]=c.z; xv[7]=c.w;
  }
  float d[10];
  #pragma unroll
  for (int r=0;r<10;r++){
    const float* wr = (r<4) ? (wg + r*256) : ((r<6) ? (wg0 + (r-4)*256) : (wg1 + (r-6)*256));
    float pp = 0.f;
    #pragma unroll
    for (int k=0;k<8;k++) pp = fmaf(xv[k], wr[lane*8+k], pp);
    d[r] = warpSum(pp);
  }
  if (lane == 0){
    float m = fmaxf(fmaxf(d[0],d[1]),fmaxf(d[2],d[3]));
    float e[4], se=0.f;
    #pragma unroll
    for (int k=0;k<4;k++){ e[k]=expf(d[k]-m); se+=e[k]; }
    float gg[4];
    #pragma unroll
    for (int k=0;k<4;k++) gg[k]=e[k]/se;
    int i0=0;
    #pragma unroll
    for (int k=1;k<4;k++) if (gg[k]>gg[i0]) i0=k;
    int i1=-1;
    #pragma unroll
    for (int k=0;k<4;k++) if (k!=i0 && (i1<0 || gg[k]>gg[i1])) i1=k;
    float s2 = fmaxf(gg[i0]+gg[i1], EPSF);
    float routed[4]={0.f,0.f,0.f,0.f};
    routed[i0]=gg[i0]/s2*2.f; routed[i1]=gg[i1]/s2*2.f;
    float m0 = fmaxf(d[4],d[5]);
    float e4=expf(d[4]-m0), e5=expf(d[5]-m0);
    float w00 = e4/(e4+e5)*2.f, w01 = e5/(e4+e5)*2.f;
    float m1 = fmaxf(fmaxf(d[6],d[7]),fmaxf(d[8],d[9]));
    float es[4], ss2=0.f;
    #pragma unroll
    for (int k=0;k<4;k++){ es[k]=expf(d[6+k]-m1); ss2+=es[k]; }
    float* gp = g_gate + w*8;
    #pragma unroll
    for (int k=0;k<4;k++) gp[k]   = w00 * (es[k]/ss2*4.f);
    #pragma unroll
    for (int k=0;k<4;k++) gp[4+k] = w01 * routed[k];
  }
}

// ---------------- 8x8 avg pool + LayerNorm ---------------------------------------
__global__ void __launch_bounds__(256)
pool_ln_kernel(const float* __restrict__ ng, const float* __restrict__ nb)
{
  int b = blockIdx.x >> 6, p = blockIdx.x & 63;
  int c = threadIdx.x;
  int pi = p >> 3, pj = p & 7;
  float s = 0.f;
  #pragma unroll
  for (int si=0; si<8; si++){
    int rowbase = b*4096 + (pi*8+si)*64 + pj*8;
    #pragma unroll
    for (int sj=0; sj<8; sj++)
      s += g_xs[(rowbase + sj)*256 + c];
  }
  float v = s * (1.f/64.f);
  __shared__ float shs[8], shq[8];
  int lane = c & 31, wid = c >> 5;
  float s1 = warpSum(v), sq = warpSum(v*v);
  if (lane==0){ shs[wid]=s1; shq[wid]=sq; }
  __syncthreads();
  float tot=0.f, totq=0.f;
  #pragma unroll
  for (int i=0;i<8;i++){ tot+=shs[i]; totq+=shq[i]; }
  float mu = tot*(1.f/256.f);
  float var = totq*(1.f/256.f) - mu*mu;
  g_pool[(b*64+p)*256 + c] = (v-mu)*rsqrtf(var+1e-5f)*ng[c] + nb[c];
}

// ---------------- cpb MLP --------------------------------------------------------
__global__ void __launch_bounds__(256)
cpb_hidden_kernel(const float* __restrict__ ct, const float* __restrict__ w1,
                  const float* __restrict__ b1)
{
  int tid = blockIdx.x*256 + threadIdx.x;
  if (tid >= 4096*512) return;
  int t = tid >> 9, j = tid & 511;
  float v = fmaf(ct[t*2], w1[j*2], fmaf(ct[t*2+1], w1[j*2+1], b1[j]));
  g_cpbh[tid] = fmaxf(v, 0.f);
}

__global__ void __launch_bounds__(256)
cpb_out_kernel(const float* __restrict__ w2, const float* __restrict__ b2)
{
  int t = (blockIdx.x*256 + threadIdx.x) >> 5;   // table row
  int lane = threadIdx.x & 31;
  float s[8] = {0,0,0,0,0,0,0,0};
  #pragma unroll
  for (int it=0; it<16; it++){
    float hv = g_cpbh[t*512 + it*32 + lane];
    #pragma unroll
    for (int h=0;h<8;h++) s[h] = fmaf(hv, w2[h*512 + it*32 + lane], s[h]);
  }
  #pragma unroll
  for (int h=0;h<8;h++){
    float tot = warpSum(s[h]);
    if (lane == 0) g_cpb[t*8 + h] = tot + b2[h];
  }
}

// ---------------- fused local+pool attention -------------------------------------
__global__ void __launch_bounds__(256)
attn_kernel(const float* __restrict__ rpb, const int* __restrict__ rpi)
{
  __shared__ float ks[32*64];   // k_pool transposed [d][p]
  __shared__ float vs[64*32];   // v_pool [p][d]
  const int bh = blockIdx.y;
  const int h = bh & 7, b = bh >> 3;
  const int tid = threadIdx.x;
  for (int idx = tid; idx < 2048; idx += 256){
    int p = idx >> 5, d = idx & 31;
    const float* base = g_kvp2 + (b*64+p)*512 + h*32 + d;
    ks[d*64+p] = base[0];
    vs[idx]    = base[256];
  }
  __syncthreads();
  const int warp = tid >> 5, lane = tid & 31;
  float rpbl[9];
  #pragma unroll
  for (int l=0;l<9;l++) rpbl[l] = rpb[h*9+l];

  for (int it=0; it<8; it++){
    int n = blockIdx.x*64 + warp*8 + it;
    int yi = n >> 6, xj = n & 63;
    float qs = g_q[((b*8+h)*4096 + n)*32 + lane];
    // local window scores (zero-padded -> score = rpb, v = 0)
    float sloc[9]; int nloc[9];
    #pragma unroll
    for (int l=0;l<9;l++){
      int y  = yi + l/3 - 1;
      int x2 = xj + l%3 - 1;
      bool val = ((unsigned)y < 64u) && ((unsigned)x2 < 64u);
      int nl = y*64 + x2;
      nloc[l] = val ? nl : -1;
      float kd = val ? g_kv[(b*4096+nl)*512 + h*32 + lane] : 0.f;
      sloc[l] = warpSum(qs*kd) + rpbl[l];
    }
    // pool scores: lane handles p=lane and p=lane+32
    const int* rr = rpi + n*64;
    int ia = rr[lane], ib = rr[lane+32];
    float s0 = g_cpb[ia*8+h];
    float s1 = g_cpb[ib*8+h];
    #pragma unroll
    for (int d=0; d<32; d++){
      float qd = __shfl_sync(0xffffffffu, qs, d);
      s0 = fmaf(qd, ks[d*64+lane],    s0);
      s1 = fmaf(qd, ks[d*64+lane+32], s1);
    }
    // softmax over 73
    float m = fmaxf(s0, s1);
    #pragma unroll
    for (int l=0;l<9;l++) m = fmaxf(m, sloc[l]);
    m = warpMax(m);
    float el[9], suml = 0.f;
    #pragma unroll
    for (int l=0;l<9;l++){ el[l] = expf(sloc[l]-m); suml += el[l]; }
    float e0 = expf(s0-m), e1 = expf(s1-m);
    float inv = 1.f / (suml + warpSum(e0+e1));
    // local AV (+ learnable-token modulation)
    const float* ltdp = g_ltd + ((b*8+h)*4096 + n)*9;
    float outv = 0.f;
    #pragma unroll
    for (int l=0;l<9;l++){
      float al = el[l]*inv + ltdp[l];
      if (nloc[l] >= 0)
        outv = fmaf(al, g_kv[(b*4096+nloc[l])*512 + 256 + h*32 + lane], outv);
    }
    // pool AV
    #pragma unroll
    for (int p=0;p<32;p++){
      float ap = __shfl_sync(0xffffffffu, e0, p) * inv;
      outv = fmaf(ap, vs[p*32+lane], outv);
    }
    #pragma unroll
    for (int p=0;p<32;p++){
      float ap = __shfl_sync(0xffffffffu, e1, p) * inv;
      outv = fmaf(ap, vs[(p+32)*32+lane], outv);
    }
    float gate = g_gate[(b*4096+n)*8 + h];
    g_attnout[(b*4096+n)*256 + h*32 + lane] = outv * gate;
  }
}

// ---------------- launch ---------------------------------------------------------
extern "C" void kernel_launch(void* const* d_in, const int* in_sizes, int n_in,
                              void* d_out, int out_size)
{
  const float* x      = (const float*)d_in[0];
  const float* ctab   = (const float*)d_in[1];
  const float* q_w    = (const float*)d_in[2];
  const float* q_b    = (const float*)d_in[3];
  const float* kv_w   = (const float*)d_in[4];
  const float* kv_b   = (const float*)d_in[5];
  const float* temp   = (const float*)d_in[6];
  const float* qe     = (const float*)d_in[7];
  const float* rpb    = (const float*)d_in[8];
  const float* lt     = (const float*)d_in[9];
  const float* lb     = (const float*)d_in[10];
  const float* cpb1_w = (const float*)d_in[11];
  const float* cpb1_b = (const float*)d_in[12];
  const float* cpb2_w = (const float*)d_in[13];
  const float* cpb2_b = (const float*)d_in[14];
  const float* sr_w   = (const float*)d_in[15];
  const float* sr_b   = (const float*)d_in[16];
  const float* norm_g = (const float*)d_in[17];
  const float* norm_b = (const float*)d_in[18];
  const float* wg_w   = (const float*)d_in[19];
  const float* wg0_w  = (const float*)d_in[20];
  const float* wg1_w  = (const float*)d_in[21];
  const float* proj_w = (const float*)d_in[22];
  const float* proj_b = (const float*)d_in[23];
  const int*   rpi    = (const int*)d_in[24];
  float* out = (float*)d_out;

  float *p_qtmp, *p_kv, *p_xs, *p_pool, *p_kvp2, *p_attnout;
  cudaGetSymbolAddress((void**)&p_qtmp,    g_qtmp);
  cudaGetSymbolAddress((void**)&p_kv,      g_kv);
  cudaGetSymbolAddress((void**)&p_xs,      g_xs);
  cudaGetSymbolAddress((void**)&p_pool,    g_pool);
  cudaGetSymbolAddress((void**)&p_kvp2,    g_kvp2);
  cudaGetSymbolAddress((void**)&p_attnout, g_attnout);

  const int M = NBATCH*NTOK;   // 16384

  // gating (only needs x)
  gates_kernel<<<2048, 256>>>(x, wg_w, wg0_w, wg1_w);
  // q path
  sgemm_kernel<false><<<dim3(2,128), 256>>>(x, q_w, q_b, p_qtmp, M, 256, 256);
  qpost_kernel<<<16384, 256>>>(temp, qe, lt, lb);
  // kv path
  sgemm_kernel<false><<<dim3(4,128), 256>>>(x, kv_w, kv_b, p_kv, M, 512, 256);
  kvpost_kernel<<<16384, 256>>>();
  // pooled path
  sgemm_kernel<true><<<dim3(2,128), 256>>>(x, sr_w, sr_b, p_xs, M, 256, 256);
  pool_ln_kernel<<<256, 256>>>(norm_g, norm_b);
  sgemm_kernel<false><<<dim3(4,2), 256>>>(p_pool, kv_w, kv_b, p_kvp2, 256, 512, 256);
  kvp2post_kernel<<<256, 256>>>();
  // cpb MLP
  cpb_hidden_kernel<<<8192, 256>>>(ctab, cpb1_w, cpb1_b);
  cpb_out_kernel<<<512, 256>>>(cpb2_w, cpb2_b);
  // fused attention
  attn_kernel<<<dim3(64, 32), 256>>>(rpb, rpi);
  // projection
  sgemm_kernel<false><<<dim3(2,128), 256>>>(p_attnout, proj_w, proj_b, out, M, 256, 256);
}

// round 9
// speedup vs baseline: 1.1497x; 1.0341x over previous
#include <cuda_runtime.h>
#include <math.h>

#define NBATCH 4
#define NTOK   4096
#define NC     256
#define NH     8
#define ND     32
#define NPL    64
#define EPSF   1.1920929e-07f

// ---------------- scratch (device globals; no runtime alloc allowed) -------------
__device__ float g_qtmp[NBATCH*NTOK*NC];        // raw q gemm out (16 MB)
__device__ float g_q[NBATCH*NTOK*NC];           // q_scaled, layout (B,H,N,D) (16 MB)
__device__ float g_ltd[NBATCH*NH*NTOK*9];       // learnable-token dots + bias (4.7 MB)
__device__ float g_kv[NBATCH*NTOK*2*NC];        // kv, k-half l2-normalized in place (32 MB)
__device__ float g_gate[NBATCH*NTOK*NH];        // per-head gates (0.5 MB)
__device__ float g_xs[NBATCH*NTOK*NC];          // sr+gelu out (16 MB)
__device__ float g_pool[NBATCH*NPL*NC];         // pooled + LN (0.25 MB)
__device__ float g_kvp2[NBATCH*NPL*2*NC];       // pooled kv, k-half normalized (0.5 MB)
__device__ float g_cpbh[4096*512];              // cpb hidden (8 MB)
__device__ float g_cpb[4096*NH];                // cpb table (128 KB)
__device__ float g_attnout[NBATCH*NTOK*NC];     // pre-proj attention out (16 MB)

// ---------------- helpers --------------------------------------------------------
__device__ __forceinline__ float warpSum(float v){
  #pragma unroll
  for (int o=16;o>0;o>>=1) v += __shfl_xor_sync(0xffffffffu, v, o);
  return v;
}
__device__ __forceinline__ float warpMax(float v){
  #pragma unroll
  for (int o=16;o>0;o>>=1) v = fmaxf(v, __shfl_xor_sync(0xffffffffu, v, o));
  return v;
}

// packed f32x2 helpers (Blackwell FFMA2 path — 2 exact fp32 FMAs per issue)
__device__ __forceinline__ unsigned long long pack2(float lo, float hi){
  unsigned long long r;
  asm("mov.b64 %0, {%1, %2};" : "=l"(r) : "f"(lo), "f"(hi));
  return r;
}
__device__ __forceinline__ void unpack2(unsigned long long v, float& lo, float& hi){
  asm("mov.b64 {%0, %1}, %2;" : "=f"(lo), "=f"(hi) : "l"(v));
}
__device__ __forceinline__ void ffma2(unsigned long long& d,
                                      unsigned long long a, unsigned long long b){
  asm("fma.rn.f32x2 %0, %1, %2, %0;" : "+l"(d) : "l"(a), "l"(b));
}

// ---------------- fp32 SGEMM: C = A(MxK) * W(NxK)^T + bias -----------------------
// 128x128 block tile, 8x8 per thread, double-buffered SMEM, conflict-free
// fragment layout; inner product via packed fma.rn.f32x2 (FFMA2).
template<bool GELU>
__global__ void __launch_bounds__(256, 2)
sgemm_kernel(const float* __restrict__ A, const float* __restrict__ W,
             const float* __restrict__ bias, float* __restrict__ C,
             int M, int N, int K)
{
  __shared__ float As[2][16][128];
  __shared__ float Ws[2][16][128];
  const int tid = threadIdx.x;
  const int m0 = blockIdx.y * 128;
  const int n0 = blockIdx.x * 128;
  const int lrow = tid >> 1;         // loader row within tile (0..127)
  const int lk   = (tid & 1) * 8;    // loader k offset (0 or 8)

  const int wid  = tid >> 5, lane = tid & 31;
  const int wy   = wid & 3;          // warp row group (4 along M)
  const int wx   = wid >> 2;         // warp col group (2 along N)
  const int ly   = lane >> 3;        // 0..3
  const int lx   = lane & 7;         // 0..7
  const int ra   = wy*32 + ly*4;     // A fragment base row in tile
  const int cb   = wx*64 + lx*4;     // W fragment base col in tile

  const float* Ap = A + (long)(m0 + lrow) * K + lk;
  const float* Wp = W + (long)(n0 + lrow) * K + lk;

  // acc2[i][j]: packed pair = cols {2j, 2j+1} of the 8-col fragment for row i
  unsigned long long acc2[8][4];
  #pragma unroll
  for (int i=0;i<8;i++)
    #pragma unroll
    for (int j=0;j<4;j++) acc2[i][j]=0ULL;

  // initial tile -> buffer 0
  {
    float4 a0 = *(const float4*)(Ap);
    float4 a1 = *(const float4*)(Ap+4);
    float4 w0 = *(const float4*)(Wp);
    float4 w1 = *(const float4*)(Wp+4);
    As[0][lk+0][lrow]=a0.x; As[0][lk+1][lrow]=a0.y; As[0][lk+2][lrow]=a0.z; As[0][lk+3][lrow]=a0.w;
    As[0][lk+4][lrow]=a1.x; As[0][lk+5][lrow]=a1.y; As[0][lk+6][lrow]=a1.z; As[0][lk+7][lrow]=a1.w;
    Ws[0][lk+0][lrow]=w0.x; Ws[0][lk+1][lrow]=w0.y; Ws[0][lk+2][lrow]=w0.z; Ws[0][lk+3][lrow]=w0.w;
    Ws[0][lk+4][lrow]=w1.x; Ws[0][lk+5][lrow]=w1.y; Ws[0][lk+6][lrow]=w1.z; Ws[0][lk+7][lrow]=w1.w;
  }
  __syncthreads();

  int buf = 0;
  for (int k0 = 0; k0 < K; k0 += 16){
    const bool more = (k0 + 16 < K);
    float4 pa0, pa1, pw0, pw1;
    if (more){
      pa0 = *(const float4*)(Ap + k0 + 16);
      pa1 = *(const float4*)(Ap + k0 + 20);
      pw0 = *(const float4*)(Wp + k0 + 16);
      pw1 = *(const float4*)(Wp + k0 + 20);
    }
    #pragma unroll
    for (int kk=0; kk<16; kk++){
      float4 af0 = *(const float4*)(&As[buf][kk][ra]);
      float4 af1 = *(const float4*)(&As[buf][kk][ra+16]);
      float4 wf0 = *(const float4*)(&Ws[buf][kk][cb]);
      float4 wf1 = *(const float4*)(&Ws[buf][kk][cb+32]);
      // broadcast-pack A rows, pair-pack W cols
      unsigned long long ab[8], wp2[4];
      ab[0]=pack2(af0.x,af0.x); ab[1]=pack2(af0.y,af0.y);
      ab[2]=pack2(af0.z,af0.z); ab[3]=pack2(af0.w,af0.w);
      ab[4]=pack2(af1.x,af1.x); ab[5]=pack2(af1.y,af1.y);
      ab[6]=pack2(af1.z,af1.z); ab[7]=pack2(af1.w,af1.w);
      wp2[0]=pack2(wf0.x,wf0.y); wp2[1]=pack2(wf0.z,wf0.w);
      wp2[2]=pack2(wf1.x,wf1.y); wp2[3]=pack2(wf1.z,wf1.w);
      #pragma unroll
      for (int i=0;i<8;i++)
        #pragma unroll
        for (int j=0;j<4;j++)
          ffma2(acc2[i][j], ab[i], wp2[j]);
    }
    if (more){
      int nb = buf ^ 1;
      As[nb][lk+0][lrow]=pa0.x; As[nb][lk+1][lrow]=pa0.y; As[nb][lk+2][lrow]=pa0.z; As[nb][lk+3][lrow]=pa0.w;
      As[nb][lk+4][lrow]=pa1.x; As[nb][lk+5][lrow]=pa1.y; As[nb][lk+6][lrow]=pa1.z; As[nb][lk+7][lrow]=pa1.w;
      Ws[nb][lk+0][lrow]=pw0.x; Ws[nb][lk+1][lrow]=pw0.y; Ws[nb][lk+2][lrow]=pw0.z; Ws[nb][lk+3][lrow]=pw0.w;
      Ws[nb][lk+4][lrow]=pw1.x; Ws[nb][lk+5][lrow]=pw1.y; Ws[nb][lk+6][lrow]=pw1.z; Ws[nb][lk+7][lrow]=pw1.w;
    }
    __syncthreads();
    buf ^= 1;
  }

  #pragma unroll
  for (int i=0;i<8;i++){
    int m = m0 + ra + ((i < 4) ? i : (12 + i));   // rows ra+{0..3}, ra+16+{0..3}
    #pragma unroll
    for (int jg=0;jg<2;jg++){
      int n = n0 + cb + jg*32;
      float4 v;
      unpack2(acc2[i][jg*2+0], v.x, v.y);
      unpack2(acc2[i][jg*2+1], v.z, v.w);
      v.x += bias[n+0];
      v.y += bias[n+1];
      v.z += bias[n+2];
      v.w += bias[n+3];
      if (GELU){
        v.x = 0.5f*v.x*(1.f + erff(v.x*0.70710678118654752f));
        v.y = 0.5f*v.y*(1.f + erff(v.y*0.70710678118654752f));
        v.z = 0.5f*v.z*(1.f + erff(v.z*0.70710678118654752f));
        v.w = 0.5f*v.w*(1.f + erff(v.w*0.70710678118654752f));
      }
      *(float4*)(C + (long)m*N + n) = v;
    }
  }
}

// ---------------- q post: l2norm, scale, learnable-token dots ---------------------
__global__ void __launch_bounds__(256)
qpost_kernel(const float* __restrict__ temp, const float* __restrict__ qe,
             const float* __restrict__ lt, const float* __restrict__ lb)
{
  int w = (blockIdx.x * 256 + threadIdx.x) >> 5;   // (b*8+h)*4096+n
  int lane = threadIdx.x & 31;
  int n = w & 4095;
  int bh = w >> 12;
  int h = bh & 7, b = bh >> 3;
  float qv = g_qtmp[(b*4096+n)*256 + h*32 + lane];
  float ss = warpSum(qv*qv);
  float qn = qv / fmaxf(sqrtf(ss), EPSF);
  int yi = n >> 6, xj = n & 63;
  int ch = min(yi+1,63) - max(yi-1,0) + 1;
  int cw = min(xj+1,63) - max(xj-1,0) + 1;
  float sls = logf((float)(ch*cw) + 64.f);
  float sp = log1pf(expf(temp[h]));
  g_q[w*32 + lane] = (qn + qe[h*32+lane]) * sp * sls;
  #pragma unroll
  for (int l=0;l<9;l++){
    float p = warpSum(qn * lt[h*288 + lane*9 + l]);
    if (lane == l) g_ltd[w*9 + l] = p + lb[h*9+l];
  }
}

// ---------------- kv post: l2-normalize k half per head (in place) ---------------
__global__ void __launch_bounds__(256)
kvpost_kernel()
{
  int w = (blockIdx.x*256 + threadIdx.x) >> 5;  // row*8+h
  int lane = threadIdx.x & 31;
  int h = w & 7, row = w >> 3;
  float* p = g_kv + row*512 + h*32 + lane;
  float v = *p;
  float ss = warpSum(v*v);
  *p = v / fmaxf(sqrtf(ss), EPSF);
}

__global__ void __launch_bounds__(256)
kvp2post_kernel()
{
  int w = (blockIdx.x*256 + threadIdx.x) >> 5;  // row*8+h, row < 256
  int lane = threadIdx.x & 31;
  int h = w & 7, row = w >> 3;
  float* p = g_kvp2 + row*512 + h*32 + lane;
  float v = *p;
  float ss = warpSum(v*v);
  *p = v / fmaxf(sqrtf(ss), EPSF);
}

// ---------------- gating (routed top-2, shared, w0) ------------------------------
__global__ void __launch_bounds__(256)
gates_kernel(const float* __restrict__ x, const float* __restrict__ wg,
             const float* __restrict__ wg0, const float* __restrict__ wg1)
{
  int w = (blockIdx.x*256 + threadIdx.x) >> 5;   // row = b*4096+n
  int lane = threadIdx.x & 31;
  const float* xr = x + w*256;
  float xv[8];
  {
    float4 a = *(const float4*)(xr + lane*8);
    float4 c = *(const float4*)(xr + lane*8 + 4);
    xv[0]=a.x; xv[1]=a.y; xv[2]=a.z; xv[3]=a.w;
    xv[4]=c.x; xv[5]=c.y; xv[6]=c.z; xv[7]=c.w;
  }
  float d[10];
  #pragma unroll
  for (int r=0;r<10;r++){
    const float* wr = (r<4) ? (wg + r*256) : ((r<6) ? (wg0 + (r-4)*256) : (wg1 + (r-6)*256));
    float pp = 0.f;
    #pragma unroll
    for (int k=0;k<8;k++) pp = fmaf(xv[k], wr[lane*8+k], pp);
    d[r] = warpSum(pp);
  }
  if (lane == 0){
    float m = fmaxf(fmaxf(d[0],d[1]),fmaxf(d[2],d[3]));
    float e[4], se=0.f;
    #pragma unroll
    for (int k=0;k<4;k++){ e[k]=expf(d[k]-m); se+=e[k]; }
    float gg[4];
    #pragma unroll
    for (int k=0;k<4;k++) gg[k]=e[k]/se;
    int i0=0;
    #pragma unroll
    for (int k=1;k<4;k++) if (gg[k]>gg[i0]) i0=k;
    int i1=-1;
    #pragma unroll
    for (int k=0;k<4;k++) if (k!=i0 && (i1<0 || gg[k]>gg[i1])) i1=k;
    float s2 = fmaxf(gg[i0]+gg[i1], EPSF);
    float routed[4]={0.f,0.f,0.f,0.f};
    routed[i0]=gg[i0]/s2*2.f; routed[i1]=gg[i1]/s2*2.f;
    float m0 = fmaxf(d[4],d[5]);
    float e4=expf(d[4]-m0), e5=expf(d[5]-m0);
    float w00 = e4/(e4+e5)*2.f, w01 = e5/(e4+e5)*2.f;
    float m1 = fmaxf(fmaxf(d[6],d[7]),fmaxf(d[8],d[9]));
    float es[4], ss2=0.f;
    #pragma unroll
    for (int k=0;k<4;k++){ es[k]=expf(d[6+k]-m1); ss2+=es[k]; }
    float* gp = g_gate + w*8;
    #pragma unroll
    for (int k=0;k<4;k++) gp[k]   = w00 * (es[k]/ss2*4.f);
    #pragma unroll
    for (int k=0;k<4;k++) gp[4+k] = w01 * routed[k];
  }
}

// ---------------- 8x8 avg pool + LayerNorm ---------------------------------------
__global__ void __launch_bounds__(256)
pool_ln_kernel(const float* __restrict__ ng, const float* __restrict__ nb)
{
  int b = blockIdx.x >> 6, p = blockIdx.x & 63;
  int c = threadIdx.x;
  int pi = p >> 3, pj = p & 7;
  float s = 0.f;
  #pragma unroll
  for (int si=0; si<8; si++){
    int rowbase = b*4096 + (pi*8+si)*64 + pj*8;
    #pragma unroll
    for (int sj=0; sj<8; sj++)
      s += g_xs[(rowbase + sj)*256 + c];
  }
  float v = s * (1.f/64.f);
  __shared__ float shs[8], shq[8];
  int lane = c & 31, wid = c >> 5;
  float s1 = warpSum(v), sq = warpSum(v*v);
  if (lane==0){ shs[wid]=s1; shq[wid]=sq; }
  __syncthreads();
  float tot=0.f, totq=0.f;
  #pragma unroll
  for (int i=0;i<8;i++){ tot+=shs[i]; totq+=shq[i]; }
  float mu = tot*(1.f/256.f);
  float var = totq*(1.f/256.f) - mu*mu;
  g_pool[(b*64+p)*256 + c] = (v-mu)*rsqrtf(var+1e-5f)*ng[c] + nb[c];
}

// ---------------- cpb MLP --------------------------------------------------------
__global__ void __launch_bounds__(256)
cpb_hidden_kernel(const float* __restrict__ ct, const float* __restrict__ w1,
                  const float* __restrict__ b1)
{
  int tid = blockIdx.x*256 + threadIdx.x;
  if (tid >= 4096*512) return;
  int t = tid >> 9, j = tid & 511;
  float v = fmaf(ct[t*2], w1[j*2], fmaf(ct[t*2+1], w1[j*2+1], b1[j]));
  g_cpbh[tid] = fmaxf(v, 0.f);
}

__global__ void __launch_bounds__(256)
cpb_out_kernel(const float* __restrict__ w2, const float* __restrict__ b2)
{
  int t = (blockIdx.x*256 + threadIdx.x) >> 5;   // table row
  int lane = threadIdx.x & 31;
  float s[8] = {0,0,0,0,0,0,0,0};
  #pragma unroll
  for (int it=0; it<16; it++){
    float hv = g_cpbh[t*512 + it*32 + lane];
    #pragma unroll
    for (int h=0;h<8;h++) s[h] = fmaf(hv, w2[h*512 + it*32 + lane], s[h]);
  }
  #pragma unroll
  for (int h=0;h<8;h++){
    float tot = warpSum(s[h]);
    if (lane == 0) g_cpb[t*8 + h] = tot + b2[h];
  }
}

// ---------------- fused local+pool attention -------------------------------------
// SMEM-broadcast version: q tile and softmax probs staged in shared memory so the
// pool-score and pool-AV inner loops use LDS.128 broadcasts instead of SHFL chains.
__global__ void __launch_bounds__(256)
attn_kernel(const float* __restrict__ rpb, const int* __restrict__ rpi)
{
  __shared__ float ks[32*64];                 // k_pool transposed [d][p]
  __shared__ float vs[64*32];                 // v_pool [p][d]
  __shared__ __align__(16) float qsm[64*32];  // q tile [nl][d]
  __shared__ __align__(16) float psm[8][64];  // per-warp pool probs [warp][p]
  const int bh = blockIdx.y;
  const int h = bh & 7, b = bh >> 3;
  const int tid = threadIdx.x;
  for (int idx = tid; idx < 2048; idx += 256){
    int p = idx >> 5, d = idx & 31;
    const float* base = g_kvp2 + (b*64+p)*512 + h*32 + d;
    ks[d*64+p] = base[0];
    vs[idx]    = base[256];
  }
  // q tile: contiguous 2048 floats for this (b,h,n-block)
  {
    const float4* qg = (const float4*)(g_q + ((long)(b*8+h)*4096 + blockIdx.x*64)*32);
    float4* qs4 = (float4*)qsm;
    for (int idx = tid; idx < 512; idx += 256) qs4[idx] = qg[idx];
  }
  __syncthreads();
  const int warp = tid >> 5, lane = tid & 31;
  float rpbl[9];
  #pragma unroll
  for (int l=0;l<9;l++) rpbl[l] = rpb[h*9+l];

  for (int it=0; it<8; it++){
    int nl = warp*8 + it;
    int n = blockIdx.x*64 + nl;
    int yi = n >> 6, xj = n & 63;
    float qs = qsm[nl*32 + lane];
    // local window scores (zero-padded -> score = rpb, v = 0)
    float sloc[9]; int nloc[9];
    #pragma unroll
    for (int l=0;l<9;l++){
      int y  = yi + l/3 - 1;
      int x2 = xj + l%3 - 1;
      bool val = ((unsigned)y < 64u) && ((unsigned)x2 < 64u);
      int nl2 = y*64 + x2;
      nloc[l] = val ? nl2 : -1;
      float kd = val ? g_kv[(b*4096+nl2)*512 + h*32 + lane] : 0.f;
      sloc[l] = warpSum(qs*kd) + rpbl[l];
    }
    // pool scores: lane handles p=lane and p=lane+32; q via LDS.128 broadcast
    const int* rr = rpi + (long)n*64;
    int ia = rr[lane], ib = rr[lane+32];
    float s0 = g_cpb[ia*8+h];
    float s1 = g_cpb[ib*8+h];
    const float4* q4 = (const float4*)(qsm + nl*32);
    #pragma unroll
    for (int dq=0; dq<8; dq++){
      float4 qv = q4[dq];
      int d0 = dq*4;
      s0 = fmaf(qv.x, ks[(d0+0)*64+lane], s0);
      s0 = fmaf(qv.y, ks[(d0+1)*64+lane], s0);
      s0 = fmaf(qv.z, ks[(d0+2)*64+lane], s0);
      s0 = fmaf(qv.w, ks[(d0+3)*64+lane], s0);
      s1 = fmaf(qv.x, ks[(d0+0)*64+lane+32], s1);
      s1 = fmaf(qv.y, ks[(d0+1)*64+lane+32], s1);
      s1 = fmaf(qv.z, ks[(d0+2)*64+lane+32], s1);
      s1 = fmaf(qv.w, ks[(d0+3)*64+lane+32], s1);
    }
    // softmax over 73
    float m = fmaxf(s0, s1);
    #pragma unroll
    for (int l=0;l<9;l++) m = fmaxf(m, sloc[l]);
    m = warpMax(m);
    float el[9], suml = 0.f;
    #pragma unroll
    for (int l=0;l<9;l++){ el[l] = expf(sloc[l]-m); suml += el[l]; }
    float e0 = expf(s0-m), e1 = expf(s1-m);
    float inv = 1.f / (suml + warpSum(e0+e1));
    // stage normalized pool probs in smem for broadcast reads
    psm[warp][lane]    = e0 * inv;
    psm[warp][lane+32] = e1 * inv;
    __syncwarp();
    // local AV (+ learnable-token modulation)
    const float* ltdp = g_ltd + ((long)(b*8+h)*4096 + n)*9;
    float outv = 0.f;
    #pragma unroll
    for (int l=0;l<9;l++){
      float al = el[l]*inv + ltdp[l];
      if (nloc[l] >= 0)
        outv = fmaf(al, g_kv[(b*4096+nloc[l])*512 + 256 + h*32 + lane], outv);
    }
    // pool AV: probs via LDS.128 broadcast
    const float4* p4 = (const float4*)(&psm[warp][0]);
    #pragma unroll
    for (int pq=0; pq<16; pq++){
      float4 ap = p4[pq];
      int p0 = pq*4;
      outv = fmaf(ap.x, vs[(p0+0)*32+lane], outv);
      outv = fmaf(ap.y, vs[(p0+1)*32+lane], outv);
      outv = fmaf(ap.z, vs[(p0+2)*32+lane], outv);
      outv = fmaf(ap.w, vs[(p0+3)*32+lane], outv);
    }
    float gate = g_gate[(b*4096+n)*8 + h];
    g_attnout[(b*4096+n)*256 + h*32 + lane] = outv * gate;
  }
}

// ---------------- launch ---------------------------------------------------------
extern "C" void kernel_launch(void* const* d_in, const int* in_sizes, int n_in,
                              void* d_out, int out_size)
{
  const float* x      = (const float*)d_in[0];
  const float* ctab   = (const float*)d_in[1];
  const float* q_w    = (const float*)d_in[2];
  const float* q_b    = (const float*)d_in[3];
  const float* kv_w   = (const float*)d_in[4];
  const float* kv_b   = (const float*)d_in[5];
  const float* temp   = (const float*)d_in[6];
  const float* qe     = (const float*)d_in[7];
  const float* rpb    = (const float*)d_in[8];
  const float* lt     = (const float*)d_in[9];
  const float* lb     = (const float*)d_in[10];
  const float* cpb1_w = (const float*)d_in[11];
  const float* cpb1_b = (const float*)d_in[12];
  const float* cpb2_w = (const float*)d_in[13];
  const float* cpb2_b = (const float*)d_in[14];
  const float* sr_w   = (const float*)d_in[15];
  const float* sr_b   = (const float*)d_in[16];
  const float* norm_g = (const float*)d_in[17];
  const float* norm_b = (const float*)d_in[18];
  const float* wg_w   = (const float*)d_in[19];
  const float* wg0_w  = (const float*)d_in[20];
  const float* wg1_w  = (const float*)d_in[21];
  const float* proj_w = (const float*)d_in[22];
  const float* proj_b = (const float*)d_in[23];
  const int*   rpi    = (const int*)d_in[24];
  float* out = (float*)d_out;

  float *p_qtmp, *p_kv, *p_xs, *p_pool, *p_kvp2, *p_attnout;
  cudaGetSymbolAddress((void**)&p_qtmp,    g_qtmp);
  cudaGetSymbolAddress((void**)&p_kv,      g_kv);
  cudaGetSymbolAddress((void**)&p_xs,      g_xs);
  cudaGetSymbolAddress((void**)&p_pool,    g_pool);
  cudaGetSymbolAddress((void**)&p_kvp2,    g_kvp2);
  cudaGetSymbolAddress((void**)&p_attnout, g_attnout);

  const int M = NBATCH*NTOK;   // 16384

  // gating (only needs x)
  gates_kernel<<<2048, 256>>>(x, wg_w, wg0_w, wg1_w);
  // q path
  sgemm_kernel<false><<<dim3(2,128), 256>>>(x, q_w, q_b, p_qtmp, M, 256, 256);
  qpost_kernel<<<16384, 256>>>(temp, qe, lt, lb);
  // kv path
  sgemm_kernel<false><<<dim3(4,128), 256>>>(x, kv_w, kv_b, p_kv, M, 512, 256);
  kvpost_kernel<<<16384, 256>>>();
  // pooled path
  sgemm_kernel<true><<<dim3(2,128), 256>>>(x, sr_w, sr_b, p_xs, M, 256, 256);
  pool_ln_kernel<<<256, 256>>>(norm_g, norm_b);
  sgemm_kernel<false><<<dim3(4,2), 256>>>(p_pool, kv_w, kv_b, p_kvp2, 256, 512, 256);
  kvp2post_kernel<<<256, 256>>>();
  // cpb MLP
  cpb_hidden_kernel<<<8192, 256>>>(ctab, cpb1_w, cpb1_b);
  cpb_out_kernel<<<512, 256>>>(cpb2_w, cpb2_b);
  // fused attention
  attn_kernel<<<dim3(64, 32), 256>>>(rpb, rpi);
  // projection
  sgemm_kernel<false><<<dim3(2,128), 256>>>(p_attnout, proj_w, proj_b, out, M, 256, 256);
}

// round 12
// speedup vs baseline: 1.3806x; 1.2008x over previous
#include <cuda_runtime.h>
#include <cuda_bf16.h>
#include <cstdint>
#include <cstring>
#include <math.h>

#define NBATCH 4
#define NTOK   4096
#define NC     256
#define NH     8
#define ND     32
#define NPL    64
#define EPSF   1.1920929e-07f

// ---------------- scratch (device globals; no runtime alloc allowed) -------------
__device__ float g_qtmp[NBATCH*NTOK*NC];        // raw q gemm out
__device__ float g_q[NBATCH*NTOK*NC];           // q_scaled, layout (B,H,N,D)
__device__ float g_ltd[NBATCH*NH*NTOK*9];       // learnable-token dots + bias
__device__ float g_kv[NBATCH*NTOK*2*NC];        // kv, k-half l2-normalized in place
__device__ float g_gate[NBATCH*NTOK*NH];        // per-head gates
__device__ float g_xs[NBATCH*NTOK*NC];          // sr+gelu out
__device__ float g_pool[NBATCH*NPL*NC];         // pooled + LN
__device__ float g_kvp2[NBATCH*NPL*2*NC];       // pooled kv, k-half normalized
__device__ float g_cpbh[4096*512];              // cpb hidden
__device__ float g_cpb[4096*NH];                // cpb table
__device__ float g_attnout[NBATCH*NTOK*NC];     // pre-proj attention out

// bf16 split buffers for tensor-core GEMMs
__device__ __nv_bfloat16 g_xhi[NBATCH*NTOK*NC];
__device__ __nv_bfloat16 g_xlo[NBATCH*NTOK*NC];
__device__ __nv_bfloat16 g_whi[1280*NC];        // [q 0:256 | kv 256:768 | sr 768:1024 | proj 1024:1280]
__device__ __nv_bfloat16 g_wlo[1280*NC];
__device__ __nv_bfloat16 g_aohi[NBATCH*NTOK*NC];
__device__ __nv_bfloat16 g_aolo[NBATCH*NTOK*NC];

// ---------------- helpers --------------------------------------------------------
__device__ __forceinline__ float warpSum(float v){
  #pragma unroll
  for (int o=16;o>0;o>>=1) v += __shfl_xor_sync(0xffffffffu, v, o);
  return v;
}
__device__ __forceinline__ float warpMax(float v){
  #pragma unroll
  for (int o=16;o>0;o>>=1) v = fmaxf(v, __shfl_xor_sync(0xffffffffu, v, o));
  return v;
}

// packed f32x2 helpers (Blackwell FFMA2)
__device__ __forceinline__ unsigned long long pack2(float lo, float hi){
  unsigned long long r;
  asm("mov.b64 %0, {%1, %2};" : "=l"(r) : "f"(lo), "f"(hi));
  return r;
}
__device__ __forceinline__ void unpack2(unsigned long long v, float& lo, float& hi){
  asm("mov.b64 {%0, %1}, %2;" : "=f"(lo), "=f"(hi) : "l"(v));
}
__device__ __forceinline__ void ffma2(unsigned long long& d,
                                      unsigned long long a, unsigned long long b){
  asm("fma.rn.f32x2 %0, %1, %2, %0;" : "+l"(d) : "l"(a), "l"(b));
}

__device__ __forceinline__ uint32_t smem_u32(const void* p){
  uint32_t a;
  asm("{ .reg .u64 t; cvta.to.shared.u64 t, %1; cvt.u32.u64 %0, t; }" : "=r"(a) : "l"(p));
  return a;
}

// ---------------- mma.sync helpers (sm_80+; legal on plain compute_103) ----------
__device__ __forceinline__ void ldmx4(uint32_t& r0, uint32_t& r1, uint32_t& r2, uint32_t& r3,
                                      uint32_t addr){
  asm volatile("ldmatrix.sync.aligned.m8n8.x4.shared.b16 {%0,%1,%2,%3}, [%4];"
               : "=r"(r0), "=r"(r1), "=r"(r2), "=r"(r3) : "r"(addr));
}
__device__ __forceinline__ void ldmx2(uint32_t& r0, uint32_t& r1, uint32_t addr){
  asm volatile("ldmatrix.sync.aligned.m8n8.x2.shared.b16 {%0,%1}, [%2];"
               : "=r"(r0), "=r"(r1) : "r"(addr));
}
__device__ __forceinline__ void mma_bf16(float* c, const uint32_t* a, uint32_t b0, uint32_t b1){
  asm volatile("mma.sync.aligned.m16n8k16.row.col.f32.bf16.bf16.f32 "
               "{%0,%1,%2,%3}, {%4,%5,%6,%7}, {%8,%9}, {%0,%1,%2,%3};"
               : "+f"(c[0]), "+f"(c[1]), "+f"(c[2]), "+f"(c[3])
               : "r"(a[0]), "r"(a[1]), "r"(a[2]), "r"(a[3]), "r"(b0), "r"(b1));
}

// ---------------- hi/lo split conversion -----------------------------------------
__global__ void __launch_bounds__(256)
convert_split_kernel(const float* __restrict__ src, __nv_bfloat16* __restrict__ hi,
                     __nv_bfloat16* __restrict__ lo, int n)
{
  int i = (blockIdx.x*256 + threadIdx.x)*4;
  if (i >= n) return;
  float4 v = *(const float4*)(src + i);
  __nv_bfloat16 h0=__float2bfloat16(v.x), h1=__float2bfloat16(v.y);
  __nv_bfloat16 h2=__float2bfloat16(v.z), h3=__float2bfloat16(v.w);
  __nv_bfloat16 l0=__float2bfloat16(v.x-__bfloat162float(h0));
  __nv_bfloat16 l1=__float2bfloat16(v.y-__bfloat162float(h1));
  __nv_bfloat16 l2=__float2bfloat16(v.z-__bfloat162float(h2));
  __nv_bfloat16 l3=__float2bfloat16(v.w-__bfloat162float(h3));
  __nv_bfloat162 hp0(h0,h1), hp1(h2,h3), lp0(l0,l1), lp1(l2,l3);
  uint32_t u0, u1, u2, u3;
  memcpy(&u0, &hp0, 4); memcpy(&u1, &hp1, 4);
  memcpy(&u2, &lp0, 4); memcpy(&u3, &lp1, 4);
  *(uint2*)(hi + i) = make_uint2(u0, u1);
  *(uint2*)(lo + i) = make_uint2(u2, u3);
}

// ---------------- HMMA split-bf16 GEMM: C = A(Mx256)*W(Nx256)^T + bias -----------
// 128x128 CTA tile, 8 warps (4M x 2N), warp tile 32x64, K chunks of 64.
// smem rows padded to 72 bf16 (144 B) for conflict-free ldmatrix.
#define SPITCH 72
__global__ void __launch_bounds__(256, 1)
hmma_gemm(const __nv_bfloat16* __restrict__ Ahi, const __nv_bfloat16* __restrict__ Alo,
          const __nv_bfloat16* __restrict__ Whi, const __nv_bfloat16* __restrict__ Wlo,
          const float* __restrict__ bias, float* __restrict__ dst,
          int ncols, int gelu)
{
  extern __shared__ __nv_bfloat16 sm[];
  __nv_bfloat16* sAh = sm;
  __nv_bfloat16* sAl = sm + 128*SPITCH;
  __nv_bfloat16* sWh = sm + 2*128*SPITCH;
  __nv_bfloat16* sWl = sm + 3*128*SPITCH;

  const int tid = threadIdx.x;
  const int wid = tid >> 5, lane = tid & 31;
  const int wy = wid & 3;        // 4 along M
  const int wx = wid >> 2;       // 2 along N
  const long m0 = (long)blockIdx.y * 128;
  const long n0 = (long)blockIdx.x * 128;

  const uint32_t sAh32 = smem_u32(sAh), sAl32 = smem_u32(sAl);
  const uint32_t sWh32 = smem_u32(sWh), sWl32 = smem_u32(sWl);

  float acc[2][8][4];
  #pragma unroll
  for (int mt=0;mt<2;mt++)
    #pragma unroll
    for (int nt=0;nt<8;nt++)
      #pragma unroll
      for (int j=0;j<4;j++) acc[mt][nt][j]=0.f;

  // ldmatrix source addresses (per-lane)
  // A x4: lanes 0-15 -> rows base+0..15 @k, lanes 16-31 -> same rows @k+8
  const int a_row = (lane & 15);
  const int a_kof = (lane >> 4) << 3;
  // B x2: lanes 0-7 -> rows n..n+7 @k, lanes 8-15 -> same rows @k+8
  const int b_row = (lane & 7);
  const int b_kof = ((lane >> 3) & 1) << 3;

  for (int c4 = 0; c4 < 4; c4++){
    const int k0 = c4 * 64;
    // load 4 tiles: 128 rows x 64 k each (8 bf16 per uint4)
    #pragma unroll
    for (int it = 0; it < 4; it++){
      int idx = it*256 + tid;          // 0..1023
      int r = idx >> 3, seg = idx & 7;
      long goffA = (m0 + r) * 256 + k0 + seg*8;
      long goffW = (n0 + r) * 256 + k0 + seg*8;
      *(uint4*)(sAh + r*SPITCH + seg*8) = *(const uint4*)(Ahi + goffA);
      *(uint4*)(sAl + r*SPITCH + seg*8) = *(const uint4*)(Alo + goffA);
      *(uint4*)(sWh + r*SPITCH + seg*8) = *(const uint4*)(Whi + goffW);
      *(uint4*)(sWl + r*SPITCH + seg*8) = *(const uint4*)(Wlo + goffW);
    }
    __syncthreads();

    #pragma unroll
    for (int kk = 0; kk < 64; kk += 16){
      // A fragments for 2 m-tiles, hi and lo
      uint32_t ah[2][4], al[2][4];
      #pragma unroll
      for (int mt=0; mt<2; mt++){
        uint32_t off = (uint32_t)((wy*32 + mt*16 + a_row)*SPITCH + kk + a_kof) * 2u;
        ldmx4(ah[mt][0], ah[mt][1], ah[mt][2], ah[mt][3], sAh32 + off);
        ldmx4(al[mt][0], al[mt][1], al[mt][2], al[mt][3], sAl32 + off);
      }
      #pragma unroll
      for (int nt=0; nt<8; nt++){
        uint32_t boff = (uint32_t)((wx*64 + nt*8 + b_row)*SPITCH + kk + b_kof) * 2u;
        uint32_t bh0, bh1, bl0, bl1;
        ldmx2(bh0, bh1, sWh32 + boff);
        ldmx2(bl0, bl1, sWl32 + boff);
        #pragma unroll
        for (int mt=0; mt<2; mt++){
          mma_bf16(acc[mt][nt], ah[mt], bh0, bh1);   // hi*hi
          mma_bf16(acc[mt][nt], ah[mt], bl0, bl1);   // hi*lo
          mma_bf16(acc[mt][nt], al[mt], bh0, bh1);   // lo*hi
        }
      }
    }
    __syncthreads();
  }

  // epilogue: c0,c1 -> (row, col..col+1); c2,c3 -> (row+8, col..col+1)
  const int cr = lane >> 2;         // 0..7
  const int cc = (lane & 3) * 2;    // 0,2,4,6
  #pragma unroll
  for (int mt=0; mt<2; mt++){
    #pragma unroll
    for (int nt=0; nt<8; nt++){
      long row0 = m0 + wy*32 + mt*16 + cr;
      long col  = n0 + wx*64 + nt*8 + cc;
      float b0 = bias[col], b1 = bias[col+1];
      float v0 = acc[mt][nt][0] + b0, v1 = acc[mt][nt][1] + b1;
      float v2 = acc[mt][nt][2] + b0, v3 = acc[mt][nt][3] + b1;
      if (gelu){
        v0 = 0.5f*v0*(1.f + erff(v0*0.70710678118654752f));
        v1 = 0.5f*v1*(1.f + erff(v1*0.70710678118654752f));
        v2 = 0.5f*v2*(1.f + erff(v2*0.70710678118654752f));
        v3 = 0.5f*v3*(1.f + erff(v3*0.70710678118654752f));
      }
      *(float2*)(dst + row0*ncols + col)     = make_float2(v0, v1);
      *(float2*)(dst + (row0+8)*ncols + col) = make_float2(v2, v3);
    }
  }
}

// ---------------- fp32 SGEMM (kept for the tiny pooled-kv GEMM) ------------------
template<bool GELU>
__global__ void __launch_bounds__(256, 2)
sgemm_kernel(const float* __restrict__ A, const float* __restrict__ W,
             const float* __restrict__ bias, float* __restrict__ C,
             int M, int N, int K)
{
  __shared__ float As[2][16][128];
  __shared__ float Ws[2][16][128];
  const int tid = threadIdx.x;
  const int m0 = blockIdx.y * 128;
  const int n0 = blockIdx.x * 128;
  const int lrow = tid >> 1;
  const int lk   = (tid & 1) * 8;
  const int wid  = tid >> 5, lane = tid & 31;
  const int wy   = wid & 3;
  const int wx   = wid >> 2;
  const int ly   = lane >> 3;
  const int lx   = lane & 7;
  const int ra   = wy*32 + ly*4;
  const int cb   = wx*64 + lx*4;

  const float* Ap = A + (long)(m0 + lrow) * K + lk;
  const float* Wp = W + (long)(n0 + lrow) * K + lk;

  unsigned long long acc2[8][4];
  #pragma unroll
  for (int i=0;i<8;i++)
    #pragma unroll
    for (int j=0;j<4;j++) acc2[i][j]=0ULL;

  {
    float4 a0 = *(const float4*)(Ap);
    float4 a1 = *(const float4*)(Ap+4);
    float4 w0 = *(const float4*)(Wp);
    float4 w1 = *(const float4*)(Wp+4);
    As[0][lk+0][lrow]=a0.x; As[0][lk+1][lrow]=a0.y; As[0][lk+2][lrow]=a0.z; As[0][lk+3][lrow]=a0.w;
    As[0][lk+4][lrow]=a1.x; As[0][lk+5][lrow]=a1.y; As[0][lk+6][lrow]=a1.z; As[0][lk+7][lrow]=a1.w;
    Ws[0][lk+0][lrow]=w0.x; Ws[0][lk+1][lrow]=w0.y; Ws[0][lk+2][lrow]=w0.z; Ws[0][lk+3][lrow]=w0.w;
    Ws[0][lk+4][lrow]=w1.x; Ws[0][lk+5][lrow]=w1.y; Ws[0][lk+6][lrow]=w1.z; Ws[0][lk+7][lrow]=w1.w;
  }
  __syncthreads();

  int buf = 0;
  for (int k0 = 0; k0 < K; k0 += 16){
    const bool more = (k0 + 16 < K);
    float4 pa0, pa1, pw0, pw1;
    if (more){
      pa0 = *(const float4*)(Ap + k0 + 16);
      pa1 = *(const float4*)(Ap + k0 + 20);
      pw0 = *(const float4*)(Wp + k0 + 16);
      pw1 = *(const float4*)(Wp + k0 + 20);
    }
    #pragma unroll
    for (int kk=0; kk<16; kk++){
      float4 af0 = *(const float4*)(&As[buf][kk][ra]);
      float4 af1 = *(const float4*)(&As[buf][kk][ra+16]);
      float4 wf0 = *(const float4*)(&Ws[buf][kk][cb]);
      float4 wf1 = *(const float4*)(&Ws[buf][kk][cb+32]);
      unsigned long long ab[8], wp2[4];
      ab[0]=pack2(af0.x,af0.x); ab[1]=pack2(af0.y,af0.y);
      ab[2]=pack2(af0.z,af0.z); ab[3]=pack2(af0.w,af0.w);
      ab[4]=pack2(af1.x,af1.x); ab[5]=pack2(af1.y,af1.y);
      ab[6]=pack2(af1.z,af1.z); ab[7]=pack2(af1.w,af1.w);
      wp2[0]=pack2(wf0.x,wf0.y); wp2[1]=pack2(wf0.z,wf0.w);
      wp2[2]=pack2(wf1.x,wf1.y); wp2[3]=pack2(wf1.z,wf1.w);
      #pragma unroll
      for (int i=0;i<8;i++)
        #pragma unroll
        for (int j=0;j<4;j++)
          ffma2(acc2[i][j], ab[i], wp2[j]);
    }
    if (more){
      int nb = buf ^ 1;
      As[nb][lk+0][lrow]=pa0.x; As[nb][lk+1][lrow]=pa0.y; As[nb][lk+2][lrow]=pa0.z; As[nb][lk+3][lrow]=pa0.w;
      As[nb][lk+4][lrow]=pa1.x; As[nb][lk+5][lrow]=pa1.y; As[nb][lk+6][lrow]=pa1.z; As[nb][lk+7][lrow]=pa1.w;
      Ws[nb][lk+0][lrow]=pw0.x; Ws[nb][lk+1][lrow]=pw0.y; Ws[nb][lk+2][lrow]=pw0.z; Ws[nb][lk+3][lrow]=pw0.w;
      Ws[nb][lk+4][lrow]=pw1.x; Ws[nb][lk+5][lrow]=pw1.y; Ws[nb][lk+6][lrow]=pw1.z; Ws[nb][lk+7][lrow]=pw1.w;
    }
    __syncthreads();
    buf ^= 1;
  }

  #pragma unroll
  for (int i=0;i<8;i++){
    int m = m0 + ra + ((i < 4) ? i : (12 + i));
    #pragma unroll
    for (int jg=0;jg<2;jg++){
      int n = n0 + cb + jg*32;
      float4 v;
      unpack2(acc2[i][jg*2+0], v.x, v.y);
      unpack2(acc2[i][jg*2+1], v.z, v.w);
      v.x += bias[n+0];
      v.y += bias[n+1];
      v.z += bias[n+2];
      v.w += bias[n+3];
      if (GELU){
        v.x = 0.5f*v.x*(1.f + erff(v.x*0.70710678118654752f));
        v.y = 0.5f*v.y*(1.f + erff(v.y*0.70710678118654752f));
        v.z = 0.5f*v.z*(1.f + erff(v.z*0.70710678118654752f));
        v.w = 0.5f*v.w*(1.f + erff(v.w*0.70710678118654752f));
      }
      *(float4*)(C + (long)m*N + n) = v;
    }
  }
}

// ---------------- q post: l2norm, scale, learnable-token dots ---------------------
__global__ void __launch_bounds__(256)
qpost_kernel(const float* __restrict__ temp, const float* __restrict__ qe,
             const float* __restrict__ lt, const float* __restrict__ lb)
{
  int w = (blockIdx.x * 256 + threadIdx.x) >> 5;
  int lane = threadIdx.x & 31;
  int n = w & 4095;
  int bh = w >> 12;
  int h = bh & 7, b = bh >> 3;
  float qv = g_qtmp[(b*4096+n)*256 + h*32 + lane];
  float ss = warpSum(qv*qv);
  float qn = qv / fmaxf(sqrtf(ss), EPSF);
  int yi = n >> 6, xj = n & 63;
  int ch = min(yi+1,63) - max(yi-1,0) + 1;
  int cw = min(xj+1,63) - max(xj-1,0) + 1;
  float sls = logf((float)(ch*cw) + 64.f);
  float sp = log1pf(expf(temp[h]));
  g_q[w*32 + lane] = (qn + qe[h*32+lane]) * sp * sls;
  #pragma unroll
  for (int l=0;l<9;l++){
    float p = warpSum(qn * lt[h*288 + lane*9 + l]);
    if (lane == l) g_ltd[w*9 + l] = p + lb[h*9+l];
  }
}

// ---------------- kv post: l2-normalize k half per head (in place) ---------------
__global__ void __launch_bounds__(256)
kvpost_kernel()
{
  int w = (blockIdx.x*256 + threadIdx.x) >> 5;
  int lane = threadIdx.x & 31;
  int h = w & 7, row = w >> 3;
  float* p = g_kv + row*512 + h*32 + lane;
  float v = *p;
  float ss = warpSum(v*v);
  *p = v / fmaxf(sqrtf(ss), EPSF);
}

__global__ void __launch_bounds__(256)
kvp2post_kernel()
{
  int w = (blockIdx.x*256 + threadIdx.x) >> 5;
  int lane = threadIdx.x & 31;
  int h = w & 7, row = w >> 3;
  float* p = g_kvp2 + row*512 + h*32 + lane;
  float v = *p;
  float ss = warpSum(v*v);
  *p = v / fmaxf(sqrtf(ss), EPSF);
}

// ---------------- gating (routed top-2, shared, w0) ------------------------------
__global__ void __launch_bounds__(256)
gates_kernel(const float* __restrict__ x, const float* __restrict__ wg,
             const float* __restrict__ wg0, const float* __restrict__ wg1)
{
  int w = (blockIdx.x*256 + threadIdx.x) >> 5;
  int lane = threadIdx.x & 31;
  const float* xr = x + w*256;
  float xv[8];
  {
    float4 a = *(const float4*)(xr + lane*8);
    float4 c = *(const float4*)(xr + lane*8 + 4);
    xv[0]=a.x; xv[1]=a.y; xv[2]=a.z; xv[3]=a.w;
    xv[4]=c.x; xv[5]=c.y; xv[6]=c.z; xv[7]=c.w;
  }
  float d[10];
  #pragma unroll
  for (int r=0;r<10;r++){
    const float* wr = (r<4) ? (wg + r*256) : ((r<6) ? (wg0 + (r-4)*256) : (wg1 + (r-6)*256));
    float pp = 0.f;
    #pragma unroll
    for (int k=0;k<8;k++) pp = fmaf(xv[k], wr[lane*8+k], pp);
    d[r] = warpSum(pp);
  }
  if (lane == 0){
    float m = fmaxf(fmaxf(d[0],d[1]),fmaxf(d[2],d[3]));
    float e[4], se=0.f;
    #pragma unroll
    for (int k=0;k<4;k++){ e[k]=expf(d[k]-m); se+=e[k]; }
    float gg[4];
    #pragma unroll
    for (int k=0;k<4;k++) gg[k]=e[k]/se;
    int i0=0;
    #pragma unroll
    for (int k=1;k<4;k++) if (gg[k]>gg[i0]) i0=k;
    int i1=-1;
    #pragma unroll
    for (int k=0;k<4;k++) if (k!=i0 && (i1<0 || gg[k]>gg[i1])) i1=k;
    float s2 = fmaxf(gg[i0]+gg[i1], EPSF);
    float routed[4]={0.f,0.f,0.f,0.f};
    routed[i0]=gg[i0]/s2*2.f; routed[i1]=gg[i1]/s2*2.f;
    float m0 = fmaxf(d[4],d[5]);
    float e4=expf(d[4]-m0), e5=expf(d[5]-m0);
    float w00 = e4/(e4+e5)*2.f, w01 = e5/(e4+e5)*2.f;
    float m1 = fmaxf(fmaxf(d[6],d[7]),fmaxf(d[8],d[9]));
    float es[4], ss2=0.f;
    #pragma unroll
    for (int k=0;k<4;k++){ es[k]=expf(d[6+k]-m1); ss2+=es[k]; }
    float* gp = g_gate + w*8;
    #pragma unroll
    for (int k=0;k<4;k++) gp[k]   = w00 * (es[k]/ss2*4.f);
    #pragma unroll
    for (int k=0;k<4;k++) gp[4+k] = w01 * routed[k];
  }
}

// ---------------- 8x8 avg pool + LayerNorm ---------------------------------------
__global__ void __launch_bounds__(256)
pool_ln_kernel(const float* __restrict__ ng, const float* __restrict__ nb)
{
  int b = blockIdx.x >> 6, p = blockIdx.x & 63;
  int c = threadIdx.x;
  int pi = p >> 3, pj = p & 7;
  float s = 0.f;
  #pragma unroll
  for (int si=0; si<8; si++){
    int rowbase = b*4096 + (pi*8+si)*64 + pj*8;
    #pragma unroll
    for (int sj=0; sj<8; sj++)
      s += g_xs[(rowbase + sj)*256 + c];
  }
  float v = s * (1.f/64.f);
  __shared__ float shs[8], shq[8];
  int lane = c & 31, wid = c >> 5;
  float s1 = warpSum(v), sq = warpSum(v*v);
  if (lane==0){ shs[wid]=s1; shq[wid]=sq; }
  __syncthreads();
  float tot=0.f, totq=0.f;
  #pragma unroll
  for (int i=0;i<8;i++){ tot+=shs[i]; totq+=shq[i]; }
  float mu = tot*(1.f/256.f);
  float var = totq*(1.f/256.f) - mu*mu;
  g_pool[(b*64+p)*256 + c] = (v-mu)*rsqrtf(var+1e-5f)*ng[c] + nb[c];
}

// ---------------- cpb MLP --------------------------------------------------------
__global__ void __launch_bounds__(256)
cpb_hidden_kernel(const float* __restrict__ ct, const float* __restrict__ w1,
                  const float* __restrict__ b1)
{
  int tid = blockIdx.x*256 + threadIdx.x;
  if (tid >= 4096*512) return;
  int t = tid >> 9, j = tid & 511;
  float v = fmaf(ct[t*2], w1[j*2], fmaf(ct[t*2+1], w1[j*2+1], b1[j]));
  g_cpbh[tid] = fmaxf(v, 0.f);
}

__global__ void __launch_bounds__(256)
cpb_out_kernel(const float* __restrict__ w2, const float* __restrict__ b2)
{
  int t = (blockIdx.x*256 + threadIdx.x) >> 5;
  int lane = threadIdx.x & 31;
  float s[8] = {0,0,0,0,0,0,0,0};
  #pragma unroll
  for (int it=0; it<16; it++){
    float hv = g_cpbh[t*512 + it*32 + lane];
    #pragma unroll
    for (int h=0;h<8;h++) s[h] = fmaf(hv, w2[h*512 + it*32 + lane], s[h]);
  }
  #pragma unroll
  for (int h=0;h<8;h++){
    float tot = warpSum(s[h]);
    if (lane == 0) g_cpb[t*8 + h] = tot + b2[h];
  }
}

// ---------------- fused local+pool attention -------------------------------------
__global__ void __launch_bounds__(256)
attn_kernel(const float* __restrict__ rpb, const int* __restrict__ rpi)
{
  __shared__ float ks[32*64];
  __shared__ float vs[64*32];
  __shared__ __align__(16) float qsm[64*32];
  __shared__ __align__(16) float psm[8][64];
  const int bh = blockIdx.y;
  const int h = bh & 7, b = bh >> 3;
  const int tid = threadIdx.x;
  for (int idx = tid; idx < 2048; idx += 256){
    int p = idx >> 5, d = idx & 31;
    const float* base = g_kvp2 + (b*64+p)*512 + h*32 + d;
    ks[d*64+p] = base[0];
    vs[idx]    = base[256];
  }
  {
    const float4* qg = (const float4*)(g_q + ((long)(b*8+h)*4096 + blockIdx.x*64)*32);
    float4* qs4 = (float4*)qsm;
    for (int idx = tid; idx < 512; idx += 256) qs4[idx] = qg[idx];
  }
  __syncthreads();
  const int warp = tid >> 5, lane = tid & 31;
  float rpbl[9];
  #pragma unroll
  for (int l=0;l<9;l++) rpbl[l] = rpb[h*9+l];

  for (int it=0; it<8; it++){
    int nl = warp*8 + it;
    int n = blockIdx.x*64 + nl;
    int yi = n >> 6, xj = n & 63;
    float qs = qsm[nl*32 + lane];
    float sloc[9]; int nloc[9];
    #pragma unroll
    for (int l=0;l<9;l++){
      int y  = yi + l/3 - 1;
      int x2 = xj + l%3 - 1;
      bool val = ((unsigned)y < 64u) && ((unsigned)x2 < 64u);
      int nl2 = y*64 + x2;
      nloc[l] = val ? nl2 : -1;
      float kd = val ? g_kv[(b*4096+nl2)*512 + h*32 + lane] : 0.f;
      sloc[l] = warpSum(qs*kd) + rpbl[l];
    }
    const int* rr = rpi + (long)n*64;
    int ia = rr[lane], ib = rr[lane+32];
    float s0 = g_cpb[ia*8+h];
    float s1 = g_cpb[ib*8+h];
    const float4* q4 = (const float4*)(qsm + nl*32);
    #pragma unroll
    for (int dq=0; dq<8; dq++){
      float4 qv = q4[dq];
      int d0 = dq*4;
      s0 = fmaf(qv.x, ks[(d0+0)*64+lane], s0);
      s0 = fmaf(qv.y, ks[(d0+1)*64+lane], s0);
      s0 = fmaf(qv.z, ks[(d0+2)*64+lane], s0);
      s0 = fmaf(qv.w, ks[(d0+3)*64+lane], s0);
      s1 = fmaf(qv.x, ks[(d0+0)*64+lane+32], s1);
      s1 = fmaf(qv.y, ks[(d0+1)*64+lane+32], s1);
      s1 = fmaf(qv.z, ks[(d0+2)*64+lane+32], s1);
      s1 = fmaf(qv.w, ks[(d0+3)*64+lane+32], s1);
    }
    float m = fmaxf(s0, s1);
    #pragma unroll
    for (int l=0;l<9;l++) m = fmaxf(m, sloc[l]);
    m = warpMax(m);
    float el[9], suml = 0.f;
    #pragma unroll
    for (int l=0;l<9;l++){ el[l] = expf(sloc[l]-m); suml += el[l]; }
    float e0 = expf(s0-m), e1 = expf(s1-m);
    float inv = 1.f / (suml + warpSum(e0+e1));
    psm[warp][lane]    = e0 * inv;
    psm[warp][lane+32] = e1 * inv;
    __syncwarp();
    const float* ltdp = g_ltd + ((long)(b*8+h)*4096 + n)*9;
    float outv = 0.f;
    #pragma unroll
    for (int l=0;l<9;l++){
      float al = el[l]*inv + ltdp[l];
      if (nloc[l] >= 0)
        outv = fmaf(al, g_kv[(b*4096+nloc[l])*512 + 256 + h*32 + lane], outv);
    }
    const float4* p4 = (const float4*)(&psm[warp][0]);
    #pragma unroll
    for (int pq=0; pq<16; pq++){
      float4 ap = p4[pq];
      int p0 = pq*4;
      outv = fmaf(ap.x, vs[(p0+0)*32+lane], outv);
      outv = fmaf(ap.y, vs[(p0+1)*32+lane], outv);
      outv = fmaf(ap.z, vs[(p0+2)*32+lane], outv);
      outv = fmaf(ap.w, vs[(p0+3)*32+lane], outv);
    }
    float gate = g_gate[(b*4096+n)*8 + h];
    g_attnout[(b*4096+n)*256 + h*32 + lane] = outv * gate;
  }
}

// ---------------- launch ---------------------------------------------------------
extern "C" void kernel_launch(void* const* d_in, const int* in_sizes, int n_in,
                              void* d_out, int out_size)
{
  const float* x      = (const float*)d_in[0];
  const float* ctab   = (const float*)d_in[1];
  const float* q_w    = (const float*)d_in[2];
  const float* q_b    = (const float*)d_in[3];
  const float* kv_w   = (const float*)d_in[4];
  const float* kv_b   = (const float*)d_in[5];
  const float* temp   = (const float*)d_in[6];
  const float* qe     = (const float*)d_in[7];
  const float* rpb    = (const float*)d_in[8];
  const float* lt     = (const float*)d_in[9];
  const float* lb     = (const float*)d_in[10];
  const float* cpb1_w = (const float*)d_in[11];
  const float* cpb1_b = (const float*)d_in[12];
  const float* cpb2_w = (const float*)d_in[13];
  const float* cpb2_b = (const float*)d_in[14];
  const float* sr_w   = (const float*)d_in[15];
  const float* sr_b   = (const float*)d_in[16];
  const float* norm_g = (const float*)d_in[17];
  const float* norm_b = (const float*)d_in[18];
  const float* wg_w   = (const float*)d_in[19];
  const float* wg0_w  = (const float*)d_in[20];
  const float* wg1_w  = (const float*)d_in[21];
  const float* proj_w = (const float*)d_in[22];
  const float* proj_b = (const float*)d_in[23];
  const int*   rpi    = (const int*)d_in[24];
  float* out = (float*)d_out;

  float *p_qtmp, *p_kv, *p_xs, *p_pool, *p_kvp2, *p_attnout;
  __nv_bfloat16 *p_xhi, *p_xlo, *p_whi, *p_wlo, *p_aohi, *p_aolo;
  cudaGetSymbolAddress((void**)&p_qtmp,    g_qtmp);
  cudaGetSymbolAddress((void**)&p_kv,      g_kv);
  cudaGetSymbolAddress((void**)&p_xs,      g_xs);
  cudaGetSymbolAddress((void**)&p_pool,    g_pool);
  cudaGetSymbolAddress((void**)&p_kvp2,    g_kvp2);
  cudaGetSymbolAddress((void**)&p_attnout, g_attnout);
  cudaGetSymbolAddress((void**)&p_xhi,     g_xhi);
  cudaGetSymbolAddress((void**)&p_xlo,     g_xlo);
  cudaGetSymbolAddress((void**)&p_whi,     g_whi);
  cudaGetSymbolAddress((void**)&p_wlo,     g_wlo);
  cudaGetSymbolAddress((void**)&p_aohi,    g_aohi);
  cudaGetSymbolAddress((void**)&p_aolo,    g_aolo);

  const int HG_SMEM = 4 * 128 * SPITCH * 2;   // 73728 bytes
  cudaFuncSetAttribute(hmma_gemm, cudaFuncAttributeMaxDynamicSharedMemorySize, HG_SMEM);

  // gating (only needs x)
  gates_kernel<<<2048, 256>>>(x, wg_w, wg0_w, wg1_w);

  // hi/lo conversions
  convert_split_kernel<<<4096, 256>>>(x, p_xhi, p_xlo, NBATCH*NTOK*NC);
  convert_split_kernel<<<64, 256>>>(q_w,    p_whi,            p_wlo,            256*256);
  convert_split_kernel<<<128,256>>>(kv_w,   p_whi + 256*256,  p_wlo + 256*256,  512*256);
  convert_split_kernel<<<64, 256>>>(sr_w,   p_whi + 768*256,  p_wlo + 768*256,  256*256);
  convert_split_kernel<<<64, 256>>>(proj_w, p_whi + 1024*256, p_wlo + 1024*256, 256*256);

  // q path
  hmma_gemm<<<dim3(2,128), 256, HG_SMEM>>>(p_xhi, p_xlo, p_whi, p_wlo, q_b, p_qtmp, 256, 0);
  qpost_kernel<<<16384, 256>>>(temp, qe, lt, lb);
  // kv path
  hmma_gemm<<<dim3(4,128), 256, HG_SMEM>>>(p_xhi, p_xlo, p_whi + 256*256, p_wlo + 256*256, kv_b, p_kv, 512, 0);
  kvpost_kernel<<<16384, 256>>>();
  // pooled path
  hmma_gemm<<<dim3(2,128), 256, HG_SMEM>>>(p_xhi, p_xlo, p_whi + 768*256, p_wlo + 768*256, sr_b, p_xs, 256, 1);
  pool_ln_kernel<<<256, 256>>>(norm_g, norm_b);
  sgemm_kernel<false><<<dim3(4,2), 256>>>(p_pool, kv_w, kv_b, p_kvp2, 256, 512, 256);
  kvp2post_kernel<<<256, 256>>>();
  // cpb MLP
  cpb_hidden_kernel<<<8192, 256>>>(ctab, cpb1_w, cpb1_b);
  cpb_out_kernel<<<512, 256>>>(cpb2_w, cpb2_b);
  // fused attention
  attn_kernel<<<dim3(64, 32), 256>>>(rpb, rpi);
  // projection (tensor core)
  convert_split_kernel<<<4096, 256>>>(p_attnout, p_aohi, p_aolo, NBATCH*NTOK*NC);
  hmma_gemm<<<dim3(2,128), 256, HG_SMEM>>>(p_aohi, p_aolo, p_whi + 1024*256, p_wlo + 1024*256, proj_b, out, 256, 0);
}

// round 13
// speedup vs baseline: 1.4536x; 1.0529x over previous
#include <cuda_runtime.h>
#include <cuda_bf16.h>
#include <cstdint>
#include <cstring>
#include <math.h>

#define NBATCH 4
#define NTOK   4096
#define NC     256
#define NH     8
#define ND     32
#define NPL    64
#define EPSF   1.1920929e-07f

// ---------------- scratch (device globals; no runtime alloc allowed) -------------
__device__ float g_qtmp[NBATCH*NTOK*NC];        // raw q gemm out
__device__ float g_q[NBATCH*NTOK*NC];           // q_scaled, layout (B,H,N,D)
__device__ float g_ltd[NBATCH*NH*NTOK*9];       // learnable-token dots + bias
__device__ float g_kv[NBATCH*NTOK*2*NC];        // kv, k-half l2-normalized in place
__device__ float g_gate[NBATCH*NTOK*NH];        // per-head gates
__device__ float g_xs[NBATCH*NTOK*NC];          // sr+gelu out
__device__ float g_pool[NBATCH*NPL*NC];         // pooled + LN
__device__ float g_kvp2[NBATCH*NPL*2*NC];       // pooled kv, k-half normalized
__device__ float g_cpbh[4096*512];              // cpb hidden
__device__ float g_cpb[4096*NH];                // cpb table
__device__ float g_attnout[NBATCH*NTOK*NC];     // pre-proj attention out

// ---------------- helpers --------------------------------------------------------
__device__ __forceinline__ float warpSum(float v){
  #pragma unroll
  for (int o=16;o>0;o>>=1) v += __shfl_xor_sync(0xffffffffu, v, o);
  return v;
}
__device__ __forceinline__ float warpMax(float v){
  #pragma unroll
  for (int o=16;o>0;o>>=1) v = fmaxf(v, __shfl_xor_sync(0xffffffffu, v, o));
  return v;
}

// packed f32x2 helpers (Blackwell FFMA2)
__device__ __forceinline__ unsigned long long pack2(float lo, float hi){
  unsigned long long r;
  asm("mov.b64 %0, {%1, %2};" : "=l"(r) : "f"(lo), "f"(hi));
  return r;
}
__device__ __forceinline__ void unpack2(unsigned long long v, float& lo, float& hi){
  asm("mov.b64 {%0, %1}, %2;" : "=f"(lo), "=f"(hi) : "l"(v));
}
__device__ __forceinline__ void ffma2(unsigned long long& d,
                                      unsigned long long a, unsigned long long b){
  asm("fma.rn.f32x2 %0, %1, %2, %0;" : "+l"(d) : "l"(a), "l"(b));
}

__device__ __forceinline__ uint32_t smem_u32(const void* p){
  uint32_t a;
  asm("{ .reg .u64 t; cvta.to.shared.u64 t, %1; cvt.u32.u64 %0, t; }" : "=r"(a) : "l"(p));
  return a;
}

// ---------------- mma.sync helpers (sm_80+; legal on plain compute_103) ----------
__device__ __forceinline__ void ldmx4(uint32_t& r0, uint32_t& r1, uint32_t& r2, uint32_t& r3,
                                      uint32_t addr){
  asm volatile("ldmatrix.sync.aligned.m8n8.x4.shared.b16 {%0,%1,%2,%3}, [%4];"
               : "=r"(r0), "=r"(r1), "=r"(r2), "=r"(r3) : "r"(addr));
}
__device__ __forceinline__ void ldmx2(uint32_t& r0, uint32_t& r1, uint32_t addr){
  asm volatile("ldmatrix.sync.aligned.m8n8.x2.shared.b16 {%0,%1}, [%2];"
               : "=r"(r0), "=r"(r1) : "r"(addr));
}
__device__ __forceinline__ void mma_bf16(float* c, const uint32_t* a, uint32_t b0, uint32_t b1){
  asm volatile("mma.sync.aligned.m16n8k16.row.col.f32.bf16.bf16.f32 "
               "{%0,%1,%2,%3}, {%4,%5,%6,%7}, {%8,%9}, {%0,%1,%2,%3};"
               : "+f"(c[0]), "+f"(c[1]), "+f"(c[2]), "+f"(c[3])
               : "r"(a[0]), "r"(a[1]), "r"(a[2]), "r"(a[3]), "r"(b0), "r"(b1));
}

// fp32 -> bf16 hi/lo split, 8 elements at a time (packed to uint4)
__device__ __forceinline__ void split8(const float4& a, const float4& b, uint4& hi, uint4& lo){
  float f[8] = {a.x,a.y,a.z,a.w,b.x,b.y,b.z,b.w};
  __nv_bfloat16 h[8], l[8];
  #pragma unroll
  for (int i=0;i<8;i++){
    h[i] = __float2bfloat16(f[i]);
    l[i] = __float2bfloat16(f[i] - __bfloat162float(h[i]));
  }
  __nv_bfloat162 hp0(h[0],h[1]), hp1(h[2],h[3]), hp2(h[4],h[5]), hp3(h[6],h[7]);
  __nv_bfloat162 lp0(l[0],l[1]), lp1(l[2],l[3]), lp2(l[4],l[5]), lp3(l[6],l[7]);
  memcpy(&hi.x,&hp0,4); memcpy(&hi.y,&hp1,4); memcpy(&hi.z,&hp2,4); memcpy(&hi.w,&hp3,4);
  memcpy(&lo.x,&lp0,4); memcpy(&lo.y,&lp1,4); memcpy(&lo.z,&lp2,4); memcpy(&lo.w,&lp3,4);
}

// ---------------- HMMA split-bf16 GEMM: C = A(Mx256)*W(Nx256)^T + bias -----------
// Reads fp32 A/W directly; hi/lo split fused into the smem store phase.
// 128x128 CTA tile, 8 warps (4M x 2N), warp tile 32x64, K chunks of 64.
// smem rows padded to 72 bf16 (144 B) for conflict-free ldmatrix. 2 CTAs/SM.
#define SPITCH 72
__global__ void __launch_bounds__(256, 2)
hmma_gemm(const float* __restrict__ A, const float* __restrict__ W,
          const float* __restrict__ bias, float* __restrict__ dst,
          int ncols, int gelu)
{
  extern __shared__ __nv_bfloat16 sm[];
  __nv_bfloat16* sAh = sm;
  __nv_bfloat16* sAl = sm + 128*SPITCH;
  __nv_bfloat16* sWh = sm + 2*128*SPITCH;
  __nv_bfloat16* sWl = sm + 3*128*SPITCH;

  const int tid = threadIdx.x;
  const int wid = tid >> 5, lane = tid & 31;
  const int wy = wid & 3;        // 4 along M
  const int wx = wid >> 2;       // 2 along N
  const long m0 = (long)blockIdx.y * 128;
  const long n0 = (long)blockIdx.x * 128;

  const uint32_t sAh32 = smem_u32(sAh), sAl32 = smem_u32(sAl);
  const uint32_t sWh32 = smem_u32(sWh), sWl32 = smem_u32(sWl);

  float acc[2][8][4];
  #pragma unroll
  for (int mt=0;mt<2;mt++)
    #pragma unroll
    for (int nt=0;nt<8;nt++)
      #pragma unroll
      for (int j=0;j<4;j++) acc[mt][nt][j]=0.f;

  const int a_row = (lane & 15);
  const int a_kof = (lane >> 4) << 3;
  const int b_row = (lane & 7);
  const int b_kof = ((lane >> 3) & 1) << 3;

  for (int c4 = 0; c4 < 4; c4++){
    const int k0 = c4 * 64;
    // load + split 4 tiles: 128 rows x 64 k each
    #pragma unroll
    for (int it = 0; it < 4; it++){
      int idx = it*256 + tid;          // 0..1023
      int r = idx >> 3, seg = idx & 7;
      long goffA = (m0 + r) * 256 + k0 + seg*8;
      long goffW = (n0 + r) * 256 + k0 + seg*8;
      float4 a0 = *(const float4*)(A + goffA);
      float4 a1 = *(const float4*)(A + goffA + 4);
      float4 w0 = *(const float4*)(W + goffW);
      float4 w1 = *(const float4*)(W + goffW + 4);
      uint4 ahi, alo, whi, wlo;
      split8(a0, a1, ahi, alo);
      split8(w0, w1, whi, wlo);
      *(uint4*)(sAh + r*SPITCH + seg*8) = ahi;
      *(uint4*)(sAl + r*SPITCH + seg*8) = alo;
      *(uint4*)(sWh + r*SPITCH + seg*8) = whi;
      *(uint4*)(sWl + r*SPITCH + seg*8) = wlo;
    }
    __syncthreads();

    #pragma unroll
    for (int kk = 0; kk < 64; kk += 16){
      uint32_t ah[2][4], al[2][4];
      #pragma unroll
      for (int mt=0; mt<2; mt++){
        uint32_t off = (uint32_t)((wy*32 + mt*16 + a_row)*SPITCH + kk + a_kof) * 2u;
        ldmx4(ah[mt][0], ah[mt][1], ah[mt][2], ah[mt][3], sAh32 + off);
        ldmx4(al[mt][0], al[mt][1], al[mt][2], al[mt][3], sAl32 + off);
      }
      #pragma unroll
      for (int nt=0; nt<8; nt++){
        uint32_t boff = (uint32_t)((wx*64 + nt*8 + b_row)*SPITCH + kk + b_kof) * 2u;
        uint32_t bh0, bh1, bl0, bl1;
        ldmx2(bh0, bh1, sWh32 + boff);
        ldmx2(bl0, bl1, sWl32 + boff);
        #pragma unroll
        for (int mt=0; mt<2; mt++){
          mma_bf16(acc[mt][nt], ah[mt], bh0, bh1);   // hi*hi
          mma_bf16(acc[mt][nt], ah[mt], bl0, bl1);   // hi*lo
          mma_bf16(acc[mt][nt], al[mt], bh0, bh1);   // lo*hi
        }
      }
    }
    __syncthreads();
  }

  // epilogue: c0,c1 -> (row, col..col+1); c2,c3 -> (row+8, col..col+1)
  const int cr = lane >> 2;         // 0..7
  const int cc = (lane & 3) * 2;    // 0,2,4,6
  #pragma unroll
  for (int mt=0; mt<2; mt++){
    #pragma unroll
    for (int nt=0; nt<8; nt++){
      long row0 = m0 + wy*32 + mt*16 + cr;
      long col  = n0 + wx*64 + nt*8 + cc;
      float b0 = bias[col], b1 = bias[col+1];
      float v0 = acc[mt][nt][0] + b0, v1 = acc[mt][nt][1] + b1;
      float v2 = acc[mt][nt][2] + b0, v3 = acc[mt][nt][3] + b1;
      if (gelu){
        v0 = 0.5f*v0*(1.f + erff(v0*0.70710678118654752f));
        v1 = 0.5f*v1*(1.f + erff(v1*0.70710678118654752f));
        v2 = 0.5f*v2*(1.f + erff(v2*0.70710678118654752f));
        v3 = 0.5f*v3*(1.f + erff(v3*0.70710678118654752f));
      }
      *(float2*)(dst + row0*ncols + col)     = make_float2(v0, v1);
      *(float2*)(dst + (row0+8)*ncols + col) = make_float2(v2, v3);
    }
  }
}

// ---------------- fp32 SGEMM (kept for the tiny pooled-kv GEMM) ------------------
template<bool GELU>
__global__ void __launch_bounds__(256, 2)
sgemm_kernel(const float* __restrict__ A, const float* __restrict__ W,
             const float* __restrict__ bias, float* __restrict__ C,
             int M, int N, int K)
{
  __shared__ float As[2][16][128];
  __shared__ float Ws[2][16][128];
  const int tid = threadIdx.x;
  const int m0 = blockIdx.y * 128;
  const int n0 = blockIdx.x * 128;
  const int lrow = tid >> 1;
  const int lk   = (tid & 1) * 8;
  const int wid  = tid >> 5, lane = tid & 31;
  const int wy   = wid & 3;
  const int wx   = wid >> 2;
  const int ly   = lane >> 3;
  const int lx   = lane & 7;
  const int ra   = wy*32 + ly*4;
  const int cb   = wx*64 + lx*4;

  const float* Ap = A + (long)(m0 + lrow) * K + lk;
  const float* Wp = W + (long)(n0 + lrow) * K + lk;

  unsigned long long acc2[8][4];
  #pragma unroll
  for (int i=0;i<8;i++)
    #pragma unroll
    for (int j=0;j<4;j++) acc2[i][j]=0ULL;

  {
    float4 a0 = *(const float4*)(Ap);
    float4 a1 = *(const float4*)(Ap+4);
    float4 w0 = *(const float4*)(Wp);
    float4 w1 = *(const float4*)(Wp+4);
    As[0][lk+0][lrow]=a0.x; As[0][lk+1][lrow]=a0.y; As[0][lk+2][lrow]=a0.z; As[0][lk+3][lrow]=a0.w;
    As[0][lk+4][lrow]=a1.x; As[0][lk+5][lrow]=a1.y; As[0][lk+6][lrow]=a1.z; As[0][lk+7][lrow]=a1.w;
    Ws[0][lk+0][lrow]=w0.x; Ws[0][lk+1][lrow]=w0.y; Ws[0][lk+2][lrow]=w0.z; Ws[0][lk+3][lrow]=w0.w;
    Ws[0][lk+4][lrow]=w1.x; Ws[0][lk+5][lrow]=w1.y; Ws[0][lk+6][lrow]=w1.z; Ws[0][lk+7][lrow]=w1.w;
  }
  __syncthreads();

  int buf = 0;
  for (int k0 = 0; k0 < K; k0 += 16){
    const bool more = (k0 + 16 < K);
    float4 pa0, pa1, pw0, pw1;
    if (more){
      pa0 = *(const float4*)(Ap + k0 + 16);
      pa1 = *(const float4*)(Ap + k0 + 20);
      pw0 = *(const float4*)(Wp + k0 + 16);
      pw1 = *(const float4*)(Wp + k0 + 20);
    }
    #pragma unroll
    for (int kk=0; kk<16; kk++){
      float4 af0 = *(const float4*)(&As[buf][kk][ra]);
      float4 af1 = *(const float4*)(&As[buf][kk][ra+16]);
      float4 wf0 = *(const float4*)(&Ws[buf][kk][cb]);
      float4 wf1 = *(const float4*)(&Ws[buf][kk][cb+32]);
      unsigned long long ab[8], wp2[4];
      ab[0]=pack2(af0.x,af0.x); ab[1]=pack2(af0.y,af0.y);
      ab[2]=pack2(af0.z,af0.z); ab[3]=pack2(af0.w,af0.w);
      ab[4]=pack2(af1.x,af1.x); ab[5]=pack2(af1.y,af1.y);
      ab[6]=pack2(af1.z,af1.z); ab[7]=pack2(af1.w,af1.w);
      wp2[0]=pack2(wf0.x,wf0.y); wp2[1]=pack2(wf0.z,wf0.w);
      wp2[2]=pack2(wf1.x,wf1.y); wp2[3]=pack2(wf1.z,wf1.w);
      #pragma unroll
      for (int i=0;i<8;i++)
        #pragma unroll
        for (int j=0;j<4;j++)
          ffma2(acc2[i][j], ab[i], wp2[j]);
    }
    if (more){
      int nb = buf ^ 1;
      As[nb][lk+0][lrow]=pa0.x; As[nb][lk+1][lrow]=pa0.y; As[nb][lk+2][lrow]=pa0.z; As[nb][lk+3][lrow]=pa0.w;
      As[nb][lk+4][lrow]=pa1.x; As[nb][lk+5][lrow]=pa1.y; As[nb][lk+6][lrow]=pa1.z; As[nb][lk+7][lrow]=pa1.w;
      Ws[nb][lk+0][lrow]=pw0.x; Ws[nb][lk+1][lrow]=pw0.y; Ws[nb][lk+2][lrow]=pw0.z; Ws[nb][lk+3][lrow]=pw0.w;
      Ws[nb][lk+4][lrow]=pw1.x; Ws[nb][lk+5][lrow]=pw1.y; Ws[nb][lk+6][lrow]=pw1.z; Ws[nb][lk+7][lrow]=pw1.w;
    }
    __syncthreads();
    buf ^= 1;
  }

  #pragma unroll
  for (int i=0;i<8;i++){
    int m = m0 + ra + ((i < 4) ? i : (12 + i));
    #pragma unroll
    for (int jg=0;jg<2;jg++){
      int n = n0 + cb + jg*32;
      float4 v;
      unpack2(acc2[i][jg*2+0], v.x, v.y);
      unpack2(acc2[i][jg*2+1], v.z, v.w);
      v.x += bias[n+0];
      v.y += bias[n+1];
      v.z += bias[n+2];
      v.w += bias[n+3];
      if (GELU){
        v.x = 0.5f*v.x*(1.f + erff(v.x*0.70710678118654752f));
        v.y = 0.5f*v.y*(1.f + erff(v.y*0.70710678118654752f));
        v.z = 0.5f*v.z*(1.f + erff(v.z*0.70710678118654752f));
        v.w = 0.5f*v.w*(1.f + erff(v.w*0.70710678118654752f));
      }
      *(float4*)(C + (long)m*N + n) = v;
    }
  }
}

// ---------------- q post: l2norm, scale, learnable-token dots ---------------------
__global__ void __launch_bounds__(256)
qpost_kernel(const float* __restrict__ temp, const float* __restrict__ qe,
             const float* __restrict__ lt, const float* __restrict__ lb)
{
  int w = (blockIdx.x * 256 + threadIdx.x) >> 5;
  int lane = threadIdx.x & 31;
  int n = w & 4095;
  int bh = w >> 12;
  int h = bh & 7, b = bh >> 3;
  float qv = g_qtmp[(b*4096+n)*256 + h*32 + lane];
  float ss = warpSum(qv*qv);
  float qn = qv / fmaxf(sqrtf(ss), EPSF);
  int yi = n >> 6, xj = n & 63;
  int ch = min(yi+1,63) - max(yi-1,0) + 1;
  int cw = min(xj+1,63) - max(xj-1,0) + 1;
  float sls = logf((float)(ch*cw) + 64.f);
  float sp = log1pf(expf(temp[h]));
  g_q[w*32 + lane] = (qn + qe[h*32+lane]) * sp * sls;
  #pragma unroll
  for (int l=0;l<9;l++){
    float p = warpSum(qn * lt[h*288 + lane*9 + l]);
    if (lane == l) g_ltd[w*9 + l] = p + lb[h*9+l];
  }
}

// ---------------- kv post: l2-normalize k half per head (in place) ---------------
__global__ void __launch_bounds__(256)
kvpost_kernel()
{
  int w = (blockIdx.x*256 + threadIdx.x) >> 5;
  int lane = threadIdx.x & 31;
  int h = w & 7, row = w >> 3;
  float* p = g_kv + row*512 + h*32 + lane;
  float v = *p;
  float ss = warpSum(v*v);
  *p = v / fmaxf(sqrtf(ss), EPSF);
}

__global__ void __launch_bounds__(256)
kvp2post_kernel()
{
  int w = (blockIdx.x*256 + threadIdx.x) >> 5;
  int lane = threadIdx.x & 31;
  int h = w & 7, row = w >> 3;
  float* p = g_kvp2 + row*512 + h*32 + lane;
  float v = *p;
  float ss = warpSum(v*v);
  *p = v / fmaxf(sqrtf(ss), EPSF);
}

// ---------------- gating (routed top-2, shared, w0) ------------------------------
__global__ void __launch_bounds__(256)
gates_kernel(const float* __restrict__ x, const float* __restrict__ wg,
             const float* __restrict__ wg0, const float* __restrict__ wg1)
{
  int w = (blockIdx.x*256 + threadIdx.x) >> 5;
  int lane = threadIdx.x & 31;
  const float* xr = x + w*256;
  float xv[8];
  {
    float4 a = *(const float4*)(xr + lane*8);
    float4 c = *(const float4*)(xr + lane*8 + 4);
    xv[0]=a.x; xv[1]=a.y; xv[2]=a.z; xv[3]=a.w;
    xv[4]=c.x; xv[5]=c.y; xv[6]=c.z; xv[7]=c.w;
  }
  float d[10];
  #pragma unroll
  for (int r=0;r<10;r++){
    const float* wr = (r<4) ? (wg + r*256) : ((r<6) ? (wg0 + (r-4)*256) : (wg1 + (r-6)*256));
    float pp = 0.f;
    #pragma unroll
    for (int k=0;k<8;k++) pp = fmaf(xv[k], wr[lane*8+k], pp);
    d[r] = warpSum(pp);
  }
  if (lane == 0){
    float m = fmaxf(fmaxf(d[0],d[1]),fmaxf(d[2],d[3]));
    float e[4], se=0.f;
    #pragma unroll
    for (int k=0;k<4;k++){ e[k]=expf(d[k]-m); se+=e[k]; }
    float gg[4];
    #pragma unroll
    for (int k=0;k<4;k++) gg[k]=e[k]/se;
    int i0=0;
    #pragma unroll
    for (int k=1;k<4;k++) if (gg[k]>gg[i0]) i0=k;
    int i1=-1;
    #pragma unroll
    for (int k=0;k<4;k++) if (k!=i0 && (i1<0 || gg[k]>gg[i1])) i1=k;
    float s2 = fmaxf(gg[i0]+gg[i1], EPSF);
    float routed[4]={0.f,0.f,0.f,0.f};
    routed[i0]=gg[i0]/s2*2.f; routed[i1]=gg[i1]/s2*2.f;
    float m0 = fmaxf(d[4],d[5]);
    float e4=expf(d[4]-m0), e5=expf(d[5]-m0);
    float w00 = e4/(e4+e5)*2.f, w01 = e5/(e4+e5)*2.f;
    float m1 = fmaxf(fmaxf(d[6],d[7]),fmaxf(d[8],d[9]));
    float es[4], ss2=0.f;
    #pragma unroll
    for (int k=0;k<4;k++){ es[k]=expf(d[6+k]-m1); ss2+=es[k]; }
    float* gp = g_gate + w*8;
    #pragma unroll
    for (int k=0;k<4;k++) gp[k]   = w00 * (es[k]/ss2*4.f);
    #pragma unroll
    for (int k=0;k<4;k++) gp[4+k] = w01 * routed[k];
  }
}

// ---------------- 8x8 avg pool + LayerNorm ---------------------------------------
__global__ void __launch_bounds__(256)
pool_ln_kernel(const float* __restrict__ ng, const float* __restrict__ nb)
{
  int b = blockIdx.x >> 6, p = blockIdx.x & 63;
  int c = threadIdx.x;
  int pi = p >> 3, pj = p & 7;
  float s = 0.f;
  #pragma unroll
  for (int si=0; si<8; si++){
    int rowbase = b*4096 + (pi*8+si)*64 + pj*8;
    #pragma unroll
    for (int sj=0; sj<8; sj++)
      s += g_xs[(rowbase + sj)*256 + c];
  }
  float v = s * (1.f/64.f);
  __shared__ float shs[8], shq[8];
  int lane = c & 31, wid = c >> 5;
  float s1 = warpSum(v), sq = warpSum(v*v);
  if (lane==0){ shs[wid]=s1; shq[wid]=sq; }
  __syncthreads();
  float tot=0.f, totq=0.f;
  #pragma unroll
  for (int i=0;i<8;i++){ tot+=shs[i]; totq+=shq[i]; }
  float mu = tot*(1.f/256.f);
  float var = totq*(1.f/256.f) - mu*mu;
  g_pool[(b*64+p)*256 + c] = (v-mu)*rsqrtf(var+1e-5f)*ng[c] + nb[c];
}

// ---------------- cpb MLP --------------------------------------------------------
__global__ void __launch_bounds__(256)
cpb_hidden_kernel(const float* __restrict__ ct, const float* __restrict__ w1,
                  const float* __restrict__ b1)
{
  int tid = blockIdx.x*256 + threadIdx.x;
  if (tid >= 4096*512) return;
  int t = tid >> 9, j = tid & 511;
  float v = fmaf(ct[t*2], w1[j*2], fmaf(ct[t*2+1], w1[j*2+1], b1[j]));
  g_cpbh[tid] = fmaxf(v, 0.f);
}

__global__ void __launch_bounds__(256)
cpb_out_kernel(const float* __restrict__ w2, const float* __restrict__ b2)
{
  int t = (blockIdx.x*256 + threadIdx.x) >> 5;
  int lane = threadIdx.x & 31;
  float s[8] = {0,0,0,0,0,0,0,0};
  #pragma unroll
  for (int it=0; it<16; it++){
    float hv = g_cpbh[t*512 + it*32 + lane];
    #pragma unroll
    for (int h=0;h<8;h++) s[h] = fmaf(hv, w2[h*512 + it*32 + lane], s[h]);
  }
  #pragma unroll
  for (int h=0;h<8;h++){
    float tot = warpSum(s[h]);
    if (lane == 0) g_cpb[t*8 + h] = tot + b2[h];
  }
}

// ---------------- fused local+pool attention -------------------------------------
__global__ void __launch_bounds__(256)
attn_kernel(const float* __restrict__ rpb, const int* __restrict__ rpi)
{
  __shared__ float ks[32*64];
  __shared__ float vs[64*32];
  __shared__ __align__(16) float qsm[64*32];
  __shared__ __align__(16) float psm[8][64];
  const int bh = blockIdx.y;
  const int h = bh & 7, b = bh >> 3;
  const int tid = threadIdx.x;
  for (int idx = tid; idx < 2048; idx += 256){
    int p = idx >> 5, d = idx & 31;
    const float* base = g_kvp2 + (b*64+p)*512 + h*32 + d;
    ks[d*64+p] = base[0];
    vs[idx]    = base[256];
  }
  {
    const float4* qg = (const float4*)(g_q + ((long)(b*8+h)*4096 + blockIdx.x*64)*32);
    float4* qs4 = (float4*)qsm;
    for (int idx = tid; idx < 512; idx += 256) qs4[idx] = qg[idx];
  }
  __syncthreads();
  const int warp = tid >> 5, lane = tid & 31;
  float rpbl[9];
  #pragma unroll
  for (int l=0;l<9;l++) rpbl[l] = rpb[h*9+l];

  for (int it=0; it<8; it++){
    int nl = warp*8 + it;
    int n = blockIdx.x*64 + nl;
    int yi = n >> 6, xj = n & 63;
    float qs = qsm[nl*32 + lane];
    float sloc[9]; int nloc[9];
    #pragma unroll
    for (int l=0;l<9;l++){
      int y  = yi + l/3 - 1;
      int x2 = xj + l%3 - 1;
      bool val = ((unsigned)y < 64u) && ((unsigned)x2 < 64u);
      int nl2 = y*64 + x2;
      nloc[l] = val ? nl2 : -1;
      float kd = val ? g_kv[(b*4096+nl2)*512 + h*32 + lane] : 0.f;
      sloc[l] = warpSum(qs*kd) + rpbl[l];
    }
    const int* rr = rpi + (long)n*64;
    int ia = rr[lane], ib = rr[lane+32];
    float s0 = g_cpb[ia*8+h];
    float s1 = g_cpb[ib*8+h];
    const float4* q4 = (const float4*)(qsm + nl*32);
    #pragma unroll
    for (int dq=0; dq<8; dq++){
      float4 qv = q4[dq];
      int d0 = dq*4;
      s0 = fmaf(qv.x, ks[(d0+0)*64+lane], s0);
      s0 = fmaf(qv.y, ks[(d0+1)*64+lane], s0);
      s0 = fmaf(qv.z, ks[(d0+2)*64+lane], s0);
      s0 = fmaf(qv.w, ks[(d0+3)*64+lane], s0);
      s1 = fmaf(qv.x, ks[(d0+0)*64+lane+32], s1);
      s1 = fmaf(qv.y, ks[(d0+1)*64+lane+32], s1);
      s1 = fmaf(qv.z, ks[(d0+2)*64+lane+32], s1);
      s1 = fmaf(qv.w, ks[(d0+3)*64+lane+32], s1);
    }
    float m = fmaxf(s0, s1);
    #pragma unroll
    for (int l=0;l<9;l++) m = fmaxf(m, sloc[l]);
    m = warpMax(m);
    float el[9], suml = 0.f;
    #pragma unroll
    for (int l=0;l<9;l++){ el[l] = expf(sloc[l]-m); suml += el[l]; }
    float e0 = expf(s0-m), e1 = expf(s1-m);
    float inv = 1.f / (suml + warpSum(e0+e1));
    psm[warp][lane]    = e0 * inv;
    psm[warp][lane+32] = e1 * inv;
    __syncwarp();
    const float* ltdp = g_ltd + ((long)(b*8+h)*4096 + n)*9;
    float outv = 0.f;
    #pragma unroll
    for (int l=0;l<9;l++){
      float al = el[l]*inv + ltdp[l];
      if (nloc[l] >= 0)
        outv = fmaf(al, g_kv[(b*4096+nloc[l])*512 + 256 + h*32 + lane], outv);
    }
    const float4* p4 = (const float4*)(&psm[warp][0]);
    #pragma unroll
    for (int pq=0; pq<16; pq++){
      float4 ap = p4[pq];
      int p0 = pq*4;
      outv = fmaf(ap.x, vs[(p0+0)*32+lane], outv);
      outv = fmaf(ap.y, vs[(p0+1)*32+lane], outv);
      outv = fmaf(ap.z, vs[(p0+2)*32+lane], outv);
      outv = fmaf(ap.w, vs[(p0+3)*32+lane], outv);
    }
    float gate = g_gate[(b*4096+n)*8 + h];
    g_attnout[(b*4096+n)*256 + h*32 + lane] = outv * gate;
  }
}

// ---------------- launch ---------------------------------------------------------
extern "C" void kernel_launch(void* const* d_in, const int* in_sizes, int n_in,
                              void* d_out, int out_size)
{
  const float* x      = (const float*)d_in[0];
  const float* ctab   = (const float*)d_in[1];
  const float* q_w    = (const float*)d_in[2];
  const float* q_b    = (const float*)d_in[3];
  const float* kv_w   = (const float*)d_in[4];
  const float* kv_b   = (const float*)d_in[5];
  const float* temp   = (const float*)d_in[6];
  const float* qe     = (const float*)d_in[7];
  const float* rpb    = (const float*)d_in[8];
  const float* lt     = (const float*)d_in[9];
  const float* lb     = (const float*)d_in[10];
  const float* cpb1_w = (const float*)d_in[11];
  const float* cpb1_b = (const float*)d_in[12];
  const float* cpb2_w = (const float*)d_in[13];
  const float* cpb2_b = (const float*)d_in[14];
  const float* sr_w   = (const float*)d_in[15];
  const float* sr_b   = (const float*)d_in[16];
  const float* norm_g = (const float*)d_in[17];
  const float* norm_b = (const float*)d_in[18];
  const float* wg_w   = (const float*)d_in[19];
  const float* wg0_w  = (const float*)d_in[20];
  const float* wg1_w  = (const float*)d_in[21];
  const float* proj_w = (const float*)d_in[22];
  const float* proj_b = (const float*)d_in[23];
  const int*   rpi    = (const int*)d_in[24];
  float* out = (float*)d_out;

  float *p_qtmp, *p_kv, *p_xs, *p_pool, *p_kvp2, *p_attnout;
  cudaGetSymbolAddress((void**)&p_qtmp,    g_qtmp);
  cudaGetSymbolAddress((void**)&p_kv,      g_kv);
  cudaGetSymbolAddress((void**)&p_xs,      g_xs);
  cudaGetSymbolAddress((void**)&p_pool,    g_pool);
  cudaGetSymbolAddress((void**)&p_kvp2,    g_kvp2);
  cudaGetSymbolAddress((void**)&p_attnout, g_attnout);

  const int HG_SMEM = 4 * 128 * SPITCH * 2;   // 73728 bytes
  cudaFuncSetAttribute(hmma_gemm, cudaFuncAttributeMaxDynamicSharedMemorySize, HG_SMEM);

  // gating (only needs x)
  gates_kernel<<<2048, 256>>>(x, wg_w, wg0_w, wg1_w);

  // q path
  hmma_gemm<<<dim3(2,128), 256, HG_SMEM>>>(x, q_w, q_b, p_qtmp, 256, 0);
  qpost_kernel<<<16384, 256>>>(temp, qe, lt, lb);
  // kv path
  hmma_gemm<<<dim3(4,128), 256, HG_SMEM>>>(x, kv_w, kv_b, p_kv, 512, 0);
  kvpost_kernel<<<16384, 256>>>();
  // pooled path
  hmma_gemm<<<dim3(2,128), 256, HG_SMEM>>>(x, sr_w, sr_b, p_xs, 256, 1);
  pool_ln_kernel<<<256, 256>>>(norm_g, norm_b);
  sgemm_kernel<false><<<dim3(4,2), 256>>>(p_pool, kv_w, kv_b, p_kvp2, 256, 512, 256);
  kvp2post_kernel<<<256, 256>>>();
  // cpb MLP
  cpb_hidden_kernel<<<8192, 256>>>(ctab, cpb1_w, cpb1_b);
  cpb_out_kernel<<<512, 256>>>(cpb2_w, cpb2_b);
  // fused attention
  attn_kernel<<<dim3(64, 32), 256>>>(rpb, rpi);
  // projection (tensor core)
  hmma_gemm<<<dim3(2,128), 256, HG_SMEM>>>(p_attnout, proj_w, proj_b, out, 256, 0);
}

// round 14
// speedup vs baseline: 1.5106x; 1.0392x over previous
#include <cuda_runtime.h>
#include <cuda_bf16.h>
#include <cstdint>
#include <cstring>
#include <math.h>

#define NBATCH 4
#define NTOK   4096
#define NC     256
#define NH     8
#define ND     32
#define NPL    64
#define EPSF   1.1920929e-07f

// ---------------- scratch (device globals; no runtime alloc allowed) -------------
__device__ float g_qtmp[NBATCH*NTOK*NC];        // raw q gemm out
__device__ float g_q[NBATCH*NTOK*NC];           // q_scaled, layout (B,H,N,D)
__device__ float g_ltd[NBATCH*NH*NTOK*9];       // learnable-token dots + bias
__device__ float g_kv[NBATCH*NTOK*2*NC];        // kv, k-half l2-normalized in place
__device__ float g_gate[NBATCH*NTOK*NH];        // per-head gates
__device__ float g_xs[NBATCH*NTOK*NC];          // sr+gelu out
__device__ float g_pool[NBATCH*NPL*NC];         // pooled + LN
__device__ float g_kvp2[NBATCH*NPL*2*NC];       // pooled kv, k-half normalized
__device__ float g_cpbh[4096*512];              // cpb hidden
__device__ float g_cpb[4096*NH];                // cpb table
__device__ float g_attnout[NBATCH*NTOK*NC];     // pre-proj attention out

// ---------------- helpers --------------------------------------------------------
__device__ __forceinline__ float warpSum(float v){
  #pragma unroll
  for (int o=16;o>0;o>>=1) v += __shfl_xor_sync(0xffffffffu, v, o);
  return v;
}
__device__ __forceinline__ float warpMax(float v){
  #pragma unroll
  for (int o=16;o>0;o>>=1) v = fmaxf(v, __shfl_xor_sync(0xffffffffu, v, o));
  return v;
}

// packed f32x2 helpers (Blackwell FFMA2)
__device__ __forceinline__ unsigned long long pack2(float lo, float hi){
  unsigned long long r;
  asm("mov.b64 %0, {%1, %2};" : "=l"(r) : "f"(lo), "f"(hi));
  return r;
}
__device__ __forceinline__ void unpack2(unsigned long long v, float& lo, float& hi){
  asm("mov.b64 {%0, %1}, %2;" : "=f"(lo), "=f"(hi) : "l"(v));
}
__device__ __forceinline__ void ffma2(unsigned long long& d,
                                      unsigned long long a, unsigned long long b){
  asm("fma.rn.f32x2 %0, %1, %2, %0;" : "+l"(d) : "l"(a), "l"(b));
}

__device__ __forceinline__ uint32_t smem_u32(const void* p){
  uint32_t a;
  asm("{ .reg .u64 t; cvta.to.shared.u64 t, %1; cvt.u32.u64 %0, t; }" : "=r"(a) : "l"(p));
  return a;
}

// ---------------- mma.sync helpers (sm_80+; legal on plain compute_103) ----------
__device__ __forceinline__ void ldmx4(uint32_t& r0, uint32_t& r1, uint32_t& r2, uint32_t& r3,
                                      uint32_t addr){
  asm volatile("ldmatrix.sync.aligned.m8n8.x4.shared.b16 {%0,%1,%2,%3}, [%4];"
               : "=r"(r0), "=r"(r1), "=r"(r2), "=r"(r3) : "r"(addr));
}
__device__ __forceinline__ void mma_bf16(float* c, const uint32_t* a, uint32_t b0, uint32_t b1){
  asm volatile("mma.sync.aligned.m16n8k16.row.col.f32.bf16.bf16.f32 "
               "{%0,%1,%2,%3}, {%4,%5,%6,%7}, {%8,%9}, {%0,%1,%2,%3};"
               : "+f"(c[0]), "+f"(c[1]), "+f"(c[2]), "+f"(c[3])
               : "r"(a[0]), "r"(a[1]), "r"(a[2]), "r"(a[3]), "r"(b0), "r"(b1));
}

// fp32 -> bf16 hi/lo split, 8 elements at a time (packed to uint4)
__device__ __forceinline__ void split8(const float4& a, const float4& b, uint4& hi, uint4& lo){
  float f[8] = {a.x,a.y,a.z,a.w,b.x,b.y,b.z,b.w};
  __nv_bfloat16 h[8], l[8];
  #pragma unroll
  for (int i=0;i<8;i++){
    h[i] = __float2bfloat16(f[i]);
    l[i] = __float2bfloat16(f[i] - __bfloat162float(h[i]));
  }
  __nv_bfloat162 hp0(h[0],h[1]), hp1(h[2],h[3]), hp2(h[4],h[5]), hp3(h[6],h[7]);
  __nv_bfloat162 lp0(l[0],l[1]), lp1(l[2],l[3]), lp2(l[4],l[5]), lp3(l[6],l[7]);
  memcpy(&hi.x,&hp0,4); memcpy(&hi.y,&hp1,4); memcpy(&hi.z,&hp2,4); memcpy(&hi.w,&hp3,4);
  memcpy(&lo.x,&lp0,4); memcpy(&lo.y,&lp1,4); memcpy(&lo.z,&lp2,4); memcpy(&lo.w,&lp3,4);
}

// ---------------- HMMA split-bf16 GEMM body --------------------------------------
// C = A(Mx256)*W(Nx256)^T + bias. Reads fp32, splits to hi/lo bf16 into smem.
// 128x128 CTA tile, 8 warps (4M x 2N), warp tile 32x64, K chunks of 64.
// smem rows padded to 72 bf16 (144 B). B fragments loaded via ldmatrix.x4
// (two n-tiles per instruction).
#define SPITCH 72
__device__ __forceinline__ void
hmma_body(const float* __restrict__ A, const float* __restrict__ W,
          const float* __restrict__ bias, float* __restrict__ dst,
          int ncols, int gelu, long m0, long n0, __nv_bfloat16* sm)
{
  __nv_bfloat16* sAh = sm;
  __nv_bfloat16* sAl = sm + 128*SPITCH;
  __nv_bfloat16* sWh = sm + 2*128*SPITCH;
  __nv_bfloat16* sWl = sm + 3*128*SPITCH;

  const int tid = threadIdx.x;
  const int wid = tid >> 5, lane = tid & 31;
  const int wy = wid & 3;        // 4 along M
  const int wx = wid >> 2;       // 2 along N

  const uint32_t sAh32 = smem_u32(sAh), sAl32 = smem_u32(sAl);
  const uint32_t sWh32 = smem_u32(sWh), sWl32 = smem_u32(sWl);

  float acc[2][8][4];
  #pragma unroll
  for (int mt=0;mt<2;mt++)
    #pragma unroll
    for (int nt=0;nt<8;nt++)
      #pragma unroll
      for (int j=0;j<4;j++) acc[mt][nt][j]=0.f;

  // A x4 lane mapping: lanes 0-15 -> rows base+0..15 @k, 16-31 -> same rows @k+8
  const int a_row = (lane & 15);
  const int a_kof = (lane >> 4) << 3;
  // B x4 lane mapping (two n-tiles): lanes 0-7 -> nt rows @k, 8-15 -> nt rows @k+8,
  // 16-23 -> nt+1 rows @k, 24-31 -> nt+1 rows @k+8
  const int b_mrow = (lane & 7);
  const int b_nof  = (lane >> 4) << 3;          // 0 or 8 (second n-tile)
  const int b_kof  = ((lane >> 3) & 1) << 3;    // 0 or 8 (k offset)

  for (int c4 = 0; c4 < 4; c4++){
    const int k0 = c4 * 64;
    #pragma unroll
    for (int it = 0; it < 4; it++){
      int idx = it*256 + tid;          // 0..1023
      int r = idx >> 3, seg = idx & 7;
      long goffA = (m0 + r) * 256 + k0 + seg*8;
      long goffW = (n0 + r) * 256 + k0 + seg*8;
      float4 a0 = *(const float4*)(A + goffA);
      float4 a1 = *(const float4*)(A + goffA + 4);
      float4 w0 = *(const float4*)(W + goffW);
      float4 w1 = *(const float4*)(W + goffW + 4);
      uint4 ahi, alo, whi, wlo;
      split8(a0, a1, ahi, alo);
      split8(w0, w1, whi, wlo);
      *(uint4*)(sAh + r*SPITCH + seg*8) = ahi;
      *(uint4*)(sAl + r*SPITCH + seg*8) = alo;
      *(uint4*)(sWh + r*SPITCH + seg*8) = whi;
      *(uint4*)(sWl + r*SPITCH + seg*8) = wlo;
    }
    __syncthreads();

    #pragma unroll
    for (int kk = 0; kk < 64; kk += 16){
      uint32_t ah[2][4], al[2][4];
      #pragma unroll
      for (int mt=0; mt<2; mt++){
        uint32_t off = (uint32_t)((wy*32 + mt*16 + a_row)*SPITCH + kk + a_kof) * 2u;
        ldmx4(ah[mt][0], ah[mt][1], ah[mt][2], ah[mt][3], sAh32 + off);
        ldmx4(al[mt][0], al[mt][1], al[mt][2], al[mt][3], sAl32 + off);
      }
      #pragma unroll
      for (int np=0; np<4; np++){           // n-tile pairs {0,1},{2,3},{4,5},{6,7}
        uint32_t boff = (uint32_t)((wx*64 + np*16 + b_nof + b_mrow)*SPITCH + kk + b_kof) * 2u;
        uint32_t bh0, bh1, bh2, bh3, bl0, bl1, bl2, bl3;
        ldmx4(bh0, bh1, bh2, bh3, sWh32 + boff);
        ldmx4(bl0, bl1, bl2, bl3, sWl32 + boff);
        #pragma unroll
        for (int mt=0; mt<2; mt++){
          mma_bf16(acc[mt][np*2+0], ah[mt], bh0, bh1);
          mma_bf16(acc[mt][np*2+0], ah[mt], bl0, bl1);
          mma_bf16(acc[mt][np*2+0], al[mt], bh0, bh1);
          mma_bf16(acc[mt][np*2+1], ah[mt], bh2, bh3);
          mma_bf16(acc[mt][np*2+1], ah[mt], bl2, bl3);
          mma_bf16(acc[mt][np*2+1], al[mt], bh2, bh3);
        }
      }
    }
    __syncthreads();
  }

  // epilogue: c0,c1 -> (row, col..col+1); c2,c3 -> (row+8, col..col+1)
  const int cr = lane >> 2;         // 0..7
  const int cc = (lane & 3) * 2;    // 0,2,4,6
  #pragma unroll
  for (int mt=0; mt<2; mt++){
    #pragma unroll
    for (int nt=0; nt<8; nt++){
      long row0 = m0 + wy*32 + mt*16 + cr;
      long col  = n0 + wx*64 + nt*8 + cc;
      float b0 = bias[col], b1 = bias[col+1];
      float v0 = acc[mt][nt][0] + b0, v1 = acc[mt][nt][1] + b1;
      float v2 = acc[mt][nt][2] + b0, v3 = acc[mt][nt][3] + b1;
      if (gelu){
        v0 = 0.5f*v0*(1.f + erff(v0*0.70710678118654752f));
        v1 = 0.5f*v1*(1.f + erff(v1*0.70710678118654752f));
        v2 = 0.5f*v2*(1.f + erff(v2*0.70710678118654752f));
        v3 = 0.5f*v3*(1.f + erff(v3*0.70710678118654752f));
      }
      *(float2*)(dst + row0*ncols + col)     = make_float2(v0, v1);
      *(float2*)(dst + (row0+8)*ncols + col) = make_float2(v2, v3);
    }
  }
}

// fused q+kv+sr GEMM (all share A = x): bx 0-1 -> q, 2-5 -> kv, 6-7 -> sr(+gelu)
__global__ void __launch_bounds__(256, 2)
hmma_qkvsr(const float* __restrict__ x,
           const float* __restrict__ q_w, const float* __restrict__ q_b,
           const float* __restrict__ kv_w, const float* __restrict__ kv_b,
           const float* __restrict__ sr_w, const float* __restrict__ sr_b,
           float* __restrict__ dq, float* __restrict__ dkv, float* __restrict__ dsr)
{
  extern __shared__ __nv_bfloat16 sm[];
  const int bx = blockIdx.x;
  const long m0 = (long)blockIdx.y * 128;
  const float *W, *bias; float* dst; int ncols, gelu; long n0;
  if (bx < 2){       W = q_w;  bias = q_b;  dst = dq;  ncols = 256; gelu = 0; n0 = (long)bx * 128; }
  else if (bx < 6){  W = kv_w; bias = kv_b; dst = dkv; ncols = 512; gelu = 0; n0 = (long)(bx-2) * 128; }
  else {             W = sr_w; bias = sr_b; dst = dsr; ncols = 256; gelu = 1; n0 = (long)(bx-6) * 128; }
  hmma_body(x, W, bias, dst, ncols, gelu, m0, n0, sm);
}

// standalone GEMM (proj)
__global__ void __launch_bounds__(256, 2)
hmma_gemm(const float* __restrict__ A, const float* __restrict__ W,
          const float* __restrict__ bias, float* __restrict__ dst,
          int ncols, int gelu)
{
  extern __shared__ __nv_bfloat16 sm[];
  hmma_body(A, W, bias, dst, ncols, gelu,
            (long)blockIdx.y * 128, (long)blockIdx.x * 128, sm);
}

// ---------------- fp32 SGEMM (kept for the tiny pooled-kv GEMM) ------------------
template<bool GELU>
__global__ void __launch_bounds__(256, 2)
sgemm_kernel(const float* __restrict__ A, const float* __restrict__ W,
             const float* __restrict__ bias, float* __restrict__ C,
             int M, int N, int K)
{
  __shared__ float As[2][16][128];
  __shared__ float Ws[2][16][128];
  const int tid = threadIdx.x;
  const int m0 = blockIdx.y * 128;
  const int n0 = blockIdx.x * 128;
  const int lrow = tid >> 1;
  const int lk   = (tid & 1) * 8;
  const int wid  = tid >> 5, lane = tid & 31;
  const int wy   = wid & 3;
  const int wx   = wid >> 2;
  const int ly   = lane >> 3;
  const int lx   = lane & 7;
  const int ra   = wy*32 + ly*4;
  const int cb   = wx*64 + lx*4;

  const float* Ap = A + (long)(m0 + lrow) * K + lk;
  const float* Wp = W + (long)(n0 + lrow) * K + lk;

  unsigned long long acc2[8][4];
  #pragma unroll
  for (int i=0;i<8;i++)
    #pragma unroll
    for (int j=0;j<4;j++) acc2[i][j]=0ULL;

  {
    float4 a0 = *(const float4*)(Ap);
    float4 a1 = *(const float4*)(Ap+4);
    float4 w0 = *(const float4*)(Wp);
    float4 w1 = *(const float4*)(Wp+4);
    As[0][lk+0][lrow]=a0.x; As[0][lk+1][lrow]=a0.y; As[0][lk+2][lrow]=a0.z; As[0][lk+3][lrow]=a0.w;
    As[0][lk+4][lrow]=a1.x; As[0][lk+5][lrow]=a1.y; As[0][lk+6][lrow]=a1.z; As[0][lk+7][lrow]=a1.w;
    Ws[0][lk+0][lrow]=w0.x; Ws[0][lk+1][lrow]=w0.y; Ws[0][lk+2][lrow]=w0.z; Ws[0][lk+3][lrow]=w0.w;
    Ws[0][lk+4][lrow]=w1.x; Ws[0][lk+5][lrow]=w1.y; Ws[0][lk+6][lrow]=w1.z; Ws[0][lk+7][lrow]=w1.w;
  }
  __syncthreads();

  int buf = 0;
  for (int k0 = 0; k0 < K; k0 += 16){
    const bool more = (k0 + 16 < K);
    float4 pa0, pa1, pw0, pw1;
    if (more){
      pa0 = *(const float4*)(Ap + k0 + 16);
      pa1 = *(const float4*)(Ap + k0 + 20);
      pw0 = *(const float4*)(Wp + k0 + 16);
      pw1 = *(const float4*)(Wp + k0 + 20);
    }
    #pragma unroll
    for (int kk=0; kk<16; kk++){
      float4 af0 = *(const float4*)(&As[buf][kk][ra]);
      float4 af1 = *(const float4*)(&As[buf][kk][ra+16]);
      float4 wf0 = *(const float4*)(&Ws[buf][kk][cb]);
      float4 wf1 = *(const float4*)(&Ws[buf][kk][cb+32]);
      unsigned long long ab[8], wp2[4];
      ab[0]=pack2(af0.x,af0.x); ab[1]=pack2(af0.y,af0.y);
      ab[2]=pack2(af0.z,af0.z); ab[3]=pack2(af0.w,af0.w);
      ab[4]=pack2(af1.x,af1.x); ab[5]=pack2(af1.y,af1.y);
      ab[6]=pack2(af1.z,af1.z); ab[7]=pack2(af1.w,af1.w);
      wp2[0]=pack2(wf0.x,wf0.y); wp2[1]=pack2(wf0.z,wf0.w);
      wp2[2]=pack2(wf1.x,wf1.y); wp2[3]=pack2(wf1.z,wf1.w);
      #pragma unroll
      for (int i=0;i<8;i++)
        #pragma unroll
        for (int j=0;j<4;j++)
          ffma2(acc2[i][j], ab[i], wp2[j]);
    }
    if (more){
      int nb = buf ^ 1;
      As[nb][lk+0][lrow]=pa0.x; As[nb][lk+1][lrow]=pa0.y; As[nb][lk+2][lrow]=pa0.z; As[nb][lk+3][lrow]=pa0.w;
      As[nb][lk+4][lrow]=pa1.x; As[nb][lk+5][lrow]=pa1.y; As[nb][lk+6][lrow]=pa1.z; As[nb][lk+7][lrow]=pa1.w;
      Ws[nb][lk+0][lrow]=pw0.x; Ws[nb][lk+1][lrow]=pw0.y; Ws[nb][lk+2][lrow]=pw0.z; Ws[nb][lk+3][lrow]=pw0.w;
      Ws[nb][lk+4][lrow]=pw1.x; Ws[nb][lk+5][lrow]=pw1.y; Ws[nb][lk+6][lrow]=pw1.z; Ws[nb][lk+7][lrow]=pw1.w;
    }
    __syncthreads();
    buf ^= 1;
  }

  #pragma unroll
  for (int i=0;i<8;i++){
    int m = m0 + ra + ((i < 4) ? i : (12 + i));
    #pragma unroll
    for (int jg=0;jg<2;jg++){
      int n = n0 + cb + jg*32;
      float4 v;
      unpack2(acc2[i][jg*2+0], v.x, v.y);
      unpack2(acc2[i][jg*2+1], v.z, v.w);
      v.x += bias[n+0];
      v.y += bias[n+1];
      v.z += bias[n+2];
      v.w += bias[n+3];
      if (GELU){
        v.x = 0.5f*v.x*(1.f + erff(v.x*0.70710678118654752f));
        v.y = 0.5f*v.y*(1.f + erff(v.y*0.70710678118654752f));
        v.z = 0.5f*v.z*(1.f + erff(v.z*0.70710678118654752f));
        v.w = 0.5f*v.w*(1.f + erff(v.w*0.70710678118654752f));
      }
      *(float4*)(C + (long)m*N + n) = v;
    }
  }
}

// ---------------- q post: l2norm, scale, learnable-token dots ---------------------
__global__ void __launch_bounds__(256)
qpost_kernel(const float* __restrict__ temp, const float* __restrict__ qe,
             const float* __restrict__ lt, const float* __restrict__ lb)
{
  int w = (blockIdx.x * 256 + threadIdx.x) >> 5;
  int lane = threadIdx.x & 31;
  int n = w & 4095;
  int bh = w >> 12;
  int h = bh & 7, b = bh >> 3;
  float qv = g_qtmp[(b*4096+n)*256 + h*32 + lane];
  float ss = warpSum(qv*qv);
  float qn = qv / fmaxf(sqrtf(ss), EPSF);
  int yi = n >> 6, xj = n & 63;
  int ch = min(yi+1,63) - max(yi-1,0) + 1;
  int cw = min(xj+1,63) - max(xj-1,0) + 1;
  float sls = logf((float)(ch*cw) + 64.f);
  float sp = log1pf(expf(temp[h]));
  g_q[w*32 + lane] = (qn + qe[h*32+lane]) * sp * sls;
  #pragma unroll
  for (int l=0;l<9;l++){
    float p = warpSum(qn * lt[h*288 + lane*9 + l]);
    if (lane == l) g_ltd[w*9 + l] = p + lb[h*9+l];
  }
}

// ---------------- kv post: l2-normalize k half per head (in place) ---------------
__global__ void __launch_bounds__(256)
kvpost_kernel()
{
  int w = (blockIdx.x*256 + threadIdx.x) >> 5;
  int lane = threadIdx.x & 31;
  int h = w & 7, row = w >> 3;
  float* p = g_kv + row*512 + h*32 + lane;
  float v = *p;
  float ss = warpSum(v*v);
  *p = v / fmaxf(sqrtf(ss), EPSF);
}

__global__ void __launch_bounds__(256)
kvp2post_kernel()
{
  int w = (blockIdx.x*256 + threadIdx.x) >> 5;
  int lane = threadIdx.x & 31;
  int h = w & 7, row = w >> 3;
  float* p = g_kvp2 + row*512 + h*32 + lane;
  float v = *p;
  float ss = warpSum(v*v);
  *p = v / fmaxf(sqrtf(ss), EPSF);
}

// ---------------- gating (routed top-2, shared, w0) ------------------------------
__global__ void __launch_bounds__(256)
gates_kernel(const float* __restrict__ x, const float* __restrict__ wg,
             const float* __restrict__ wg0, const float* __restrict__ wg1)
{
  int w = (blockIdx.x*256 + threadIdx.x) >> 5;
  int lane = threadIdx.x & 31;
  const float* xr = x + w*256;
  float xv[8];
  {
    float4 a = *(const float4*)(xr + lane*8);
    float4 c = *(const float4*)(xr + lane*8 + 4);
    xv[0]=a.x; xv[1]=a.y; xv[2]=a.z; xv[3]=a.w;
    xv[4]=c.x; xv[5]=c.y; xv[6]=c.z; xv[7]=c.w;
  }
  float d[10];
  #pragma unroll
  for (int r=0;r<10;r++){
    const float* wr = (r<4) ? (wg + r*256) : ((r<6) ? (wg0 + (r-4)*256) : (wg1 + (r-6)*256));
    float pp = 0.f;
    #pragma unroll
    for (int k=0;k<8;k++) pp = fmaf(xv[k], wr[lane*8+k], pp);
    d[r] = warpSum(pp);
  }
  if (lane == 0){
    float m = fmaxf(fmaxf(d[0],d[1]),fmaxf(d[2],d[3]));
    float e[4], se=0.f;
    #pragma unroll
    for (int k=0;k<4;k++){ e[k]=expf(d[k]-m); se+=e[k]; }
    float gg[4];
    #pragma unroll
    for (int k=0;k<4;k++) gg[k]=e[k]/se;
    int i0=0;
    #pragma unroll
    for (int k=1;k<4;k++) if (gg[k]>gg[i0]) i0=k;
    int i1=-1;
    #pragma unroll
    for (int k=0;k<4;k++) if (k!=i0 && (i1<0 || gg[k]>gg[i1])) i1=k;
    float s2 = fmaxf(gg[i0]+gg[i1], EPSF);
    float routed[4]={0.f,0.f,0.f,0.f};
    routed[i0]=gg[i0]/s2*2.f; routed[i1]=gg[i1]/s2*2.f;
    float m0 = fmaxf(d[4],d[5]);
    float e4=expf(d[4]-m0), e5=expf(d[5]-m0);
    float w00 = e4/(e4+e5)*2.f, w01 = e5/(e4+e5)*2.f;
    float m1 = fmaxf(fmaxf(d[6],d[7]),fmaxf(d[8],d[9]));
    float es[4], ss2=0.f;
    #pragma unroll
    for (int k=0;k<4;k++){ es[k]=expf(d[6+k]-m1); ss2+=es[k]; }
    float* gp = g_gate + w*8;
    #pragma unroll
    for (int k=0;k<4;k++) gp[k]   = w00 * (es[k]/ss2*4.f);
    #pragma unroll
    for (int k=0;k<4;k++) gp[4+k] = w01 * routed[k];
  }
}

// ---------------- 8x8 avg pool + LayerNorm ---------------------------------------
__global__ void __launch_bounds__(256)
pool_ln_kernel(const float* __restrict__ ng, const float* __restrict__ nb)
{
  int b = blockIdx.x >> 6, p = blockIdx.x & 63;
  int c = threadIdx.x;
  int pi = p >> 3, pj = p & 7;
  float s = 0.f;
  #pragma unroll
  for (int si=0; si<8; si++){
    int rowbase = b*4096 + (pi*8+si)*64 + pj*8;
    #pragma unroll
    for (int sj=0; sj<8; sj++)
      s += g_xs[(rowbase + sj)*256 + c];
  }
  float v = s * (1.f/64.f);
  __shared__ float shs[8], shq[8];
  int lane = c & 31, wid = c >> 5;
  float s1 = warpSum(v), sq = warpSum(v*v);
  if (lane==0){ shs[wid]=s1; shq[wid]=sq; }
  __syncthreads();
  float tot=0.f, totq=0.f;
  #pragma unroll
  for (int i=0;i<8;i++){ tot+=shs[i]; totq+=shq[i]; }
  float mu = tot*(1.f/256.f);
  float var = totq*(1.f/256.f) - mu*mu;
  g_pool[(b*64+p)*256 + c] = (v-mu)*rsqrtf(var+1e-5f)*ng[c] + nb[c];
}

// ---------------- cpb MLP --------------------------------------------------------
__global__ void __launch_bounds__(256)
cpb_hidden_kernel(const float* __restrict__ ct, const float* __restrict__ w1,
                  const float* __restrict__ b1)
{
  int tid = blockIdx.x*256 + threadIdx.x;
  if (tid >= 4096*512) return;
  int t = tid >> 9, j = tid & 511;
  float v = fmaf(ct[t*2], w1[j*2], fmaf(ct[t*2+1], w1[j*2+1], b1[j]));
  g_cpbh[tid] = fmaxf(v, 0.f);
}

__global__ void __launch_bounds__(256)
cpb_out_kernel(const float* __restrict__ w2, const float* __restrict__ b2)
{
  int t = (blockIdx.x*256 + threadIdx.x) >> 5;
  int lane = threadIdx.x & 31;
  float s[8] = {0,0,0,0,0,0,0,0};
  #pragma unroll
  for (int it=0; it<16; it++){
    float hv = g_cpbh[t*512 + it*32 + lane];
    #pragma unroll
    for (int h=0;h<8;h++) s[h] = fmaf(hv, w2[h*512 + it*32 + lane], s[h]);
  }
  #pragma unroll
  for (int h=0;h<8;h++){
    float tot = warpSum(s[h]);
    if (lane == 0) g_cpb[t*8 + h] = tot + b2[h];
  }
}

// ---------------- fused local+pool attention -------------------------------------
__global__ void __launch_bounds__(256)
attn_kernel(const float* __restrict__ rpb, const int* __restrict__ rpi)
{
  __shared__ float ks[32*64];
  __shared__ float vs[64*32];
  __shared__ __align__(16) float qsm[64*32];
  __shared__ __align__(16) float psm[8][64];
  const int bh = blockIdx.y;
  const int h = bh & 7, b = bh >> 3;
  const int tid = threadIdx.x;
  for (int idx = tid; idx < 2048; idx += 256){
    int p = idx >> 5, d = idx & 31;
    const float* base = g_kvp2 + (b*64+p)*512 + h*32 + d;
    ks[d*64+p] = base[0];
    vs[idx]    = base[256];
  }
  {
    const float4* qg = (const float4*)(g_q + ((long)(b*8+h)*4096 + blockIdx.x*64)*32);
    float4* qs4 = (float4*)qsm;
    for (int idx = tid; idx < 512; idx += 256) qs4[idx] = qg[idx];
  }
  __syncthreads();
  const int warp = tid >> 5, lane = tid & 31;
  float rpbl[9];
  #pragma unroll
  for (int l=0;l<9;l++) rpbl[l] = rpb[h*9+l];

  for (int it=0; it<8; it++){
    int nl = warp*8 + it;
    int n = blockIdx.x*64 + nl;
    int yi = n >> 6, xj = n & 63;
    float qs = qsm[nl*32 + lane];
    float sloc[9]; int nloc[9];
    #pragma unroll
    for (int l=0;l<9;l++){
      int y  = yi + l/3 - 1;
      int x2 = xj + l%3 - 1;
      bool val = ((unsigned)y < 64u) && ((unsigned)x2 < 64u);
      int nl2 = y*64 + x2;
      nloc[l] = val ? nl2 : -1;
      float kd = val ? g_kv[(b*4096+nl2)*512 + h*32 + lane] : 0.f;
      sloc[l] = warpSum(qs*kd) + rpbl[l];
    }
    const int* rr = rpi + (long)n*64;
    int ia = rr[lane], ib = rr[lane+32];
    float s0 = g_cpb[ia*8+h];
    float s1 = g_cpb[ib*8+h];
    const float4* q4 = (const float4*)(qsm + nl*32);
    #pragma unroll
    for (int dq=0; dq<8; dq++){
      float4 qv = q4[dq];
      int d0 = dq*4;
      s0 = fmaf(qv.x, ks[(d0+0)*64+lane], s0);
      s0 = fmaf(qv.y, ks[(d0+1)*64+lane], s0);
      s0 = fmaf(qv.z, ks[(d0+2)*64+lane], s0);
      s0 = fmaf(qv.w, ks[(d0+3)*64+lane], s0);
      s1 = fmaf(qv.x, ks[(d0+0)*64+lane+32], s1);
      s1 = fmaf(qv.y, ks[(d0+1)*64+lane+32], s1);
      s1 = fmaf(qv.z, ks[(d0+2)*64+lane+32], s1);
      s1 = fmaf(qv.w, ks[(d0+3)*64+lane+32], s1);
    }
    float m = fmaxf(s0, s1);
    #pragma unroll
    for (int l=0;l<9;l++) m = fmaxf(m, sloc[l]);
    m = warpMax(m);
    float el[9], suml = 0.f;
    #pragma unroll
    for (int l=0;l<9;l++){ el[l] = expf(sloc[l]-m); suml += el[l]; }
    float e0 = expf(s0-m), e1 = expf(s1-m);
    float inv = 1.f / (suml + warpSum(e0+e1));
    psm[warp][lane]    = e0 * inv;
    psm[warp][lane+32] = e1 * inv;
    __syncwarp();
    const float* ltdp = g_ltd + ((long)(b*8+h)*4096 + n)*9;
    float outv = 0.f;
    #pragma unroll
    for (int l=0;l<9;l++){
      float al = el[l]*inv + ltdp[l];
      if (nloc[l] >= 0)
        outv = fmaf(al, g_kv[(b*4096+nloc[l])*512 + 256 + h*32 + lane], outv);
    }
    const float4* p4 = (const float4*)(&psm[warp][0]);
    #pragma unroll
    for (int pq=0; pq<16; pq++){
      float4 ap = p4[pq];
      int p0 = pq*4;
      outv = fmaf(ap.x, vs[(p0+0)*32+lane], outv);
      outv = fmaf(ap.y, vs[(p0+1)*32+lane], outv);
      outv = fmaf(ap.z, vs[(p0+2)*32+lane], outv);
      outv = fmaf(ap.w, vs[(p0+3)*32+lane], outv);
    }
    float gate = g_gate[(b*4096+n)*8 + h];
    g_attnout[(b*4096+n)*256 + h*32 + lane] = outv * gate;
  }
}

// ---------------- launch ---------------------------------------------------------
extern "C" void kernel_launch(void* const* d_in, const int* in_sizes, int n_in,
                              void* d_out, int out_size)
{
  const float* x      = (const float*)d_in[0];
  const float* ctab   = (const float*)d_in[1];
  const float* q_w    = (const float*)d_in[2];
  const float* q_b    = (const float*)d_in[3];
  const float* kv_w   = (const float*)d_in[4];
  const float* kv_b   = (const float*)d_in[5];
  const float* temp   = (const float*)d_in[6];
  const float* qe     = (const float*)d_in[7];
  const float* rpb    = (const float*)d_in[8];
  const float* lt     = (const float*)d_in[9];
  const float* lb     = (const float*)d_in[10];
  const float* cpb1_w = (const float*)d_in[11];
  const float* cpb1_b = (const float*)d_in[12];
  const float* cpb2_w = (const float*)d_in[13];
  const float* cpb2_b = (const float*)d_in[14];
  const float* sr_w   = (const float*)d_in[15];
  const float* sr_b   = (const float*)d_in[16];
  const float* norm_g = (const float*)d_in[17];
  const float* norm_b = (const float*)d_in[18];
  const float* wg_w   = (const float*)d_in[19];
  const float* wg0_w  = (const float*)d_in[20];
  const float* wg1_w  = (const float*)d_in[21];
  const float* proj_w = (const float*)d_in[22];
  const float* proj_b = (const float*)d_in[23];
  const int*   rpi    = (const int*)d_in[24];
  float* out = (float*)d_out;

  float *p_qtmp, *p_kv, *p_xs, *p_pool, *p_kvp2, *p_attnout;
  cudaGetSymbolAddress((void**)&p_qtmp,    g_qtmp);
  cudaGetSymbolAddress((void**)&p_kv,      g_kv);
  cudaGetSymbolAddress((void**)&p_xs,      g_xs);
  cudaGetSymbolAddress((void**)&p_pool,    g_pool);
  cudaGetSymbolAddress((void**)&p_kvp2,    g_kvp2);
  cudaGetSymbolAddress((void**)&p_attnout, g_attnout);

  const int HG_SMEM = 4 * 128 * SPITCH * 2;   // 73728 bytes
  cudaFuncSetAttribute(hmma_qkvsr, cudaFuncAttributeMaxDynamicSharedMemorySize, HG_SMEM);
  cudaFuncSetAttribute(hmma_gemm,  cudaFuncAttributeMaxDynamicSharedMemorySize, HG_SMEM);

  // gating (only needs x)
  gates_kernel<<<2048, 256>>>(x, wg_w, wg0_w, wg1_w);

  // fused q + kv + sr GEMM
  hmma_qkvsr<<<dim3(8,128), 256, HG_SMEM>>>(x, q_w, q_b, kv_w, kv_b, sr_w, sr_b,
                                            p_qtmp, p_kv, p_xs);
  qpost_kernel<<<16384, 256>>>(temp, qe, lt, lb);
  kvpost_kernel<<<16384, 256>>>();
  // pooled path
  pool_ln_kernel<<<256, 256>>>(norm_g, norm_b);
  sgemm_kernel<false><<<dim3(4,2), 256>>>(p_pool, kv_w, kv_b, p_kvp2, 256, 512, 256);
  kvp2post_kernel<<<256, 256>>>();
  // cpb MLP
  cpb_hidden_kernel<<<8192, 256>>>(ctab, cpb1_w, cpb1_b);
  cpb_out_kernel<<<512, 256>>>(cpb2_w, cpb2_b);
  // fused attention
  attn_kernel<<<dim3(64, 32), 256>>>(rpb, rpi);
  // projection
  hmma_gemm<<<dim3(2,128), 256, HG_SMEM>>>(p_attnout, proj_w, proj_b, out, 256, 0);
}

// round 16
// speedup vs baseline: 1.5492x; 1.0255x over previous
#include <cuda_runtime.h>
#include <cuda_bf16.h>
#include <cstdint>
#include <cstring>
#include <math.h>

#define NBATCH 4
#define NTOK   4096
#define NC     256
#define NH     8
#define ND     32
#define NPL    64
#define EPSF   1.1920929e-07f

// ---------------- scratch (device globals; no runtime alloc allowed) -------------
__device__ float g_qtmp[NBATCH*NTOK*NC];        // raw q gemm out
__device__ float g_q[NBATCH*NTOK*NC];           // q_scaled, layout (B,H,N,D)
__device__ float g_ltd[NBATCH*NH*NTOK*9];       // learnable-token dots + bias
__device__ float g_kv[NBATCH*NTOK*2*NC];        // kv, k-half l2-normalized in place
__device__ float g_gate[NBATCH*NTOK*NH];        // per-head gates
__device__ float g_xs[NBATCH*NTOK*NC];          // sr+gelu out
__device__ float g_pool[NBATCH*NPL*NC];         // pooled + LN
__device__ float g_kvp2[NBATCH*NPL*2*NC];       // pooled kv, k-half normalized
__device__ float g_cpbh[4096*512];              // cpb hidden
__device__ float g_cpb[4096*NH];                // cpb table
__device__ float g_attnout[NBATCH*NTOK*NC];     // pre-proj attention out

// ---------------- helpers --------------------------------------------------------
__device__ __forceinline__ float warpSum(float v){
  #pragma unroll
  for (int o=16;o>0;o>>=1) v += __shfl_xor_sync(0xffffffffu, v, o);
  return v;
}
__device__ __forceinline__ float warpMax(float v){
  #pragma unroll
  for (int o=16;o>0;o>>=1) v = fmaxf(v, __shfl_xor_sync(0xffffffffu, v, o));
  return v;
}

// packed f32x2 helpers (Blackwell FFMA2)
__device__ __forceinline__ unsigned long long pack2(float lo, float hi){
  unsigned long long r;
  asm("mov.b64 %0, {%1, %2};" : "=l"(r) : "f"(lo), "f"(hi));
  return r;
}
__device__ __forceinline__ void unpack2(unsigned long long v, float& lo, float& hi){
  asm("mov.b64 {%0, %1}, %2;" : "=f"(lo), "=f"(hi) : "l"(v));
}
__device__ __forceinline__ void ffma2(unsigned long long& d,
                                      unsigned long long a, unsigned long long b){
  asm("fma.rn.f32x2 %0, %1, %2, %0;" : "+l"(d) : "l"(a), "l"(b));
}

__device__ __forceinline__ uint32_t smem_u32(const void* p){
  uint32_t a;
  asm("{ .reg .u64 t; cvta.to.shared.u64 t, %1; cvt.u32.u64 %0, t; }" : "=r"(a) : "l"(p));
  return a;
}

// ---------------- mma.sync helpers (sm_80+; legal on plain compute_103) ----------
__device__ __forceinline__ void ldmx4(uint32_t& r0, uint32_t& r1, uint32_t& r2, uint32_t& r3,
                                      uint32_t addr){
  asm volatile("ldmatrix.sync.aligned.m8n8.x4.shared.b16 {%0,%1,%2,%3}, [%4];"
               : "=r"(r0), "=r"(r1), "=r"(r2), "=r"(r3) : "r"(addr));
}
__device__ __forceinline__ void mma_bf16(float* c, const uint32_t* a, uint32_t b0, uint32_t b1){
  asm volatile("mma.sync.aligned.m16n8k16.row.col.f32.bf16.bf16.f32 "
               "{%0,%1,%2,%3}, {%4,%5,%6,%7}, {%8,%9}, {%0,%1,%2,%3};"
               : "+f"(c[0]), "+f"(c[1]), "+f"(c[2]), "+f"(c[3])
               : "r"(a[0]), "r"(a[1]), "r"(a[2]), "r"(a[3]), "r"(b0), "r"(b1));
}

// fp32 -> bf16 hi/lo split, 8 elements at a time (packed to uint4)
__device__ __forceinline__ void split8(const float4& a, const float4& b, uint4& hi, uint4& lo){
  float f[8] = {a.x,a.y,a.z,a.w,b.x,b.y,b.z,b.w};
  __nv_bfloat16 h[8], l[8];
  #pragma unroll
  for (int i=0;i<8;i++){
    h[i] = __float2bfloat16(f[i]);
    l[i] = __float2bfloat16(f[i] - __bfloat162float(h[i]));
  }
  __nv_bfloat162 hp0(h[0],h[1]), hp1(h[2],h[3]), hp2(h[4],h[5]), hp3(h[6],h[7]);
  __nv_bfloat162 lp0(l[0],l[1]), lp1(l[2],l[3]), lp2(l[4],l[5]), lp3(l[6],l[7]);
  memcpy(&hi.x,&hp0,4); memcpy(&hi.y,&hp1,4); memcpy(&hi.z,&hp2,4); memcpy(&hi.w,&hp3,4);
  memcpy(&lo.x,&lp0,4); memcpy(&lo.y,&lp1,4); memcpy(&lo.z,&lp2,4); memcpy(&lo.w,&lp3,4);
}

// ---------------- HMMA split-bf16 GEMM body --------------------------------------
#define SPITCH 72
__device__ __forceinline__ void
hmma_body(const float* __restrict__ A, const float* __restrict__ W,
          const float* __restrict__ bias, float* __restrict__ dst,
          int ncols, int gelu, long m0, long n0, __nv_bfloat16* sm)
{
  __nv_bfloat16* sAh = sm;
  __nv_bfloat16* sAl = sm + 128*SPITCH;
  __nv_bfloat16* sWh = sm + 2*128*SPITCH;
  __nv_bfloat16* sWl = sm + 3*128*SPITCH;

  const int tid = threadIdx.x;
  const int wid = tid >> 5, lane = tid & 31;
  const int wy = wid & 3;        // 4 along M
  const int wx = wid >> 2;       // 2 along N

  const uint32_t sAh32 = smem_u32(sAh), sAl32 = smem_u32(sAl);
  const uint32_t sWh32 = smem_u32(sWh), sWl32 = smem_u32(sWl);

  float acc[2][8][4];
  #pragma unroll
  for (int mt=0;mt<2;mt++)
    #pragma unroll
    for (int nt=0;nt<8;nt++)
      #pragma unroll
      for (int j=0;j<4;j++) acc[mt][nt][j]=0.f;

  const int a_row = (lane & 15);
  const int a_kof = (lane >> 4) << 3;
  const int b_mrow = (lane & 7);
  const int b_nof  = (lane >> 4) << 3;
  const int b_kof  = ((lane >> 3) & 1) << 3;

  for (int c4 = 0; c4 < 4; c4++){
    const int k0 = c4 * 64;
    #pragma unroll
    for (int it = 0; it < 4; it++){
      int idx = it*256 + tid;
      int r = idx >> 3, seg = idx & 7;
      long goffA = (m0 + r) * 256 + k0 + seg*8;
      long goffW = (n0 + r) * 256 + k0 + seg*8;
      float4 a0 = *(const float4*)(A + goffA);
      float4 a1 = *(const float4*)(A + goffA + 4);
      float4 w0 = *(const float4*)(W + goffW);
      float4 w1 = *(const float4*)(W + goffW + 4);
      uint4 ahi, alo, whi, wlo;
      split8(a0, a1, ahi, alo);
      split8(w0, w1, whi, wlo);
      *(uint4*)(sAh + r*SPITCH + seg*8) = ahi;
      *(uint4*)(sAl + r*SPITCH + seg*8) = alo;
      *(uint4*)(sWh + r*SPITCH + seg*8) = whi;
      *(uint4*)(sWl + r*SPITCH + seg*8) = wlo;
    }
    __syncthreads();

    #pragma unroll
    for (int kk = 0; kk < 64; kk += 16){
      uint32_t ah[2][4], al[2][4];
      #pragma unroll
      for (int mt=0; mt<2; mt++){
        uint32_t off = (uint32_t)((wy*32 + mt*16 + a_row)*SPITCH + kk + a_kof) * 2u;
        ldmx4(ah[mt][0], ah[mt][1], ah[mt][2], ah[mt][3], sAh32 + off);
        ldmx4(al[mt][0], al[mt][1], al[mt][2], al[mt][3], sAl32 + off);
      }
      #pragma unroll
      for (int np=0; np<4; np++){
        uint32_t boff = (uint32_t)((wx*64 + np*16 + b_nof + b_mrow)*SPITCH + kk + b_kof) * 2u;
        uint32_t bh0, bh1, bh2, bh3, bl0, bl1, bl2, bl3;
        ldmx4(bh0, bh1, bh2, bh3, sWh32 + boff);
        ldmx4(bl0, bl1, bl2, bl3, sWl32 + boff);
        #pragma unroll
        for (int mt=0; mt<2; mt++){
          mma_bf16(acc[mt][np*2+0], ah[mt], bh0, bh1);
          mma_bf16(acc[mt][np*2+0], ah[mt], bl0, bl1);
          mma_bf16(acc[mt][np*2+0], al[mt], bh0, bh1);
          mma_bf16(acc[mt][np*2+1], ah[mt], bh2, bh3);
          mma_bf16(acc[mt][np*2+1], ah[mt], bl2, bl3);
          mma_bf16(acc[mt][np*2+1], al[mt], bh2, bh3);
        }
      }
    }
    __syncthreads();
  }

  const int cr = lane >> 2;
  const int cc = (lane & 3) * 2;
  #pragma unroll
  for (int mt=0; mt<2; mt++){
    #pragma unroll
    for (int nt=0; nt<8; nt++){
      long row0 = m0 + wy*32 + mt*16 + cr;
      long col  = n0 + wx*64 + nt*8 + cc;
      float b0 = bias[col], b1 = bias[col+1];
      float v0 = acc[mt][nt][0] + b0, v1 = acc[mt][nt][1] + b1;
      float v2 = acc[mt][nt][2] + b0, v3 = acc[mt][nt][3] + b1;
      if (gelu){
        v0 = 0.5f*v0*(1.f + erff(v0*0.70710678118654752f));
        v1 = 0.5f*v1*(1.f + erff(v1*0.70710678118654752f));
        v2 = 0.5f*v2*(1.f + erff(v2*0.70710678118654752f));
        v3 = 0.5f*v3*(1.f + erff(v3*0.70710678118654752f));
      }
      *(float2*)(dst + row0*ncols + col)     = make_float2(v0, v1);
      *(float2*)(dst + (row0+8)*ncols + col) = make_float2(v2, v3);
    }
  }
}

// fused q+kv+sr GEMM (all share A = x): bx 0-1 -> q, 2-5 -> kv, 6-7 -> sr(+gelu)
__global__ void __launch_bounds__(256, 2)
hmma_qkvsr(const float* __restrict__ x,
           const float* __restrict__ q_w, const float* __restrict__ q_b,
           const float* __restrict__ kv_w, const float* __restrict__ kv_b,
           const float* __restrict__ sr_w, const float* __restrict__ sr_b,
           float* __restrict__ dq, float* __restrict__ dkv, float* __restrict__ dsr)
{
  extern __shared__ __nv_bfloat16 sm[];
  const int bx = blockIdx.x;
  const long m0 = (long)blockIdx.y * 128;
  const float *W, *bias; float* dst; int ncols, gelu; long n0;
  if (bx < 2){       W = q_w;  bias = q_b;  dst = dq;  ncols = 256; gelu = 0; n0 = (long)bx * 128; }
  else if (bx < 6){  W = kv_w; bias = kv_b; dst = dkv; ncols = 512; gelu = 0; n0 = (long)(bx-2) * 128; }
  else {             W = sr_w; bias = sr_b; dst = dsr; ncols = 256; gelu = 1; n0 = (long)(bx-6) * 128; }
  hmma_body(x, W, bias, dst, ncols, gelu, m0, n0, sm);
}

// standalone GEMM (proj)
__global__ void __launch_bounds__(256, 2)
hmma_gemm(const float* __restrict__ A, const float* __restrict__ W,
          const float* __restrict__ bias, float* __restrict__ dst,
          int ncols, int gelu)
{
  extern __shared__ __nv_bfloat16 sm[];
  hmma_body(A, W, bias, dst, ncols, gelu,
            (long)blockIdx.y * 128, (long)blockIdx.x * 128, sm);
}

// ---------------- fp32 SGEMM (kept for the tiny pooled-kv GEMM) ------------------
template<bool GELU>
__global__ void __launch_bounds__(256, 2)
sgemm_kernel(const float* __restrict__ A, const float* __restrict__ W,
             const float* __restrict__ bias, float* __restrict__ C,
             int M, int N, int K)
{
  __shared__ float As[2][16][128];
  __shared__ float Ws[2][16][128];
  const int tid = threadIdx.x;
  const int m0 = blockIdx.y * 128;
  const int n0 = blockIdx.x * 128;
  const int lrow = tid >> 1;
  const int lk   = (tid & 1) * 8;
  const int wid  = tid >> 5, lane = tid & 31;
  const int wy   = wid & 3;
  const int wx   = wid >> 2;
  const int ly   = lane >> 3;
  const int lx   = lane & 7;
  const int ra   = wy*32 + ly*4;
  const int cb   = wx*64 + lx*4;

  const float* Ap = A + (long)(m0 + lrow) * K + lk;
  const float* Wp = W + (long)(n0 + lrow) * K + lk;

  unsigned long long acc2[8][4];
  #pragma unroll
  for (int i=0;i<8;i++)
    #pragma unroll
    for (int j=0;j<4;j++) acc2[i][j]=0ULL;

  {
    float4 a0 = *(const float4*)(Ap);
    float4 a1 = *(const float4*)(Ap+4);
    float4 w0 = *(const float4*)(Wp);
    float4 w1 = *(const float4*)(Wp+4);
    As[0][lk+0][lrow]=a0.x; As[0][lk+1][lrow]=a0.y; As[0][lk+2][lrow]=a0.z; As[0][lk+3][lrow]=a0.w;
    As[0][lk+4][lrow]=a1.x; As[0][lk+5][lrow]=a1.y; As[0][lk+6][lrow]=a1.z; As[0][lk+7][lrow]=a1.w;
    Ws[0][lk+0][lrow]=w0.x; Ws[0][lk+1][lrow]=w0.y; Ws[0][lk+2][lrow]=w0.z; Ws[0][lk+3][lrow]=w0.w;
    Ws[0][lk+4][lrow]=w1.x; Ws[0][lk+5][lrow]=w1.y; Ws[0][lk+6][lrow]=w1.z; Ws[0][lk+7][lrow]=w1.w;
  }
  __syncthreads();

  int buf = 0;
  for (int k0 = 0; k0 < K; k0 += 16){
    const bool more = (k0 + 16 < K);
    float4 pa0, pa1, pw0, pw1;
    if (more){
      pa0 = *(const float4*)(Ap + k0 + 16);
      pa1 = *(const float4*)(Ap + k0 + 20);
      pw0 = *(const float4*)(Wp + k0 + 16);
      pw1 = *(const float4*)(Wp + k0 + 20);
    }
    #pragma unroll
    for (int kk=0; kk<16; kk++){
      float4 af0 = *(const float4*)(&As[buf][kk][ra]);
      float4 af1 = *(const float4*)(&As[buf][kk][ra+16]);
      float4 wf0 = *(const float4*)(&Ws[buf][kk][cb]);
      float4 wf1 = *(const float4*)(&Ws[buf][kk][cb+32]);
      unsigned long long ab[8], wp2[4];
      ab[0]=pack2(af0.x,af0.x); ab[1]=pack2(af0.y,af0.y);
      ab[2]=pack2(af0.z,af0.z); ab[3]=pack2(af0.w,af0.w);
      ab[4]=pack2(af1.x,af1.x); ab[5]=pack2(af1.y,af1.y);
      ab[6]=pack2(af1.z,af1.z); ab[7]=pack2(af1.w,af1.w);
      wp2[0]=pack2(wf0.x,wf0.y); wp2[1]=pack2(wf0.z,wf0.w);
      wp2[2]=pack2(wf1.x,wf1.y); wp2[3]=pack2(wf1.z,wf1.w);
      #pragma unroll
      for (int i=0;i<8;i++)
        #pragma unroll
        for (int j=0;j<4;j++)
          ffma2(acc2[i][j], ab[i], wp2[j]);
    }
    if (more){
      int nb = buf ^ 1;
      As[nb][lk+0][lrow]=pa0.x; As[nb][lk+1][lrow]=pa0.y; As[nb][lk+2][lrow]=pa0.z; As[nb][lk+3][lrow]=pa0.w;
      As[nb][lk+4][lrow]=pa1.x; As[nb][lk+5][lrow]=pa1.y; As[nb][lk+6][lrow]=pa1.z; As[nb][lk+7][lrow]=pa1.w;
      Ws[nb][lk+0][lrow]=pw0.x; Ws[nb][lk+1][lrow]=pw0.y; Ws[nb][lk+2][lrow]=pw0.z; Ws[nb][lk+3][lrow]=pw0.w;
      Ws[nb][lk+4][lrow]=pw1.x; Ws[nb][lk+5][lrow]=pw1.y; Ws[nb][lk+6][lrow]=pw1.z; Ws[nb][lk+7][lrow]=pw1.w;
    }
    __syncthreads();
    buf ^= 1;
  }

  #pragma unroll
  for (int i=0;i<8;i++){
    int m = m0 + ra + ((i < 4) ? i : (12 + i));
    #pragma unroll
    for (int jg=0;jg<2;jg++){
      int n = n0 + cb + jg*32;
      float4 v;
      unpack2(acc2[i][jg*2+0], v.x, v.y);
      unpack2(acc2[i][jg*2+1], v.z, v.w);
      v.x += bias[n+0];
      v.y += bias[n+1];
      v.z += bias[n+2];
      v.w += bias[n+3];
      if (GELU){
        v.x = 0.5f*v.x*(1.f + erff(v.x*0.70710678118654752f));
        v.y = 0.5f*v.y*(1.f + erff(v.y*0.70710678118654752f));
        v.z = 0.5f*v.z*(1.f + erff(v.z*0.70710678118654752f));
        v.w = 0.5f*v.w*(1.f + erff(v.w*0.70710678118654752f));
      }
      *(float4*)(C + (long)m*N + n) = v;
    }
  }
}

// ---------------- fused q/kv post: vectorized (warp per row, oct per head) --------
// blocks 0..2047   : qpost rows (b*4096+n), l2norm+scale+ltd
// blocks 2048..4095: kvpost rows, k-half l2norm in place
__global__ void __launch_bounds__(256)
qkvpost_kernel(const float* __restrict__ temp, const float* __restrict__ qe,
               const float* __restrict__ lt, const float* __restrict__ lb)
{
  const int gw = (blockIdx.x*256 + threadIdx.x) >> 5;   // global warp id, 0..32767
  const int lane = threadIdx.x & 31;
  const int oct = lane >> 3;      // 0..3
  const int oc  = lane & 7;       // 0..7
  const int d0  = oc * 4;

  if (gw < 16384){
    // ---- qpost ----
    const int row = gw;                 // b*4096+n
    const int n = row & 4095, b = row >> 12;
    const float4* src = (const float4*)(g_qtmp + (long)row * 256);
    float4 v1 = src[lane];
    float4 v2 = src[lane + 32];
    const int h1 = oct, h2 = oct + 4;
    float ss1 = v1.x*v1.x + v1.y*v1.y + v1.z*v1.z + v1.w*v1.w;
    float ss2 = v2.x*v2.x + v2.y*v2.y + v2.z*v2.z + v2.w*v2.w;
    #pragma unroll
    for (int o=4;o>0;o>>=1){
      ss1 += __shfl_xor_sync(0xffffffffu, ss1, o);
      ss2 += __shfl_xor_sync(0xffffffffu, ss2, o);
    }
    float inv1 = 1.f / fmaxf(sqrtf(ss1), EPSF);
    float inv2 = 1.f / fmaxf(sqrtf(ss2), EPSF);
    float qn1[4] = {v1.x*inv1, v1.y*inv1, v1.z*inv1, v1.w*inv1};
    float qn2[4] = {v2.x*inv2, v2.y*inv2, v2.z*inv2, v2.w*inv2};

    int yi = n >> 6, xj = n & 63;
    int chh = min(yi+1,63) - max(yi-1,0) + 1;
    int cww = min(xj+1,63) - max(xj-1,0) + 1;
    float sls = logf((float)(chh*cww) + 64.f);
    float sc1 = log1pf(expf(temp[h1])) * sls;
    float sc2 = log1pf(expf(temp[h2])) * sls;

    float4 qe1 = *(const float4*)(qe + h1*32 + d0);
    float4 qe2 = *(const float4*)(qe + h2*32 + d0);
    float4 o1 = make_float4((qn1[0]+qe1.x)*sc1, (qn1[1]+qe1.y)*sc1,
                            (qn1[2]+qe1.z)*sc1, (qn1[3]+qe1.w)*sc1);
    float4 o2 = make_float4((qn2[0]+qe2.x)*sc2, (qn2[1]+qe2.y)*sc2,
                            (qn2[2]+qe2.z)*sc2, (qn2[3]+qe2.w)*sc2);
    *(float4*)(g_q + ((long)(b*8+h1)*4096 + n)*32 + d0) = o1;
    *(float4*)(g_q + ((long)(b*8+h2)*4096 + n)*32 + d0) = o2;

    // ltd: 9 dots per head, partial over this lane's 4 dims, oct-reduced
    float p1[9], p2[9];
    #pragma unroll
    for (int l=0;l<9;l++){ p1[l]=0.f; p2[l]=0.f; }
    const float* lt1 = lt + h1*288 + d0*9;
    const float* lt2 = lt + h2*288 + d0*9;
    #pragma unroll
    for (int j=0;j<4;j++){
      #pragma unroll
      for (int l=0;l<9;l++){
        p1[l] = fmaf(qn1[j], lt1[j*9+l], p1[l]);
        p2[l] = fmaf(qn2[j], lt2[j*9+l], p2[l]);
      }
    }
    #pragma unroll
    for (int o=4;o>0;o>>=1){
      #pragma unroll
      for (int l=0;l<9;l++){
        p1[l] += __shfl_xor_sync(0xffffffffu, p1[l], o);
        p2[l] += __shfl_xor_sync(0xffffffffu, p2[l], o);
      }
    }
    if (oc == 0){
      long base1 = ((long)(b*8+h1)*4096 + n)*9;
      long base2 = ((long)(b*8+h2)*4096 + n)*9;
      #pragma unroll
      for (int l=0;l<9;l++){
        g_ltd[base1+l] = p1[l] + lb[h1*9+l];
        g_ltd[base2+l] = p2[l] + lb[h2*9+l];
      }
    }
  } else {
    // ---- kvpost ----
    const int row = gw - 16384;         // b*4096+n
    float4* base = (float4*)(g_kv + (long)row * 512);
    float4 v1 = base[lane];
    float4 v2 = base[lane + 32];
    float ss1 = v1.x*v1.x + v1.y*v1.y + v1.z*v1.z + v1.w*v1.w;
    float ss2 = v2.x*v2.x + v2.y*v2.y + v2.z*v2.z + v2.w*v2.w;
    #pragma unroll
    for (int o=4;o>0;o>>=1){
      ss1 += __shfl_xor_sync(0xffffffffu, ss1, o);
      ss2 += __shfl_xor_sync(0xffffffffu, ss2, o);
    }
    float inv1 = 1.f / fmaxf(sqrtf(ss1), EPSF);
    float inv2 = 1.f / fmaxf(sqrtf(ss2), EPSF);
    base[lane]      = make_float4(v1.x*inv1, v1.y*inv1, v1.z*inv1, v1.w*inv1);
    base[lane + 32] = make_float4(v2.x*inv2, v2.y*inv2, v2.z*inv2, v2.w*inv2);
  }
}

// ---------------- kvp2 post (tiny) -----------------------------------------------
__global__ void __launch_bounds__(256)
kvp2post_kernel()
{
  int w = (blockIdx.x*256 + threadIdx.x) >> 5;
  int lane = threadIdx.x & 31;
  int h = w & 7, row = w >> 3;
  float* p = g_kvp2 + row*512 + h*32 + lane;
  float v = *p;
  float ss = warpSum(v*v);
  *p = v / fmaxf(sqrtf(ss), EPSF);
}

// ---------------- gating (routed top-2, shared, w0) ------------------------------
__global__ void __launch_bounds__(256)
gates_kernel(const float* __restrict__ x, const float* __restrict__ wg,
             const float* __restrict__ wg0, const float* __restrict__ wg1)
{
  int w = (blockIdx.x*256 + threadIdx.x) >> 5;
  int lane = threadIdx.x & 31;
  const float* xr = x + w*256;
  float xv[8];
  {
    float4 a = *(const float4*)(xr + lane*8);
    float4 c = *(const float4*)(xr + lane*8 + 4);
    xv[0]=a.x; xv[1]=a.y; xv[2]=a.z; xv[3]=a.w;
    xv[4]=c.x; xv[5]=c.y; xv[6]=c.z; xv[7]=c.w;
  }
  float d[10];
  #pragma unroll
  for (int r=0;r<10;r++){
    const float* wr = (r<4) ? (wg + r*256) : ((r<6) ? (wg0 + (r-4)*256) : (wg1 + (r-6)*256));
    float pp = 0.f;
    #pragma unroll
    for (int k=0;k<8;k++) pp = fmaf(xv[k], wr[lane*8+k], pp);
    d[r] = warpSum(pp);
  }
  if (lane == 0){
    float m = fmaxf(fmaxf(d[0],d[1]),fmaxf(d[2],d[3]));
    float e[4], se=0.f;
    #pragma unroll
    for (int k=0;k<4;k++){ e[k]=expf(d[k]-m); se+=e[k]; }
    float gg[4];
    #pragma unroll
    for (int k=0;k<4;k++) gg[k]=e[k]/se;
    int i0=0;
    #pragma unroll
    for (int k=1;k<4;k++) if (gg[k]>gg[i0]) i0=k;
    int i1=-1;
    #pragma unroll
    for (int k=0;k<4;k++) if (k!=i0 && (i1<0 || gg[k]>gg[i1])) i1=k;
    float s2 = fmaxf(gg[i0]+gg[i1], EPSF);
    float routed[4]={0.f,0.f,0.f,0.f};
    routed[i0]=gg[i0]/s2*2.f; routed[i1]=gg[i1]/s2*2.f;
    float m0 = fmaxf(d[4],d[5]);
    float e4=expf(d[4]-m0), e5=expf(d[5]-m0);
    float w00 = e4/(e4+e5)*2.f, w01 = e5/(e4+e5)*2.f;
    float m1 = fmaxf(fmaxf(d[6],d[7]),fmaxf(d[8],d[9]));
    float es[4], ss2=0.f;
    #pragma unroll
    for (int k=0;k<4;k++){ es[k]=expf(d[6+k]-m1); ss2+=es[k]; }
    float* gp = g_gate + w*8;
    #pragma unroll
    for (int k=0;k<4;k++) gp[k]   = w00 * (es[k]/ss2*4.f);
    #pragma unroll
    for (int k=0;k<4;k++) gp[4+k] = w01 * routed[k];
  }
}

// ---------------- 8x8 avg pool + LayerNorm ---------------------------------------
__global__ void __launch_bounds__(256)
pool_ln_kernel(const float* __restrict__ ng, const float* __restrict__ nb)
{
  int b = blockIdx.x >> 6, p = blockIdx.x & 63;
  int c = threadIdx.x;
  int pi = p >> 3, pj = p & 7;
  float s = 0.f;
  #pragma unroll
  for (int si=0; si<8; si++){
    int rowbase = b*4096 + (pi*8+si)*64 + pj*8;
    #pragma unroll
    for (int sj=0; sj<8; sj++)
      s += g_xs[(rowbase + sj)*256 + c];
  }
  float v = s * (1.f/64.f);
  __shared__ float shs[8], shq[8];
  int lane = c & 31, wid = c >> 5;
  float s1 = warpSum(v), sq = warpSum(v*v);
  if (lane==0){ shs[wid]=s1; shq[wid]=sq; }
  __syncthreads();
  float tot=0.f, totq=0.f;
  #pragma unroll
  for (int i=0;i<8;i++){ tot+=shs[i]; totq+=shq[i]; }
  float mu = tot*(1.f/256.f);
  float var = totq*(1.f/256.f) - mu*mu;
  g_pool[(b*64+p)*256 + c] = (v-mu)*rsqrtf(var+1e-5f)*ng[c] + nb[c];
}

// ---------------- cpb MLP --------------------------------------------------------
__global__ void __launch_bounds__(256)
cpb_hidden_kernel(const float* __restrict__ ct, const float* __restrict__ w1,
                  const float* __restrict__ b1)
{
  int tid = blockIdx.x*256 + threadIdx.x;
  if (tid >= 4096*512) return;
  int t = tid >> 9, j = tid & 511;
  float v = fmaf(ct[t*2], w1[j*2], fmaf(ct[t*2+1], w1[j*2+1], b1[j]));
  g_cpbh[tid] = fmaxf(v, 0.f);
}

__global__ void __launch_bounds__(256)
cpb_out_kernel(const float* __restrict__ w2, const float* __restrict__ b2)
{
  int t = (blockIdx.x*256 + threadIdx.x) >> 5;
  int lane = threadIdx.x & 31;
  float s[8] = {0,0,0,0,0,0,0,0};
  #pragma unroll
  for (int it=0; it<16; it++){
    float hv = g_cpbh[t*512 + it*32 + lane];
    #pragma unroll
    for (int h=0;h<8;h++) s[h] = fmaf(hv, w2[h*512 + it*32 + lane], s[h]);
  }
  #pragma unroll
  for (int h=0;h<8;h++){
    float tot = warpSum(s[h]);
    if (lane == 0) g_cpb[t*8 + h] = tot + b2[h];
  }
}

// ---------------- fused local+pool attention -------------------------------------
__global__ void __launch_bounds__(256)
attn_kernel(const float* __restrict__ rpb, const int* __restrict__ rpi)
{
  __shared__ float ks[32*64];
  __shared__ float vs[64*32];
  __shared__ __align__(16) float qsm[64*32];
  __shared__ __align__(16) float psm[8][64];
  const int bh = blockIdx.y;
  const int h = bh & 7, b = bh >> 3;
  const int tid = threadIdx.x;
  for (int idx = tid; idx < 2048; idx += 256){
    int p = idx >> 5, d = idx & 31;
    const float* base = g_kvp2 + (b*64+p)*512 + h*32 + d;
    ks[d*64+p] = base[0];
    vs[idx]    = base[256];
  }
  {
    const float4* qg = (const float4*)(g_q + ((long)(b*8+h)*4096 + blockIdx.x*64)*32);
    float4* qs4 = (float4*)qsm;
    for (int idx = tid; idx < 512; idx += 256) qs4[idx] = qg[idx];
  }
  __syncthreads();
  const int warp = tid >> 5, lane = tid & 31;
  float rpbl[9];
  #pragma unroll
  for (int l=0;l<9;l++) rpbl[l] = rpb[h*9+l];

  for (int it=0; it<8; it++){
    int nl = warp*8 + it;
    int n = blockIdx.x*64 + nl;
    int yi = n >> 6, xj = n & 63;
    float qs = qsm[nl*32 + lane];
    float sloc[9]; int nloc[9];
    #pragma unroll
    for (int l=0;l<9;l++){
      int y  = yi + l/3 - 1;
      int x2 = xj + l%3 - 1;
      bool val = ((unsigned)y < 64u) && ((unsigned)x2 < 64u);
      int nl2 = y*64 + x2;
      nloc[l] = val ? nl2 : -1;
      float kd = val ? g_kv[(b*4096+nl2)*512 + h*32 + lane] : 0.f;
      sloc[l] = warpSum(qs*kd) + rpbl[l];
    }
    const int* rr = rpi + (long)n*64;
    int ia = rr[lane], ib = rr[lane+32];
    float s0 = g_cpb[ia*8+h];
    float s1 = g_cpb[ib*8+h];
    const float4* q4 = (const float4*)(qsm + nl*32);
    #pragma unroll
    for (int dq=0; dq<8; dq++){
      float4 qv = q4[dq];
      int d0 = dq*4;
      s0 = fmaf(qv.x, ks[(d0+0)*64+lane], s0);
      s0 = fmaf(qv.y, ks[(d0+1)*64+lane], s0);
      s0 = fmaf(qv.z, ks[(d0+2)*64+lane], s0);
      s0 = fmaf(qv.w, ks[(d0+3)*64+lane], s0);
      s1 = fmaf(qv.x, ks[(d0+0)*64+lane+32], s1);
      s1 = fmaf(qv.y, ks[(d0+1)*64+lane+32], s1);
      s1 = fmaf(qv.z, ks[(d0+2)*64+lane+32], s1);
      s1 = fmaf(qv.w, ks[(d0+3)*64+lane+32], s1);
    }
    float m = fmaxf(s0, s1);
    #pragma unroll
    for (int l=0;l<9;l++) m = fmaxf(m, sloc[l]);
    m = warpMax(m);
    float el[9], suml = 0.f;
    #pragma unroll
    for (int l=0;l<9;l++){ el[l] = expf(sloc[l]-m); suml += el[l]; }
    float e0 = expf(s0-m), e1 = expf(s1-m);
    float inv = 1.f / (suml + warpSum(e0+e1));
    psm[warp][lane]    = e0 * inv;
    psm[warp][lane+32] = e1 * inv;
    __syncwarp();
    const float* ltdp = g_ltd + ((long)(b*8+h)*4096 + n)*9;
    float outv = 0.f;
    #pragma unroll
    for (int l=0;l<9;l++){
      float al = el[l]*inv + ltdp[l];
      if (nloc[l] >= 0)
        outv = fmaf(al, g_kv[(b*4096+nloc[l])*512 + 256 + h*32 + lane], outv);
    }
    const float4* p4 = (const float4*)(&psm[warp][0]);
    #pragma unroll
    for (int pq=0; pq<16; pq++){
      float4 ap = p4[pq];
      int p0 = pq*4;
      outv = fmaf(ap.x, vs[(p0+0)*32+lane], outv);
      outv = fmaf(ap.y, vs[(p0+1)*32+lane], outv);
      outv = fmaf(ap.z, vs[(p0+2)*32+lane], outv);
      outv = fmaf(ap.w, vs[(p0+3)*32+lane], outv);
    }
    float gate = g_gate[(b*4096+n)*8 + h];
    g_attnout[(b*4096+n)*256 + h*32 + lane] = outv * gate;
  }
}

// ---------------- launch ---------------------------------------------------------
extern "C" void kernel_launch(void* const* d_in, const int* in_sizes, int n_in,
                              void* d_out, int out_size)
{
  const float* x      = (const float*)d_in[0];
  const float* ctab   = (const float*)d_in[1];
  const float* q_w    = (const float*)d_in[2];
  const float* q_b    = (const float*)d_in[3];
  const float* kv_w   = (const float*)d_in[4];
  const float* kv_b   = (const float*)d_in[5];
  const float* temp   = (const float*)d_in[6];
  const float* qe     = (const float*)d_in[7];
  const float* rpb    = (const float*)d_in[8];
  const float* lt     = (const float*)d_in[9];
  const float* lb     = (const float*)d_in[10];
  const float* cpb1_w = (const float*)d_in[11];
  const float* cpb1_b = (const float*)d_in[12];
  const float* cpb2_w = (const float*)d_in[13];
  const float* cpb2_b = (const float*)d_in[14];
  const float* sr_w   = (const float*)d_in[15];
  const float* sr_b   = (const float*)d_in[16];
  const float* norm_g = (const float*)d_in[17];
  const float* norm_b = (const float*)d_in[18];
  const float* wg_w   = (const float*)d_in[19];
  const float* wg0_w  = (const float*)d_in[20];
  const float* wg1_w  = (const float*)d_in[21];
  const float* proj_w = (const float*)d_in[22];
  const float* proj_b = (const float*)d_in[23];
  const int*   rpi    = (const int*)d_in[24];
  float* out = (float*)d_out;

  float *p_qtmp, *p_kv, *p_xs, *p_pool, *p_kvp2, *p_attnout;
  cudaGetSymbolAddress((void**)&p_qtmp,    g_qtmp);
  cudaGetSymbolAddress((void**)&p_kv,      g_kv);
  cudaGetSymbolAddress((void**)&p_xs,      g_xs);
  cudaGetSymbolAddress((void**)&p_pool,    g_pool);
  cudaGetSymbolAddress((void**)&p_kvp2,    g_kvp2);
  cudaGetSymbolAddress((void**)&p_attnout, g_attnout);

  const int HG_SMEM = 4 * 128 * SPITCH * 2;   // 73728 bytes
  cudaFuncSetAttribute(hmma_qkvsr, cudaFuncAttributeMaxDynamicSharedMemorySize, HG_SMEM);
  cudaFuncSetAttribute(hmma_gemm,  cudaFuncAttributeMaxDynamicSharedMemorySize, HG_SMEM);

  // gating (only needs x)
  gates_kernel<<<2048, 256>>>(x, wg_w, wg0_w, wg1_w);

  // fused q + kv + sr GEMM
  hmma_qkvsr<<<dim3(8,128), 256, HG_SMEM>>>(x, q_w, q_b, kv_w, kv_b, sr_w, sr_b,
                                            p_qtmp, p_kv, p_xs);
  // fused q/kv post-processing
  qkvpost_kernel<<<4096, 256>>>(temp, qe, lt, lb);
  // pooled path
  pool_ln_kernel<<<256, 256>>>(norm_g, norm_b);
  sgemm_kernel<false><<<dim3(4,2), 256>>>(p_pool, kv_w, kv_b, p_kvp2, 256, 512, 256);
  kvp2post_kernel<<<256, 256>>>();
  // cpb MLP
  cpb_hidden_kernel<<<8192, 256>>>(ctab, cpb1_w, cpb1_b);
  cpb_out_kernel<<<512, 256>>>(cpb2_w, cpb2_b);
  // fused attention
  attn_kernel<<<dim3(64, 32), 256>>>(rpb, rpi);
  // projection
  hmma_gemm<<<dim3(2,128), 256, HG_SMEM>>>(p_attnout, proj_w, proj_b, out, 256, 0);
}